// round 7
// baseline (speedup 1.0000x reference)
#include <cuda_runtime.h>
#include <cuda_bf16.h>
#include <stdint.h>
#include <math.h>

#define DD   1024
#define NH   16
#define HDIM 64
#define BB   2
#define LL   2048
#define MTOK (BB*LL)   // 4096

#define AKS 40     // [row][k] bf16 smem stride (32 + 8)
#define BKS 136    // [k][n]  bf16 smem stride (128 + 8)

// ---------------- scratch (device globals; no allocations allowed) ----------
__device__ __nv_bfloat16 g_Wch[3][DD*DD], g_Wcl[3][DD*DD];  // combined W^T@R, split
__device__ __nv_bfloat16 g_Xh[MTOK*DD],  g_Xl[MTOK*DD];     // X split
__device__ __nv_bfloat16 g_Woh[DD*DD],   g_Wol[DD*DD];      // Wo split
__device__ __nv_bfloat16 g_Oh[MTOK*DD],  g_Ol[MTOK*DD];     // attn out (B,L,D) split
__device__ float g_Q[BB*NH*LL*HDIM];    // [b][h][l][d] fp32, pre-scaled by ent/8
__device__ float g_K[BB*NH*LL*HDIM];
__device__ float g_V[BB*NH*LL*HDIM];

// ---------------- helpers ----------------------------------------------------
__device__ __forceinline__ uint32_t f2tf32(float x) {
    uint32_t u;
    asm("cvt.rna.tf32.f32 %0, %1;" : "=r"(u) : "f"(x));
    return u;
}
__device__ __forceinline__ float tfr(float x) { return __uint_as_float(f2tf32(x)); }

__device__ __forceinline__ void mma8(float d[4], const uint32_t a[4], const uint32_t b[2]) {
    asm volatile(
        "mma.sync.aligned.m16n8k8.row.col.f32.tf32.tf32.f32 "
        "{%0,%1,%2,%3}, {%4,%5,%6,%7}, {%8,%9}, {%0,%1,%2,%3};"
        : "+f"(d[0]), "+f"(d[1]), "+f"(d[2]), "+f"(d[3])
        : "r"(a[0]), "r"(a[1]), "r"(a[2]), "r"(a[3]), "r"(b[0]), "r"(b[1]));
}

__device__ __forceinline__ void mma16(float* d, const uint32_t* a, const uint32_t* b) {
    asm volatile(
        "mma.sync.aligned.m16n8k16.row.col.f32.bf16.bf16.f32 "
        "{%0,%1,%2,%3}, {%4,%5,%6,%7}, {%8,%9}, {%0,%1,%2,%3};"
        : "+f"(d[0]), "+f"(d[1]), "+f"(d[2]), "+f"(d[3])
        : "r"(a[0]), "r"(a[1]), "r"(a[2]), "r"(a[3]), "r"(b[0]), "r"(b[1]));
}

__device__ __forceinline__ void ldsm4(uint32_t* r, const void* p) {
    uint32_t a = (uint32_t)__cvta_generic_to_shared(p);
    asm volatile("ldmatrix.sync.aligned.m8n8.x4.shared.b16 {%0,%1,%2,%3}, [%4];"
        : "=r"(r[0]), "=r"(r[1]), "=r"(r[2]), "=r"(r[3]) : "r"(a));
}
__device__ __forceinline__ void ldsm4t(uint32_t* r, const void* p) {
    uint32_t a = (uint32_t)__cvta_generic_to_shared(p);
    asm volatile("ldmatrix.sync.aligned.m8n8.x4.trans.shared.b16 {%0,%1,%2,%3}, [%4];"
        : "=r"(r[0]), "=r"(r[1]), "=r"(r[2]), "=r"(r[3]) : "r"(a));
}

// split 4 fp32 -> bf16 hi/lo, store 8B to each of hp/lp
__device__ __forceinline__ void sst4(__nv_bfloat16* hp, __nv_bfloat16* lp, float4 v) {
    __nv_bfloat16 hx = __float2bfloat16_rn(v.x), hy = __float2bfloat16_rn(v.y);
    __nv_bfloat16 hz = __float2bfloat16_rn(v.z), hw = __float2bfloat16_rn(v.w);
    __nv_bfloat162* H = (__nv_bfloat162*)hp;
    H[0] = __halves2bfloat162(hx, hy);
    H[1] = __halves2bfloat162(hz, hw);
    __nv_bfloat162* L = (__nv_bfloat162*)lp;
    L[0] = __halves2bfloat162(__float2bfloat16_rn(v.x - __bfloat162float(hx)),
                              __float2bfloat16_rn(v.y - __bfloat162float(hy)));
    L[1] = __halves2bfloat162(__float2bfloat16_rn(v.z - __bfloat162float(hz)),
                              __float2bfloat16_rn(v.w - __bfloat162float(hw)));
}

__device__ __forceinline__ void split2(__nv_bfloat16* hp, __nv_bfloat16* lp, float a, float b) {
    __nv_bfloat16 ha = __float2bfloat16_rn(a), hb = __float2bfloat16_rn(b);
    *(__nv_bfloat162*)hp = __halves2bfloat162(ha, hb);
    *(__nv_bfloat162*)lp = __halves2bfloat162(
        __float2bfloat16_rn(a - __bfloat162float(ha)),
        __float2bfloat16_rn(b - __bfloat162float(hb)));
}

// ============================================================================
// Kernel 0: split X and Wo into bf16 hi/lo (done once; GEMMs then pure-copy).
// ============================================================================
__global__ __launch_bounds__(256) void convert_inputs(
    const float* __restrict__ X, const float* __restrict__ Wo)
{
    int i0 = blockIdx.x * blockDim.x + threadIdx.x;
    int st = gridDim.x * blockDim.x;
    for (int i = i0; i < MTOK * DD / 4; i += st) {
        float4 v = ((const float4*)X)[i];
        sst4(&g_Xh[i * 4], &g_Xl[i * 4], v);
    }
    for (int i = i0; i < DD * DD / 4; i += st) {
        float4 v = ((const float4*)Wo)[i];
        sst4(&g_Woh[i * 4], &g_Wol[i * 4], v);
    }
}

// ============================================================================
// Kernel 1: Wc[z] = W[z]^T @ R  (TN), bf16x3 + ldmatrix.trans on both operands.
// A stored [k][m] (direct row copy of W), B stored [k][n]. Output = split bf16.
// ============================================================================
__global__ __launch_bounds__(256) void combine_b3(
    const float* __restrict__ Wq, const float* __restrict__ Wk,
    const float* __restrict__ Wv, const float* __restrict__ R)
{
    const int z = blockIdx.z;
    const float* W = (z == 0) ? Wq : ((z == 1) ? Wk : Wv);

    __shared__ __align__(16) __nv_bfloat16 Ath[32][BKS], Atl[32][BKS];
    __shared__ __align__(16) __nv_bfloat16 Bth[32][BKS], Btl[32][BKS];

    const int tid = threadIdx.x, lane = tid & 31, g = lane >> 2, t = lane & 3;
    const int warp = tid >> 5, wm = warp >> 2, wn = warp & 3;
    const int i0 = blockIdx.y * 128, j0 = blockIdx.x * 128;
    const int kr = tid >> 5, cc = (tid & 31) * 4;

    float acc[4][4][4] = {};
    float4 pa[4], pb[4];
    #pragma unroll
    for (int r = 0; r < 4; r++) {
        pa[r] = *(const float4*)&W[(size_t)(kr + r * 8) * DD + i0 + cc];
        pb[r] = *(const float4*)&R[(size_t)(kr + r * 8) * DD + j0 + cc];
    }

    for (int kt = 0; kt < DD; kt += 32) {
        #pragma unroll
        for (int r = 0; r < 4; r++) {
            sst4(&Ath[kr + r * 8][cc], &Atl[kr + r * 8][cc], pa[r]);
            sst4(&Bth[kr + r * 8][cc], &Btl[kr + r * 8][cc], pb[r]);
        }
        __syncthreads();
        if (kt + 32 < DD) {
            #pragma unroll
            for (int r = 0; r < 4; r++) {
                pa[r] = *(const float4*)&W[(size_t)(kt + 32 + kr + r * 8) * DD + i0 + cc];
                pb[r] = *(const float4*)&R[(size_t)(kt + 32 + kr + r * 8) * DD + j0 + cc];
            }
        }
        #pragma unroll
        for (int ks = 0; ks < 2; ks++) {
            const int kk0 = ks * 16;
            uint32_t ah[4][4], al[4][4], bh[2][4], bl[2][4];
            const int arow = kk0 + (lane >> 4) * 8 + (lane & 7);
            const int acol = wm * 64 + ((lane >> 3) & 1) * 8;
            #pragma unroll
            for (int mi = 0; mi < 4; mi++) {
                ldsm4t(ah[mi], &Ath[arow][acol + mi * 16]);
                ldsm4t(al[mi], &Atl[arow][acol + mi * 16]);
            }
            const int brow = kk0 + (lane & 7) + ((lane >> 3) & 1) * 8;
            const int bcol = wn * 32 + (lane >> 4) * 8;
            #pragma unroll
            for (int nj = 0; nj < 2; nj++) {
                ldsm4t(bh[nj], &Bth[brow][bcol + nj * 16]);
                ldsm4t(bl[nj], &Btl[brow][bcol + nj * 16]);
            }
            #pragma unroll
            for (int mi = 0; mi < 4; mi++)
                #pragma unroll
                for (int nj = 0; nj < 2; nj++)
                    #pragma unroll
                    for (int h2 = 0; h2 < 2; h2++) {
                        float* c = acc[mi][nj * 2 + h2];
                        mma16(c, ah[mi], &bh[nj][h2 * 2]);
                        mma16(c, ah[mi], &bl[nj][h2 * 2]);
                        mma16(c, al[mi], &bh[nj][h2 * 2]);
                    }
        }
        __syncthreads();
    }

    __nv_bfloat16* Ch = g_Wch[z];
    __nv_bfloat16* Cl = g_Wcl[z];
    #pragma unroll
    for (int mi = 0; mi < 4; mi++) {
        int row0 = i0 + wm * 64 + mi * 16 + g;
        #pragma unroll
        for (int ni = 0; ni < 4; ni++) {
            int col = j0 + wn * 32 + ni * 8 + 2 * t;
            split2(&Ch[(size_t)row0 * DD + col], &Cl[(size_t)row0 * DD + col],
                   acc[mi][ni][0], acc[mi][ni][1]);
            split2(&Ch[(size_t)(row0 + 8) * DD + col], &Cl[(size_t)(row0 + 8) * DD + col],
                   acc[mi][ni][2], acc[mi][ni][3]);
        }
    }
}

// ============================================================================
// Kernel 2: P = X @ Wc[z] (NN), bf16x3, scatter into [b][h][l][d] fp32.
// A (X split) [m][k] non-trans ldmatrix; B (Wc split) [k][n] trans ldmatrix.
// ============================================================================
__global__ __launch_bounds__(256) void qkv_b3(const float* __restrict__ ent)
{
    const int z = blockIdx.z;
    const __nv_bfloat16* Wh = g_Wch[z];
    const __nv_bfloat16* Wl = g_Wcl[z];
    float* Out = (z == 0) ? g_Q : ((z == 1) ? g_K : g_V);

    __shared__ __align__(16) __nv_bfloat16 Ah[128][AKS], Al[128][AKS];
    __shared__ __align__(16) __nv_bfloat16 Bth[32][BKS], Btl[32][BKS];

    const int tid = threadIdx.x, lane = tid & 31, g = lane >> 2, t = lane & 3;
    const int warp = tid >> 5, wm = warp >> 2, wn = warp & 3;
    const int m0 = blockIdx.y * 128, j0 = blockIdx.x * 128;
    const int b = m0 >> 11;
    const int ar = tid >> 3, akc = (tid & 7) * 4;
    const int kr = tid >> 5, cc = (tid & 31) * 4;

    float acc[4][4][4] = {};
    uint2 pah[4], pal[4], pbh[4], pbl[4];
    #pragma unroll
    for (int r = 0; r < 4; r++) {
        size_t ai = (size_t)(m0 + ar + r * 32) * DD + akc;
        pah[r] = *(const uint2*)&g_Xh[ai];
        pal[r] = *(const uint2*)&g_Xl[ai];
        size_t bi = (size_t)(kr + r * 8) * DD + j0 + cc;
        pbh[r] = *(const uint2*)&Wh[bi];
        pbl[r] = *(const uint2*)&Wl[bi];
    }

    for (int kt = 0; kt < DD; kt += 32) {
        #pragma unroll
        for (int r = 0; r < 4; r++) {
            *(uint2*)&Ah[ar + r * 32][akc] = pah[r];
            *(uint2*)&Al[ar + r * 32][akc] = pal[r];
            *(uint2*)&Bth[kr + r * 8][cc]  = pbh[r];
            *(uint2*)&Btl[kr + r * 8][cc]  = pbl[r];
        }
        __syncthreads();
        if (kt + 32 < DD) {
            #pragma unroll
            for (int r = 0; r < 4; r++) {
                size_t ai = (size_t)(m0 + ar + r * 32) * DD + kt + 32 + akc;
                pah[r] = *(const uint2*)&g_Xh[ai];
                pal[r] = *(const uint2*)&g_Xl[ai];
                size_t bi = (size_t)(kt + 32 + kr + r * 8) * DD + j0 + cc;
                pbh[r] = *(const uint2*)&Wh[bi];
                pbl[r] = *(const uint2*)&Wl[bi];
            }
        }
        #pragma unroll
        for (int ks = 0; ks < 2; ks++) {
            const int kk0 = ks * 16;
            uint32_t ah[4][4], al[4][4], bh[2][4], bl[2][4];
            const int arow = wm * 64 + (lane & 15);
            const int ak   = kk0 + (lane >> 4) * 8;
            #pragma unroll
            for (int mi = 0; mi < 4; mi++) {
                ldsm4(ah[mi], &Ah[arow + mi * 16][ak]);
                ldsm4(al[mi], &Al[arow + mi * 16][ak]);
            }
            const int brow = kk0 + (lane & 7) + ((lane >> 3) & 1) * 8;
            const int bcol = wn * 32 + (lane >> 4) * 8;
            #pragma unroll
            for (int nj = 0; nj < 2; nj++) {
                ldsm4t(bh[nj], &Bth[brow][bcol + nj * 16]);
                ldsm4t(bl[nj], &Btl[brow][bcol + nj * 16]);
            }
            #pragma unroll
            for (int mi = 0; mi < 4; mi++)
                #pragma unroll
                for (int nj = 0; nj < 2; nj++)
                    #pragma unroll
                    for (int h2 = 0; h2 < 2; h2++) {
                        float* c = acc[mi][nj * 2 + h2];
                        mma16(c, ah[mi], &bh[nj][h2 * 2]);
                        mma16(c, ah[mi], &bl[nj][h2 * 2]);
                        mma16(c, al[mi], &bh[nj][h2 * 2]);
                    }
        }
        __syncthreads();
    }

    #pragma unroll
    for (int ni = 0; ni < 4; ni++) {
        int n = j0 + wn * 32 + ni * 8 + 2 * t;
        int h = n >> 6, d = n & 63;
        float s = (z == 0) ? (ent[h] * 0.125f) : 1.0f;
        #pragma unroll
        for (int mi = 0; mi < 4; mi++) {
            int m = m0 + wm * 64 + mi * 16 + g;
            int l = m & (LL - 1);
            size_t base = (((size_t)(b * NH + h)) * LL + l) * HDIM + d;
            *(float2*)&Out[base] =
                make_float2(acc[mi][ni][0] * s, acc[mi][ni][1] * s);
            *(float2*)&Out[base + 8 * HDIM] =
                make_float2(acc[mi][ni][2] * s, acc[mi][ni][3] * s);
        }
    }
}

// ============================================================================
// Kernel 3: flash attention, tf32 mma (unchanged math; epilogue now writes
// O as bf16 hi/lo splits for the bf16x3 out-projection).
// ============================================================================
#define KS_STR 68
#define VS_STR 72
#define PS_STR 68
#define FL_SMEM ((64*KS_STR + 64*VS_STR + 8*16*PS_STR) * 4)

__global__ __launch_bounds__(256) void flash_tf32()
{
    extern __shared__ float sm[];
    float* Ksm = sm;                       // [64][68]
    float* Vsm = sm + 64 * KS_STR;         // [64][72]
    const int tid = threadIdx.x, lane = tid & 31, g = lane >> 2, t = lane & 3;
    const int warp = tid >> 5;
    float* Pw = sm + 64 * KS_STR + 64 * VS_STR + warp * 16 * PS_STR;

    const int bh = blockIdx.y;             // = b*NH + h
    const size_t head_off = (size_t)bh * LL * HDIM;
    const float* Qb = g_Q + head_off;
    const float* Kb = g_K + head_off;
    const float* Vb = g_V + head_off;
    const int q0 = blockIdx.x * 128 + warp * 16;

    uint32_t qa[8][4];
    #pragma unroll
    for (int ks = 0; ks < 8; ks++) {
        qa[ks][0] = f2tf32(Qb[(size_t)(q0 + g) * HDIM + ks * 8 + t]);
        qa[ks][1] = f2tf32(Qb[(size_t)(q0 + 8 + g) * HDIM + ks * 8 + t]);
        qa[ks][2] = f2tf32(Qb[(size_t)(q0 + g) * HDIM + ks * 8 + t + 4]);
        qa[ks][3] = f2tf32(Qb[(size_t)(q0 + 8 + g) * HDIM + ks * 8 + t + 4]);
    }

    float o[8][4] = {};
    float m0v = -1e30f, m1v = -1e30f, l0 = 0.0f, l1 = 0.0f;

    for (int k0 = 0; k0 < LL; k0 += 64) {
        __syncthreads();
        #pragma unroll
        for (int r = 0; r < 4; r++) {
            int idx = tid + r * 256;
            int row = idx >> 4, c = (idx & 15) * 4;
            float4 k4 = *(const float4*)&Kb[(size_t)(k0 + row) * HDIM + c];
            float4 v4 = *(const float4*)&Vb[(size_t)(k0 + row) * HDIM + c];
            *(float4*)&Ksm[row * KS_STR + c] =
                make_float4(tfr(k4.x), tfr(k4.y), tfr(k4.z), tfr(k4.w));
            *(float4*)&Vsm[row * VS_STR + c] =
                make_float4(tfr(v4.x), tfr(v4.y), tfr(v4.z), tfr(v4.w));
        }
        __syncthreads();

        float s[8][4] = {};
        #pragma unroll
        for (int ks = 0; ks < 8; ks++) {
            #pragma unroll
            for (int nt = 0; nt < 8; nt++) {
                uint32_t bf[2];
                bf[0] = __float_as_uint(Ksm[(nt * 8 + g) * KS_STR + ks * 8 + t]);
                bf[1] = __float_as_uint(Ksm[(nt * 8 + g) * KS_STR + ks * 8 + t + 4]);
                mma8(s[nt], qa[ks], bf);
            }
        }

        float rmax0 = -1e30f, rmax1 = -1e30f;
        #pragma unroll
        for (int nt = 0; nt < 8; nt++) {
            rmax0 = fmaxf(rmax0, fmaxf(s[nt][0], s[nt][1]));
            rmax1 = fmaxf(rmax1, fmaxf(s[nt][2], s[nt][3]));
        }
        rmax0 = fmaxf(rmax0, __shfl_xor_sync(0xffffffffu, rmax0, 1));
        rmax0 = fmaxf(rmax0, __shfl_xor_sync(0xffffffffu, rmax0, 2));
        rmax1 = fmaxf(rmax1, __shfl_xor_sync(0xffffffffu, rmax1, 1));
        rmax1 = fmaxf(rmax1, __shfl_xor_sync(0xffffffffu, rmax1, 2));

        float nm0 = fmaxf(m0v, rmax0), nm1 = fmaxf(m1v, rmax1);
        float c0 = __expf(m0v - nm0), c1 = __expf(m1v - nm1);
        m0v = nm0; m1v = nm1;

        float sum0 = 0.0f, sum1 = 0.0f;
        #pragma unroll
        for (int nt = 0; nt < 8; nt++) {
            s[nt][0] = __expf(s[nt][0] - m0v); sum0 += s[nt][0];
            s[nt][1] = __expf(s[nt][1] - m0v); sum0 += s[nt][1];
            s[nt][2] = __expf(s[nt][2] - m1v); sum1 += s[nt][2];
            s[nt][3] = __expf(s[nt][3] - m1v); sum1 += s[nt][3];
        }
        sum0 += __shfl_xor_sync(0xffffffffu, sum0, 1);
        sum0 += __shfl_xor_sync(0xffffffffu, sum0, 2);
        sum1 += __shfl_xor_sync(0xffffffffu, sum1, 1);
        sum1 += __shfl_xor_sync(0xffffffffu, sum1, 2);
        l0 = l0 * c0 + sum0;
        l1 = l1 * c1 + sum1;

        #pragma unroll
        for (int nt = 0; nt < 8; nt++) {
            o[nt][0] *= c0; o[nt][1] *= c0;
            o[nt][2] *= c1; o[nt][3] *= c1;
        }

        #pragma unroll
        for (int nt = 0; nt < 8; nt++) {
            *(float2*)&Pw[g * PS_STR + nt * 8 + 2 * t] =
                make_float2(tfr(s[nt][0]), tfr(s[nt][1]));
            *(float2*)&Pw[(g + 8) * PS_STR + nt * 8 + 2 * t] =
                make_float2(tfr(s[nt][2]), tfr(s[nt][3]));
        }
        __syncwarp();

        #pragma unroll
        for (int ks = 0; ks < 8; ks++) {
            uint32_t pa[4];
            pa[0] = __float_as_uint(Pw[g * PS_STR + ks * 8 + t]);
            pa[1] = __float_as_uint(Pw[(g + 8) * PS_STR + ks * 8 + t]);
            pa[2] = __float_as_uint(Pw[g * PS_STR + ks * 8 + t + 4]);
            pa[3] = __float_as_uint(Pw[(g + 8) * PS_STR + ks * 8 + t + 4]);
            #pragma unroll
            for (int nt = 0; nt < 8; nt++) {
                uint32_t bf[2];
                bf[0] = __float_as_uint(Vsm[(ks * 8 + t) * VS_STR + nt * 8 + g]);
                bf[1] = __float_as_uint(Vsm[(ks * 8 + t + 4) * VS_STR + nt * 8 + g]);
                mma8(o[nt], pa, bf);
            }
        }
        __syncwarp();
    }

    const int b = bh >> 4, h = bh & 15;
    float inv0 = 1.0f / l0, inv1 = 1.0f / l1;
    size_t ob0 = ((size_t)b * LL + q0 + g) * DD + h * HDIM;
    size_t ob1 = ((size_t)b * LL + q0 + 8 + g) * DD + h * HDIM;
    #pragma unroll
    for (int nt = 0; nt < 8; nt++) {
        int col = nt * 8 + 2 * t;
        split2(&g_Oh[ob0 + col], &g_Ol[ob0 + col], o[nt][0] * inv0, o[nt][1] * inv0);
        split2(&g_Oh[ob1 + col], &g_Ol[ob1 + col], o[nt][2] * inv1, o[nt][3] * inv1);
    }
}

// ============================================================================
// Kernel 4: Y = O @ Wo^T (NT), bf16x3. A [m][k], B [n][k], both non-trans.
// ============================================================================
__global__ __launch_bounds__(256) void out_b3(float* __restrict__ Y)
{
    __shared__ __align__(16) __nv_bfloat16 Ah[128][AKS], Al[128][AKS];
    __shared__ __align__(16) __nv_bfloat16 Bh[128][AKS], Bl[128][AKS];

    const int tid = threadIdx.x, lane = tid & 31, g = lane >> 2, t = lane & 3;
    const int warp = tid >> 5, wm = warp >> 2, wn = warp & 3;
    const int m0 = blockIdx.y * 128, j0 = blockIdx.x * 128;
    const int ar = tid >> 3, akc = (tid & 7) * 4;

    float acc[4][4][4] = {};
    uint2 pah[4], pal[4], pbh[4], pbl[4];
    #pragma unroll
    for (int r = 0; r < 4; r++) {
        size_t ai = (size_t)(m0 + ar + r * 32) * DD + akc;
        pah[r] = *(const uint2*)&g_Oh[ai];
        pal[r] = *(const uint2*)&g_Ol[ai];
        size_t bi = (size_t)(j0 + ar + r * 32) * DD + akc;
        pbh[r] = *(const uint2*)&g_Woh[bi];
        pbl[r] = *(const uint2*)&g_Wol[bi];
    }

    for (int kt = 0; kt < DD; kt += 32) {
        #pragma unroll
        for (int r = 0; r < 4; r++) {
            *(uint2*)&Ah[ar + r * 32][akc] = pah[r];
            *(uint2*)&Al[ar + r * 32][akc] = pal[r];
            *(uint2*)&Bh[ar + r * 32][akc] = pbh[r];
            *(uint2*)&Bl[ar + r * 32][akc] = pbl[r];
        }
        __syncthreads();
        if (kt + 32 < DD) {
            #pragma unroll
            for (int r = 0; r < 4; r++) {
                size_t ai = (size_t)(m0 + ar + r * 32) * DD + kt + 32 + akc;
                pah[r] = *(const uint2*)&g_Oh[ai];
                pal[r] = *(const uint2*)&g_Ol[ai];
                size_t bi = (size_t)(j0 + ar + r * 32) * DD + kt + 32 + akc;
                pbh[r] = *(const uint2*)&g_Woh[bi];
                pbl[r] = *(const uint2*)&g_Wol[bi];
            }
        }
        #pragma unroll
        for (int ks = 0; ks < 2; ks++) {
            const int kk0 = ks * 16;
            uint32_t ah[4][4], al[4][4], bh[2][4], bl[2][4];
            const int arow = wm * 64 + (lane & 15);
            const int ak   = kk0 + (lane >> 4) * 8;
            #pragma unroll
            for (int mi = 0; mi < 4; mi++) {
                ldsm4(ah[mi], &Ah[arow + mi * 16][ak]);
                ldsm4(al[mi], &Al[arow + mi * 16][ak]);
            }
            const int brow = wn * 32 + (lane & 7) + ((lane >> 4) & 1) * 8;
            const int bk   = kk0 + ((lane >> 3) & 1) * 8;
            #pragma unroll
            for (int nj = 0; nj < 2; nj++) {
                ldsm4(bh[nj], &Bh[brow + nj * 16][bk]);
                ldsm4(bl[nj], &Bl[brow + nj * 16][bk]);
            }
            #pragma unroll
            for (int mi = 0; mi < 4; mi++)
                #pragma unroll
                for (int nj = 0; nj < 2; nj++)
                    #pragma unroll
                    for (int h2 = 0; h2 < 2; h2++) {
                        float* c = acc[mi][nj * 2 + h2];
                        mma16(c, ah[mi], &bh[nj][h2 * 2]);
                        mma16(c, ah[mi], &bl[nj][h2 * 2]);
                        mma16(c, al[mi], &bh[nj][h2 * 2]);
                    }
        }
        __syncthreads();
    }

    #pragma unroll
    for (int mi = 0; mi < 4; mi++) {
        int row0 = m0 + wm * 64 + mi * 16 + g;
        #pragma unroll
        for (int ni = 0; ni < 4; ni++) {
            int col = j0 + wn * 32 + ni * 8 + 2 * t;
            *(float2*)&Y[(size_t)row0 * DD + col] =
                make_float2(acc[mi][ni][0], acc[mi][ni][1]);
            *(float2*)&Y[(size_t)(row0 + 8) * DD + col] =
                make_float2(acc[mi][ni][2], acc[mi][ni][3]);
        }
    }
}

// ============================================================================
// launch
// Inputs: 0=inputs 1=rotation 2=entangle 3=Wq 4=Wk 5=Wv 6=Wo; out (B,L,D) fp32
// ============================================================================
extern "C" void kernel_launch(void* const* d_in, const int* in_sizes, int n_in,
                              void* d_out, int out_size)
{
    const float* X   = (const float*)d_in[0];
    const float* R   = (const float*)d_in[1];
    const float* ent = (const float*)d_in[2];
    const float* Wq  = (const float*)d_in[3];
    const float* Wk  = (const float*)d_in[4];
    const float* Wv  = (const float*)d_in[5];
    const float* Wo  = (const float*)d_in[6];
    float* Y = (float*)d_out;

    cudaFuncSetAttribute(flash_tf32,
                         cudaFuncAttributeMaxDynamicSharedMemorySize, FL_SMEM);

    convert_inputs<<<1184, 256>>>(X, Wo);
    combine_b3<<<dim3(8, 8, 3), 256>>>(Wq, Wk, Wv, R);
    qkv_b3<<<dim3(8, MTOK / 128, 3), 256>>>(ent);
    flash_tf32<<<dim3(LL / 128, BB * NH), 256, FL_SMEM>>>();
    out_b3<<<dim3(8, MTOK / 128), 256>>>(Y);
}

// round 8
// speedup vs baseline: 1.0624x; 1.0624x over previous
#include <cuda_runtime.h>
#include <cuda_bf16.h>
#include <stdint.h>
#include <math.h>

#define DD   1024
#define NH   16
#define HDIM 64
#define BB   2
#define LL   2048
#define MTOK (BB*LL)   // 4096

#define AKS 40     // [row][k] bf16 smem stride (32 + 8)
#define BKS 136    // [k][n]  bf16 smem stride (128 + 8)

// ---------------- scratch (device globals; no allocations allowed) ----------
__device__ __nv_bfloat16 g_Wch[3][DD*DD], g_Wcl[3][DD*DD];  // combined W^T@R, split
__device__ __nv_bfloat16 g_Xh[MTOK*DD],  g_Xl[MTOK*DD];     // X split
__device__ __nv_bfloat16 g_Woh[DD*DD],   g_Wol[DD*DD];      // Wo split
__device__ __nv_bfloat16 g_Oh[MTOK*DD],  g_Ol[MTOK*DD];     // attn out (B,L,D) split
// Q,K: [b][h][l][cperm(d)]  tf32-rounded, Q pre-scaled by ent/8
// V:   [b][h] groups of 64 keys: [l>>6][rv(l&63)][2d + b(l&63)]  tf32-rounded
__device__ float g_Q[BB*NH*LL*HDIM];
__device__ float g_K[BB*NH*LL*HDIM];
__device__ float g_V[BB*NH*LL*HDIM];

// ---------------- helpers ----------------------------------------------------
__device__ __forceinline__ uint32_t f2tf32(float x) {
    uint32_t u;
    asm("cvt.rna.tf32.f32 %0, %1;" : "=r"(u) : "f"(x));
    return u;
}
__device__ __forceinline__ float tfr(float x) { return __uint_as_float(f2tf32(x)); }

__device__ __forceinline__ void mma8(float d[4], const uint32_t a[4], const uint32_t b[2]) {
    asm volatile(
        "mma.sync.aligned.m16n8k8.row.col.f32.tf32.tf32.f32 "
        "{%0,%1,%2,%3}, {%4,%5,%6,%7}, {%8,%9}, {%0,%1,%2,%3};"
        : "+f"(d[0]), "+f"(d[1]), "+f"(d[2]), "+f"(d[3])
        : "r"(a[0]), "r"(a[1]), "r"(a[2]), "r"(a[3]), "r"(b[0]), "r"(b[1]));
}

__device__ __forceinline__ void mma16(float* d, const uint32_t* a, const uint32_t* b) {
    asm volatile(
        "mma.sync.aligned.m16n8k16.row.col.f32.bf16.bf16.f32 "
        "{%0,%1,%2,%3}, {%4,%5,%6,%7}, {%8,%9}, {%0,%1,%2,%3};"
        : "+f"(d[0]), "+f"(d[1]), "+f"(d[2]), "+f"(d[3])
        : "r"(a[0]), "r"(a[1]), "r"(a[2]), "r"(a[3]), "r"(b[0]), "r"(b[1]));
}

__device__ __forceinline__ void ldsm4(uint32_t* r, const void* p) {
    uint32_t a = (uint32_t)__cvta_generic_to_shared(p);
    asm volatile("ldmatrix.sync.aligned.m8n8.x4.shared.b16 {%0,%1,%2,%3}, [%4];"
        : "=r"(r[0]), "=r"(r[1]), "=r"(r[2]), "=r"(r[3]) : "r"(a));
}
__device__ __forceinline__ void ldsm4t(uint32_t* r, const void* p) {
    uint32_t a = (uint32_t)__cvta_generic_to_shared(p);
    asm volatile("ldmatrix.sync.aligned.m8n8.x4.trans.shared.b16 {%0,%1,%2,%3}, [%4];"
        : "=r"(r[0]), "=r"(r[1]), "=r"(r[2]), "=r"(r[3]) : "r"(a));
}

__device__ __forceinline__ void cpa16(void* smem, const void* gmem) {
    uint32_t s = (uint32_t)__cvta_generic_to_shared(smem);
    asm volatile("cp.async.cg.shared.global [%0], [%1], 16;" :: "r"(s), "l"(gmem) : "memory");
}
#define CP_COMMIT() asm volatile("cp.async.commit_group;" ::: "memory")
#define CP_WAIT0()  asm volatile("cp.async.wait_group 0;" ::: "memory")

// split 4 fp32 -> bf16 hi/lo, store 8B to each of hp/lp
__device__ __forceinline__ void sst4(__nv_bfloat16* hp, __nv_bfloat16* lp, float4 v) {
    __nv_bfloat16 hx = __float2bfloat16_rn(v.x), hy = __float2bfloat16_rn(v.y);
    __nv_bfloat16 hz = __float2bfloat16_rn(v.z), hw = __float2bfloat16_rn(v.w);
    __nv_bfloat162* H = (__nv_bfloat162*)hp;
    H[0] = __halves2bfloat162(hx, hy);
    H[1] = __halves2bfloat162(hz, hw);
    __nv_bfloat162* L = (__nv_bfloat162*)lp;
    L[0] = __halves2bfloat162(__float2bfloat16_rn(v.x - __bfloat162float(hx)),
                              __float2bfloat16_rn(v.y - __bfloat162float(hy)));
    L[1] = __halves2bfloat162(__float2bfloat16_rn(v.z - __bfloat162float(hz)),
                              __float2bfloat16_rn(v.w - __bfloat162float(hw)));
}

__device__ __forceinline__ void split2(__nv_bfloat16* hp, __nv_bfloat16* lp, float a, float b) {
    __nv_bfloat16 ha = __float2bfloat16_rn(a), hb = __float2bfloat16_rn(b);
    *(__nv_bfloat162*)hp = __halves2bfloat162(ha, hb);
    *(__nv_bfloat162*)lp = __halves2bfloat162(
        __float2bfloat16_rn(a - __bfloat162float(ha)),
        __float2bfloat16_rn(b - __bfloat162float(hb)));
}

// ============================================================================
// Kernel 0: split X and Wo into bf16 hi/lo.
// ============================================================================
__global__ __launch_bounds__(256) void convert_inputs(
    const float* __restrict__ X, const float* __restrict__ Wo)
{
    int i0 = blockIdx.x * blockDim.x + threadIdx.x;
    int st = gridDim.x * blockDim.x;
    for (int i = i0; i < MTOK * DD / 4; i += st) {
        float4 v = ((const float4*)X)[i];
        sst4(&g_Xh[i * 4], &g_Xl[i * 4], v);
    }
    for (int i = i0; i < DD * DD / 4; i += st) {
        float4 v = ((const float4*)Wo)[i];
        sst4(&g_Woh[i * 4], &g_Wol[i * 4], v);
    }
}

// ============================================================================
// Kernel 1: Wc[z] = W[z]^T @ R  (TN), bf16x3 + ldmatrix.trans both operands.
// ============================================================================
__global__ __launch_bounds__(256) void combine_b3(
    const float* __restrict__ Wq, const float* __restrict__ Wk,
    const float* __restrict__ Wv, const float* __restrict__ R)
{
    const int z = blockIdx.z;
    const float* W = (z == 0) ? Wq : ((z == 1) ? Wk : Wv);

    __shared__ __align__(16) __nv_bfloat16 Ath[32][BKS], Atl[32][BKS];
    __shared__ __align__(16) __nv_bfloat16 Bth[32][BKS], Btl[32][BKS];

    const int tid = threadIdx.x, lane = tid & 31, g = lane >> 2, t = lane & 3;
    const int warp = tid >> 5, wm = warp >> 2, wn = warp & 3;
    const int i0 = blockIdx.y * 128, j0 = blockIdx.x * 128;
    const int kr = tid >> 5, cc = (tid & 31) * 4;

    float acc[4][4][4] = {};
    float4 pa[4], pb[4];
    #pragma unroll
    for (int r = 0; r < 4; r++) {
        pa[r] = *(const float4*)&W[(size_t)(kr + r * 8) * DD + i0 + cc];
        pb[r] = *(const float4*)&R[(size_t)(kr + r * 8) * DD + j0 + cc];
    }

    for (int kt = 0; kt < DD; kt += 32) {
        #pragma unroll
        for (int r = 0; r < 4; r++) {
            sst4(&Ath[kr + r * 8][cc], &Atl[kr + r * 8][cc], pa[r]);
            sst4(&Bth[kr + r * 8][cc], &Btl[kr + r * 8][cc], pb[r]);
        }
        __syncthreads();
        if (kt + 32 < DD) {
            #pragma unroll
            for (int r = 0; r < 4; r++) {
                pa[r] = *(const float4*)&W[(size_t)(kt + 32 + kr + r * 8) * DD + i0 + cc];
                pb[r] = *(const float4*)&R[(size_t)(kt + 32 + kr + r * 8) * DD + j0 + cc];
            }
        }
        #pragma unroll
        for (int ks = 0; ks < 2; ks++) {
            const int kk0 = ks * 16;
            uint32_t ah[4][4], al[4][4], bh[2][4], bl[2][4];
            const int arow = kk0 + (lane >> 4) * 8 + (lane & 7);
            const int acol = wm * 64 + ((lane >> 3) & 1) * 8;
            #pragma unroll
            for (int mi = 0; mi < 4; mi++) {
                ldsm4t(ah[mi], &Ath[arow][acol + mi * 16]);
                ldsm4t(al[mi], &Atl[arow][acol + mi * 16]);
            }
            const int brow = kk0 + (lane & 7) + ((lane >> 3) & 1) * 8;
            const int bcol = wn * 32 + (lane >> 4) * 8;
            #pragma unroll
            for (int nj = 0; nj < 2; nj++) {
                ldsm4t(bh[nj], &Bth[brow][bcol + nj * 16]);
                ldsm4t(bl[nj], &Btl[brow][bcol + nj * 16]);
            }
            #pragma unroll
            for (int mi = 0; mi < 4; mi++)
                #pragma unroll
                for (int nj = 0; nj < 2; nj++)
                    #pragma unroll
                    for (int h2 = 0; h2 < 2; h2++) {
                        float* c = acc[mi][nj * 2 + h2];
                        mma16(c, ah[mi], &bh[nj][h2 * 2]);
                        mma16(c, ah[mi], &bl[nj][h2 * 2]);
                        mma16(c, al[mi], &bh[nj][h2 * 2]);
                    }
        }
        __syncthreads();
    }

    __nv_bfloat16* Ch = g_Wch[z];
    __nv_bfloat16* Cl = g_Wcl[z];
    #pragma unroll
    for (int mi = 0; mi < 4; mi++) {
        int row0 = i0 + wm * 64 + mi * 16 + g;
        #pragma unroll
        for (int ni = 0; ni < 4; ni++) {
            int col = j0 + wn * 32 + ni * 8 + 2 * t;
            split2(&Ch[(size_t)row0 * DD + col], &Cl[(size_t)row0 * DD + col],
                   acc[mi][ni][0], acc[mi][ni][1]);
            split2(&Ch[(size_t)(row0 + 8) * DD + col], &Cl[(size_t)(row0 + 8) * DD + col],
                   acc[mi][ni][2], acc[mi][ni][3]);
        }
    }
}

// ============================================================================
// Kernel 2: P = X @ Wc[z] (NN), bf16x3, scatter into flash-ready layouts:
//  z=0/1 (Q,K): [b][h][l][cperm(d)] tf32, Q scaled by ent/8.
//  z=2   (V)  : per head, per 64-key group: [rv][2d+b] tf32.
// ============================================================================
__global__ __launch_bounds__(256) void qkv_b3(const float* __restrict__ ent)
{
    const int z = blockIdx.z;
    const __nv_bfloat16* Wh = g_Wch[z];
    const __nv_bfloat16* Wl = g_Wcl[z];
    float* Out = (z == 0) ? g_Q : ((z == 1) ? g_K : g_V);

    __shared__ __align__(16) __nv_bfloat16 Ah[128][AKS], Al[128][AKS];
    __shared__ __align__(16) __nv_bfloat16 Bth[32][BKS], Btl[32][BKS];

    const int tid = threadIdx.x, lane = tid & 31, g = lane >> 2, t = lane & 3;
    const int warp = tid >> 5, wm = warp >> 2, wn = warp & 3;
    const int m0 = blockIdx.y * 128, j0 = blockIdx.x * 128;
    const int b = m0 >> 11;
    const int ar = tid >> 3, akc = (tid & 7) * 4;
    const int kr = tid >> 5, cc = (tid & 31) * 4;

    float acc[4][4][4] = {};
    uint2 pah[4], pal[4], pbh[4], pbl[4];
    #pragma unroll
    for (int r = 0; r < 4; r++) {
        size_t ai = (size_t)(m0 + ar + r * 32) * DD + akc;
        pah[r] = *(const uint2*)&g_Xh[ai];
        pal[r] = *(const uint2*)&g_Xl[ai];
        size_t bi = (size_t)(kr + r * 8) * DD + j0 + cc;
        pbh[r] = *(const uint2*)&Wh[bi];
        pbl[r] = *(const uint2*)&Wl[bi];
    }

    for (int kt = 0; kt < DD; kt += 32) {
        #pragma unroll
        for (int r = 0; r < 4; r++) {
            *(uint2*)&Ah[ar + r * 32][akc] = pah[r];
            *(uint2*)&Al[ar + r * 32][akc] = pal[r];
            *(uint2*)&Bth[kr + r * 8][cc]  = pbh[r];
            *(uint2*)&Btl[kr + r * 8][cc]  = pbl[r];
        }
        __syncthreads();
        if (kt + 32 < DD) {
            #pragma unroll
            for (int r = 0; r < 4; r++) {
                size_t ai = (size_t)(m0 + ar + r * 32) * DD + kt + 32 + akc;
                pah[r] = *(const uint2*)&g_Xh[ai];
                pal[r] = *(const uint2*)&g_Xl[ai];
                size_t bi = (size_t)(kt + 32 + kr + r * 8) * DD + j0 + cc;
                pbh[r] = *(const uint2*)&Wh[bi];
                pbl[r] = *(const uint2*)&Wl[bi];
            }
        }
        #pragma unroll
        for (int ks = 0; ks < 2; ks++) {
            const int kk0 = ks * 16;
            uint32_t ah[4][4], al[4][4], bh[2][4], bl[2][4];
            const int arow = wm * 64 + (lane & 15);
            const int ak   = kk0 + (lane >> 4) * 8;
            #pragma unroll
            for (int mi = 0; mi < 4; mi++) {
                ldsm4(ah[mi], &Ah[arow + mi * 16][ak]);
                ldsm4(al[mi], &Al[arow + mi * 16][ak]);
            }
            const int brow = kk0 + (lane & 7) + ((lane >> 3) & 1) * 8;
            const int bcol = wn * 32 + (lane >> 4) * 8;
            #pragma unroll
            for (int nj = 0; nj < 2; nj++) {
                ldsm4t(bh[nj], &Bth[brow][bcol + nj * 16]);
                ldsm4t(bl[nj], &Btl[brow][bcol + nj * 16]);
            }
            #pragma unroll
            for (int mi = 0; mi < 4; mi++)
                #pragma unroll
                for (int nj = 0; nj < 2; nj++)
                    #pragma unroll
                    for (int h2 = 0; h2 < 2; h2++) {
                        float* c = acc[mi][nj * 2 + h2];
                        mma16(c, ah[mi], &bh[nj][h2 * 2]);
                        mma16(c, ah[mi], &bl[nj][h2 * 2]);
                        mma16(c, al[mi], &bh[nj][h2 * 2]);
                    }
        }
        __syncthreads();
    }

    if (z < 2) {
        #pragma unroll
        for (int ni = 0; ni < 4; ni++) {
            int n = j0 + wn * 32 + ni * 8 + 2 * t;
            int h = n >> 6, d = n & 63;
            int c1 = (d & 0x38) + ((d & 3) << 1) + ((d >> 2) & 1);
            float s = (z == 0) ? (ent[h] * 0.125f) : 1.0f;
            #pragma unroll
            for (int mi = 0; mi < 4; mi++) {
                int m = m0 + wm * 64 + mi * 16 + g;
                int l = m & (LL - 1);
                size_t base = (((size_t)(b * NH + h)) * LL + l) * HDIM;
                Out[base + c1]              = tfr(acc[mi][ni][0] * s);
                Out[base + c1 + 2]          = tfr(acc[mi][ni][1] * s);
                Out[base + 8 * HDIM + c1]     = tfr(acc[mi][ni][2] * s);
                Out[base + 8 * HDIM + c1 + 2] = tfr(acc[mi][ni][3] * s);
            }
        }
    } else {
        #pragma unroll
        for (int ni = 0; ni < 4; ni++) {
            int n = j0 + wn * 32 + ni * 8 + 2 * t;
            int h = n >> 6, d = n & 63;
            #pragma unroll
            for (int mi = 0; mi < 4; mi++) {
                int m = m0 + wm * 64 + mi * 16 + g;
                int l = m & (LL - 1);
                int l6 = l & 63;
                int rv = ((l6 >> 3) << 2) + (l6 & 3);
                int bb = (l6 >> 2) & 1;
                size_t base = ((size_t)(b * NH + h)) * LL * HDIM
                            + (size_t)(l >> 6) * 4096 + rv * 128 + 2 * d + bb;
                Out[base]           = tfr(acc[mi][ni][0]);
                Out[base + 2]       = tfr(acc[mi][ni][1]);
                Out[base + 512]     = tfr(acc[mi][ni][2]);   // row l+8 -> rv+4
                Out[base + 512 + 2] = tfr(acc[mi][ni][3]);
            }
        }
    }
}

// ============================================================================
// Kernel 3: flash attention, tf32 mma, pair-interleaved layouts (LDS.64 frags),
// cp.async double-buffered K/V, 2 CTAs/SM.
// smem floats: K 2*64*72, V 2*32*144, P 8*16*72  = 27648 floats = 108 KB
// ============================================================================
#define FL2_SMEM (27648 * 4)

__global__ __launch_bounds__(256, 2) void flash2()
{
    extern __shared__ float sm[];
    float* Ksb0 = sm;
    float* Ksb1 = sm + 4608;
    float* Vsb0 = sm + 9216;
    float* Vsb1 = sm + 13824;
    const int tid = threadIdx.x, lane = tid & 31, g = lane >> 2, t = lane & 3;
    const int warp = tid >> 5;
    float* Pw = sm + 18432 + warp * (16 * 72);

    const int bh = blockIdx.y;
    const size_t head = (size_t)bh * LL * HDIM;
    const float* Qb = g_Q + head;
    const float* Kb = g_K + head;
    const float* Vb = g_V + head;
    const int q0 = blockIdx.x * 128 + warp * 16;

    // Q fragments (already tf32-rounded, column-permuted in global)
    uint32_t qa[8][4];
    #pragma unroll
    for (int ks = 0; ks < 8; ks++) {
        float2 p0 = *(const float2*)&Qb[(size_t)(q0 + g) * HDIM + ks * 8 + 2 * t];
        float2 p1 = *(const float2*)&Qb[(size_t)(q0 + 8 + g) * HDIM + ks * 8 + 2 * t];
        qa[ks][0] = __float_as_uint(p0.x); qa[ks][2] = __float_as_uint(p0.y);
        qa[ks][1] = __float_as_uint(p1.x); qa[ks][3] = __float_as_uint(p1.y);
    }

    const int krow = tid >> 4, kcol = (tid & 15) * 4;   // K: 64 rows x 64, 4 iters
    const int vrow = tid >> 5, vcol = (tid & 31) * 4;   // V: 32 rows x 128, 4 iters

    float o[8][4] = {};
    float m0v = -1e30f, m1v = -1e30f, l0 = 0.0f, l1 = 0.0f;

    // prologue: tile 0 -> buffer 0
    #pragma unroll
    for (int r = 0; r < 4; r++) {
        cpa16(&Ksb0[(krow + 16 * r) * 72 + kcol], &Kb[(size_t)(krow + 16 * r) * 64 + kcol]);
        cpa16(&Vsb0[(vrow + 8 * r) * 144 + vcol], &Vb[(size_t)(vrow + 8 * r) * 128 + vcol]);
    }
    CP_COMMIT();

    for (int it = 0; it < LL / 64; ++it) {
        CP_WAIT0();
        __syncthreads();
        if (it + 1 < LL / 64) {
            const float* Ksrc = Kb + (size_t)(it + 1) * 4096;
            const float* Vsrc = Vb + (size_t)(it + 1) * 4096;
            float* Kd = ((it + 1) & 1) ? Ksb1 : Ksb0;
            float* Vd = ((it + 1) & 1) ? Vsb1 : Vsb0;
            #pragma unroll
            for (int r = 0; r < 4; r++) {
                cpa16(&Kd[(krow + 16 * r) * 72 + kcol], &Ksrc[(size_t)(krow + 16 * r) * 64 + kcol]);
                cpa16(&Vd[(vrow + 8 * r) * 144 + vcol], &Vsrc[(size_t)(vrow + 8 * r) * 128 + vcol]);
            }
            CP_COMMIT();
        }
        const float* Ksm = (it & 1) ? Ksb1 : Ksb0;
        const float* Vsm = (it & 1) ? Vsb1 : Vsb0;

        // S = Q @ K^T : 16 x 64 per warp
        float s[8][4] = {};
        #pragma unroll
        for (int ks = 0; ks < 8; ks++) {
            #pragma unroll
            for (int nt = 0; nt < 8; nt++) {
                float2 bp = *(const float2*)&Ksm[(nt * 8 + g) * 72 + ks * 8 + 2 * t];
                uint32_t bf[2] = { __float_as_uint(bp.x), __float_as_uint(bp.y) };
                mma8(s[nt], qa[ks], bf);
            }
        }

        // online softmax (rows g and g+8, spread over 4 lanes each)
        float rmax0 = -1e30f, rmax1 = -1e30f;
        #pragma unroll
        for (int nt = 0; nt < 8; nt++) {
            rmax0 = fmaxf(rmax0, fmaxf(s[nt][0], s[nt][1]));
            rmax1 = fmaxf(rmax1, fmaxf(s[nt][2], s[nt][3]));
        }
        rmax0 = fmaxf(rmax0, __shfl_xor_sync(0xffffffffu, rmax0, 1));
        rmax0 = fmaxf(rmax0, __shfl_xor_sync(0xffffffffu, rmax0, 2));
        rmax1 = fmaxf(rmax1, __shfl_xor_sync(0xffffffffu, rmax1, 1));
        rmax1 = fmaxf(rmax1, __shfl_xor_sync(0xffffffffu, rmax1, 2));

        float nm0 = fmaxf(m0v, rmax0), nm1 = fmaxf(m1v, rmax1);
        float c0 = __expf(m0v - nm0), c1 = __expf(m1v - nm1);
        m0v = nm0; m1v = nm1;

        float sum0 = 0.0f, sum1 = 0.0f;
        #pragma unroll
        for (int nt = 0; nt < 8; nt++) {
            s[nt][0] = __expf(s[nt][0] - m0v); sum0 += s[nt][0];
            s[nt][1] = __expf(s[nt][1] - m0v); sum0 += s[nt][1];
            s[nt][2] = __expf(s[nt][2] - m1v); sum1 += s[nt][2];
            s[nt][3] = __expf(s[nt][3] - m1v); sum1 += s[nt][3];
        }
        sum0 += __shfl_xor_sync(0xffffffffu, sum0, 1);
        sum0 += __shfl_xor_sync(0xffffffffu, sum0, 2);
        sum1 += __shfl_xor_sync(0xffffffffu, sum1, 1);
        sum1 += __shfl_xor_sync(0xffffffffu, sum1, 2);
        l0 = l0 * c0 + sum0;
        l1 = l1 * c1 + sum1;

        #pragma unroll
        for (int nt = 0; nt < 8; nt++) {
            o[nt][0] *= c0; o[nt][1] *= c0;
            o[nt][2] *= c1; o[nt][3] *= c1;
        }

        // P -> warp-private smem, tf32-rounded, column-interleaved
        #pragma unroll
        for (int nt = 0; nt < 8; nt++) {
            int j1 = nt * 8 + 2 * t;
            int cidx = (j1 & 0x38) + ((j1 & 3) << 1) + ((j1 >> 2) & 1);
            Pw[g * 72 + cidx]           = tfr(s[nt][0]);
            Pw[g * 72 + cidx + 2]       = tfr(s[nt][1]);
            Pw[(g + 8) * 72 + cidx]     = tfr(s[nt][2]);
            Pw[(g + 8) * 72 + cidx + 2] = tfr(s[nt][3]);
        }
        __syncwarp();

        // O += P @ V
        #pragma unroll
        for (int ks = 0; ks < 8; ks++) {
            float2 pA = *(const float2*)&Pw[g * 72 + ks * 8 + 2 * t];
            float2 pB = *(const float2*)&Pw[(g + 8) * 72 + ks * 8 + 2 * t];
            uint32_t pa[4] = { __float_as_uint(pA.x), __float_as_uint(pB.x),
                               __float_as_uint(pA.y), __float_as_uint(pB.y) };
            #pragma unroll
            for (int nt = 0; nt < 8; nt++) {
                float2 bp = *(const float2*)&Vsm[(ks * 4 + t) * 144 + 2 * (nt * 8 + g)];
                uint32_t bf[2] = { __float_as_uint(bp.x), __float_as_uint(bp.y) };
                mma8(o[nt], pa, bf);
            }
        }
        __syncwarp();
        __syncthreads();
    }

    const int b = bh >> 4, h = bh & 15;
    float inv0 = 1.0f / l0, inv1 = 1.0f / l1;
    size_t ob0 = ((size_t)b * LL + q0 + g) * DD + h * HDIM;
    size_t ob1 = ((size_t)b * LL + q0 + 8 + g) * DD + h * HDIM;
    #pragma unroll
    for (int nt = 0; nt < 8; nt++) {
        int col = nt * 8 + 2 * t;
        split2(&g_Oh[ob0 + col], &g_Ol[ob0 + col], o[nt][0] * inv0, o[nt][1] * inv0);
        split2(&g_Oh[ob1 + col], &g_Ol[ob1 + col], o[nt][2] * inv1, o[nt][3] * inv1);
    }
}

// ============================================================================
// Kernel 4: Y = O @ Wo^T (NT), bf16x3.
// ============================================================================
__global__ __launch_bounds__(256) void out_b3(float* __restrict__ Y)
{
    __shared__ __align__(16) __nv_bfloat16 Ah[128][AKS], Al[128][AKS];
    __shared__ __align__(16) __nv_bfloat16 Bh[128][AKS], Bl[128][AKS];

    const int tid = threadIdx.x, lane = tid & 31, g = lane >> 2, t = lane & 3;
    const int warp = tid >> 5, wm = warp >> 2, wn = warp & 3;
    const int m0 = blockIdx.y * 128, j0 = blockIdx.x * 128;
    const int ar = tid >> 3, akc = (tid & 7) * 4;

    float acc[4][4][4] = {};
    uint2 pah[4], pal[4], pbh[4], pbl[4];
    #pragma unroll
    for (int r = 0; r < 4; r++) {
        size_t ai = (size_t)(m0 + ar + r * 32) * DD + akc;
        pah[r] = *(const uint2*)&g_Oh[ai];
        pal[r] = *(const uint2*)&g_Ol[ai];
        size_t bi = (size_t)(j0 + ar + r * 32) * DD + akc;
        pbh[r] = *(const uint2*)&g_Woh[bi];
        pbl[r] = *(const uint2*)&g_Wol[bi];
    }

    for (int kt = 0; kt < DD; kt += 32) {
        #pragma unroll
        for (int r = 0; r < 4; r++) {
            *(uint2*)&Ah[ar + r * 32][akc] = pah[r];
            *(uint2*)&Al[ar + r * 32][akc] = pal[r];
            *(uint2*)&Bh[ar + r * 32][akc] = pbh[r];
            *(uint2*)&Bl[ar + r * 32][akc] = pbl[r];
        }
        __syncthreads();
        if (kt + 32 < DD) {
            #pragma unroll
            for (int r = 0; r < 4; r++) {
                size_t ai = (size_t)(m0 + ar + r * 32) * DD + kt + 32 + akc;
                pah[r] = *(const uint2*)&g_Oh[ai];
                pal[r] = *(const uint2*)&g_Ol[ai];
                size_t bi = (size_t)(j0 + ar + r * 32) * DD + kt + 32 + akc;
                pbh[r] = *(const uint2*)&g_Woh[bi];
                pbl[r] = *(const uint2*)&g_Wol[bi];
            }
        }
        #pragma unroll
        for (int ks = 0; ks < 2; ks++) {
            const int kk0 = ks * 16;
            uint32_t ah[4][4], al[4][4], bh[2][4], bl[2][4];
            const int arow = wm * 64 + (lane & 15);
            const int ak   = kk0 + (lane >> 4) * 8;
            #pragma unroll
            for (int mi = 0; mi < 4; mi++) {
                ldsm4(ah[mi], &Ah[arow + mi * 16][ak]);
                ldsm4(al[mi], &Al[arow + mi * 16][ak]);
            }
            const int brow = wn * 32 + (lane & 7) + ((lane >> 4) & 1) * 8;
            const int bk   = kk0 + ((lane >> 3) & 1) * 8;
            #pragma unroll
            for (int nj = 0; nj < 2; nj++) {
                ldsm4(bh[nj], &Bh[brow + nj * 16][bk]);
                ldsm4(bl[nj], &Bl[brow + nj * 16][bk]);
            }
            #pragma unroll
            for (int mi = 0; mi < 4; mi++)
                #pragma unroll
                for (int nj = 0; nj < 2; nj++)
                    #pragma unroll
                    for (int h2 = 0; h2 < 2; h2++) {
                        float* c = acc[mi][nj * 2 + h2];
                        mma16(c, ah[mi], &bh[nj][h2 * 2]);
                        mma16(c, ah[mi], &bl[nj][h2 * 2]);
                        mma16(c, al[mi], &bh[nj][h2 * 2]);
                    }
        }
        __syncthreads();
    }

    #pragma unroll
    for (int mi = 0; mi < 4; mi++) {
        int row0 = m0 + wm * 64 + mi * 16 + g;
        #pragma unroll
        for (int ni = 0; ni < 4; ni++) {
            int col = j0 + wn * 32 + ni * 8 + 2 * t;
            *(float2*)&Y[(size_t)row0 * DD + col] =
                make_float2(acc[mi][ni][0], acc[mi][ni][1]);
            *(float2*)&Y[(size_t)(row0 + 8) * DD + col] =
                make_float2(acc[mi][ni][2], acc[mi][ni][3]);
        }
    }
}

// ============================================================================
// launch
// Inputs: 0=inputs 1=rotation 2=entangle 3=Wq 4=Wk 5=Wv 6=Wo; out (B,L,D) fp32
// ============================================================================
extern "C" void kernel_launch(void* const* d_in, const int* in_sizes, int n_in,
                              void* d_out, int out_size)
{
    const float* X   = (const float*)d_in[0];
    const float* R   = (const float*)d_in[1];
    const float* ent = (const float*)d_in[2];
    const float* Wq  = (const float*)d_in[3];
    const float* Wk  = (const float*)d_in[4];
    const float* Wv  = (const float*)d_in[5];
    const float* Wo  = (const float*)d_in[6];
    float* Y = (float*)d_out;

    cudaFuncSetAttribute(flash2,
                         cudaFuncAttributeMaxDynamicSharedMemorySize, FL2_SMEM);

    convert_inputs<<<1184, 256>>>(X, Wo);
    combine_b3<<<dim3(8, 8, 3), 256>>>(Wq, Wk, Wv, R);
    qkv_b3<<<dim3(8, MTOK / 128, 3), 256>>>(ent);
    flash2<<<dim3(LL / 128, BB * NH), 256, FL2_SMEM>>>();
    out_b3<<<dim3(8, MTOK / 128), 256>>>(Y);
}

// round 10
// speedup vs baseline: 1.1318x; 1.0653x over previous
#include <cuda_runtime.h>
#include <cuda_bf16.h>
#include <stdint.h>
#include <math.h>

#define DD   1024
#define NH   16
#define HDIM 64
#define BB   2
#define LL   2048
#define MTOK (BB*LL)   // 4096

#define AKS 40     // [row][k] bf16 smem stride (32 + 8)
#define BKS 136    // [k][n]  bf16 smem stride (128 + 8)

// ---------------- scratch (device globals; no allocations allowed) ----------
__device__ __nv_bfloat16 g_Wch[3][DD*DD], g_Wcl[3][DD*DD];  // combined W^T@R, split
__device__ __nv_bfloat16 g_Xh[MTOK*DD],  g_Xl[MTOK*DD];     // X split
__device__ __nv_bfloat16 g_Woh[DD*DD],   g_Wol[DD*DD];      // Wo split
__device__ __nv_bfloat16 g_Oh[MTOK*DD],  g_Ol[MTOK*DD];     // attn out (B,L,D) split
// Q,K: [b][h][l][cperm(d)]  tf32-rounded, Q pre-scaled by ent/8
// V:   [b][h] groups of 64 keys: [l>>6][rv(l&63)][2d + b(l&63)]  tf32-rounded
__device__ float g_Q[BB*NH*LL*HDIM];
__device__ float g_K[BB*NH*LL*HDIM];
__device__ float g_V[BB*NH*LL*HDIM];

// ---------------- helpers ----------------------------------------------------
__device__ __forceinline__ uint32_t f2tf32(float x) {
    uint32_t u;
    asm("cvt.rna.tf32.f32 %0, %1;" : "=r"(u) : "f"(x));
    return u;
}
__device__ __forceinline__ float tfr(float x) { return __uint_as_float(f2tf32(x)); }

__device__ __forceinline__ void mma8(float d[4], const uint32_t a[4], const uint32_t b[2]) {
    asm volatile(
        "mma.sync.aligned.m16n8k8.row.col.f32.tf32.tf32.f32 "
        "{%0,%1,%2,%3}, {%4,%5,%6,%7}, {%8,%9}, {%0,%1,%2,%3};"
        : "+f"(d[0]), "+f"(d[1]), "+f"(d[2]), "+f"(d[3])
        : "r"(a[0]), "r"(a[1]), "r"(a[2]), "r"(a[3]), "r"(b[0]), "r"(b[1]));
}

__device__ __forceinline__ void mma16(float* d, const uint32_t* a, const uint32_t* b) {
    asm volatile(
        "mma.sync.aligned.m16n8k16.row.col.f32.bf16.bf16.f32 "
        "{%0,%1,%2,%3}, {%4,%5,%6,%7}, {%8,%9}, {%0,%1,%2,%3};"
        : "+f"(d[0]), "+f"(d[1]), "+f"(d[2]), "+f"(d[3])
        : "r"(a[0]), "r"(a[1]), "r"(a[2]), "r"(a[3]), "r"(b[0]), "r"(b[1]));
}

__device__ __forceinline__ void ldsm4(uint32_t* r, const void* p) {
    uint32_t a = (uint32_t)__cvta_generic_to_shared(p);
    asm volatile("ldmatrix.sync.aligned.m8n8.x4.shared.b16 {%0,%1,%2,%3}, [%4];"
        : "=r"(r[0]), "=r"(r[1]), "=r"(r[2]), "=r"(r[3]) : "r"(a));
}
__device__ __forceinline__ void ldsm4t(uint32_t* r, const void* p) {
    uint32_t a = (uint32_t)__cvta_generic_to_shared(p);
    asm volatile("ldmatrix.sync.aligned.m8n8.x4.trans.shared.b16 {%0,%1,%2,%3}, [%4];"
        : "=r"(r[0]), "=r"(r[1]), "=r"(r[2]), "=r"(r[3]) : "r"(a));
}

__device__ __forceinline__ void cpa16(void* smem, const void* gmem) {
    uint32_t s = (uint32_t)__cvta_generic_to_shared(smem);
    asm volatile("cp.async.cg.shared.global [%0], [%1], 16;" :: "r"(s), "l"(gmem) : "memory");
}
#define CP_COMMIT() asm volatile("cp.async.commit_group;" ::: "memory")
#define CP_WAIT0()  asm volatile("cp.async.wait_group 0;" ::: "memory")

// split 4 fp32 -> bf16 hi/lo, store 8B to each of hp/lp
__device__ __forceinline__ void sst4(__nv_bfloat16* hp, __nv_bfloat16* lp, float4 v) {
    __nv_bfloat16 hx = __float2bfloat16_rn(v.x), hy = __float2bfloat16_rn(v.y);
    __nv_bfloat16 hz = __float2bfloat16_rn(v.z), hw = __float2bfloat16_rn(v.w);
    __nv_bfloat162* H = (__nv_bfloat162*)hp;
    H[0] = __halves2bfloat162(hx, hy);
    H[1] = __halves2bfloat162(hz, hw);
    __nv_bfloat162* L = (__nv_bfloat162*)lp;
    L[0] = __halves2bfloat162(__float2bfloat16_rn(v.x - __bfloat162float(hx)),
                              __float2bfloat16_rn(v.y - __bfloat162float(hy)));
    L[1] = __halves2bfloat162(__float2bfloat16_rn(v.z - __bfloat162float(hz)),
                              __float2bfloat16_rn(v.w - __bfloat162float(hw)));
}

__device__ __forceinline__ void split2(__nv_bfloat16* hp, __nv_bfloat16* lp, float a, float b) {
    __nv_bfloat16 ha = __float2bfloat16_rn(a), hb = __float2bfloat16_rn(b);
    *(__nv_bfloat162*)hp = __halves2bfloat162(ha, hb);
    *(__nv_bfloat162*)lp = __halves2bfloat162(
        __float2bfloat16_rn(a - __bfloat162float(ha)),
        __float2bfloat16_rn(b - __bfloat162float(hb)));
}

// ============================================================================
// Kernel 0: split X and Wo into bf16 hi/lo.
// ============================================================================
__global__ __launch_bounds__(256) void convert_inputs(
    const float* __restrict__ X, const float* __restrict__ Wo)
{
    int i0 = blockIdx.x * blockDim.x + threadIdx.x;
    int st = gridDim.x * blockDim.x;
    for (int i = i0; i < MTOK * DD / 4; i += st) {
        float4 v = ((const float4*)X)[i];
        sst4(&g_Xh[i * 4], &g_Xl[i * 4], v);
    }
    for (int i = i0; i < DD * DD / 4; i += st) {
        float4 v = ((const float4*)Wo)[i];
        sst4(&g_Woh[i * 4], &g_Wol[i * 4], v);
    }
}

// ============================================================================
// Kernel 1: Wc[z] = W[z]^T @ R  (TN), bf16x3 + ldmatrix.trans both operands.
// ============================================================================
__global__ __launch_bounds__(256) void combine_b3(
    const float* __restrict__ Wq, const float* __restrict__ Wk,
    const float* __restrict__ Wv, const float* __restrict__ R)
{
    const int z = blockIdx.z;
    const float* W = (z == 0) ? Wq : ((z == 1) ? Wk : Wv);

    __shared__ __align__(16) __nv_bfloat16 Ath[32][BKS], Atl[32][BKS];
    __shared__ __align__(16) __nv_bfloat16 Bth[32][BKS], Btl[32][BKS];

    const int tid = threadIdx.x, lane = tid & 31, g = lane >> 2, t = lane & 3;
    const int warp = tid >> 5, wm = warp >> 2, wn = warp & 3;
    const int i0 = blockIdx.y * 128, j0 = blockIdx.x * 128;
    const int kr = tid >> 5, cc = (tid & 31) * 4;

    float acc[4][4][4] = {};
    float4 pa[4], pb[4];
    #pragma unroll
    for (int r = 0; r < 4; r++) {
        pa[r] = *(const float4*)&W[(size_t)(kr + r * 8) * DD + i0 + cc];
        pb[r] = *(const float4*)&R[(size_t)(kr + r * 8) * DD + j0 + cc];
    }

    for (int kt = 0; kt < DD; kt += 32) {
        #pragma unroll
        for (int r = 0; r < 4; r++) {
            sst4(&Ath[kr + r * 8][cc], &Atl[kr + r * 8][cc], pa[r]);
            sst4(&Bth[kr + r * 8][cc], &Btl[kr + r * 8][cc], pb[r]);
        }
        __syncthreads();
        if (kt + 32 < DD) {
            #pragma unroll
            for (int r = 0; r < 4; r++) {
                pa[r] = *(const float4*)&W[(size_t)(kt + 32 + kr + r * 8) * DD + i0 + cc];
                pb[r] = *(const float4*)&R[(size_t)(kt + 32 + kr + r * 8) * DD + j0 + cc];
            }
        }
        #pragma unroll
        for (int ks = 0; ks < 2; ks++) {
            const int kk0 = ks * 16;
            uint32_t ah[4][4], al[4][4], bh[2][4], bl[2][4];
            const int arow = kk0 + (lane >> 4) * 8 + (lane & 7);
            const int acol = wm * 64 + ((lane >> 3) & 1) * 8;
            #pragma unroll
            for (int mi = 0; mi < 4; mi++) {
                ldsm4t(ah[mi], &Ath[arow][acol + mi * 16]);
                ldsm4t(al[mi], &Atl[arow][acol + mi * 16]);
            }
            const int brow = kk0 + (lane & 7) + ((lane >> 3) & 1) * 8;
            const int bcol = wn * 32 + (lane >> 4) * 8;
            #pragma unroll
            for (int nj = 0; nj < 2; nj++) {
                ldsm4t(bh[nj], &Bth[brow][bcol + nj * 16]);
                ldsm4t(bl[nj], &Btl[brow][bcol + nj * 16]);
            }
            #pragma unroll
            for (int mi = 0; mi < 4; mi++)
                #pragma unroll
                for (int nj = 0; nj < 2; nj++)
                    #pragma unroll
                    for (int h2 = 0; h2 < 2; h2++) {
                        float* c = acc[mi][nj * 2 + h2];
                        mma16(c, ah[mi], &bh[nj][h2 * 2]);
                        mma16(c, ah[mi], &bl[nj][h2 * 2]);
                        mma16(c, al[mi], &bh[nj][h2 * 2]);
                    }
        }
        __syncthreads();
    }

    __nv_bfloat16* Ch = g_Wch[z];
    __nv_bfloat16* Cl = g_Wcl[z];
    #pragma unroll
    for (int mi = 0; mi < 4; mi++) {
        int row0 = i0 + wm * 64 + mi * 16 + g;
        #pragma unroll
        for (int ni = 0; ni < 4; ni++) {
            int col = j0 + wn * 32 + ni * 8 + 2 * t;
            split2(&Ch[(size_t)row0 * DD + col], &Cl[(size_t)row0 * DD + col],
                   acc[mi][ni][0], acc[mi][ni][1]);
            split2(&Ch[(size_t)(row0 + 8) * DD + col], &Cl[(size_t)(row0 + 8) * DD + col],
                   acc[mi][ni][2], acc[mi][ni][3]);
        }
    }
}

// ============================================================================
// Kernel 2: P = X @ Wc[z] (NN), bf16x3, scatter into flash-ready layouts:
//  z=0/1 (Q,K): [b][h][l][cperm(d)] tf32, Q scaled by ent/8.
//  z=2   (V)  : per head, per 64-key group: [rv][2d+b] tf32.
// ============================================================================
__global__ __launch_bounds__(256) void qkv_b3(const float* __restrict__ ent)
{
    const int z = blockIdx.z;
    const __nv_bfloat16* Wh = g_Wch[z];
    const __nv_bfloat16* Wl = g_Wcl[z];
    float* Out = (z == 0) ? g_Q : ((z == 1) ? g_K : g_V);

    __shared__ __align__(16) __nv_bfloat16 Ah[128][AKS], Al[128][AKS];
    __shared__ __align__(16) __nv_bfloat16 Bth[32][BKS], Btl[32][BKS];

    const int tid = threadIdx.x, lane = tid & 31, g = lane >> 2, t = lane & 3;
    const int warp = tid >> 5, wm = warp >> 2, wn = warp & 3;
    const int m0 = blockIdx.y * 128, j0 = blockIdx.x * 128;
    const int b = m0 >> 11;
    const int ar = tid >> 3, akc = (tid & 7) * 4;
    const int kr = tid >> 5, cc = (tid & 31) * 4;

    float acc[4][4][4] = {};
    uint2 pah[4], pal[4], pbh[4], pbl[4];
    #pragma unroll
    for (int r = 0; r < 4; r++) {
        size_t ai = (size_t)(m0 + ar + r * 32) * DD + akc;
        pah[r] = *(const uint2*)&g_Xh[ai];
        pal[r] = *(const uint2*)&g_Xl[ai];
        size_t bi = (size_t)(kr + r * 8) * DD + j0 + cc;
        pbh[r] = *(const uint2*)&Wh[bi];
        pbl[r] = *(const uint2*)&Wl[bi];
    }

    for (int kt = 0; kt < DD; kt += 32) {
        #pragma unroll
        for (int r = 0; r < 4; r++) {
            *(uint2*)&Ah[ar + r * 32][akc] = pah[r];
            *(uint2*)&Al[ar + r * 32][akc] = pal[r];
            *(uint2*)&Bth[kr + r * 8][cc]  = pbh[r];
            *(uint2*)&Btl[kr + r * 8][cc]  = pbl[r];
        }
        __syncthreads();
        if (kt + 32 < DD) {
            #pragma unroll
            for (int r = 0; r < 4; r++) {
                size_t ai = (size_t)(m0 + ar + r * 32) * DD + kt + 32 + akc;
                pah[r] = *(const uint2*)&g_Xh[ai];
                pal[r] = *(const uint2*)&g_Xl[ai];
                size_t bi = (size_t)(kt + 32 + kr + r * 8) * DD + j0 + cc;
                pbh[r] = *(const uint2*)&Wh[bi];
                pbl[r] = *(const uint2*)&Wl[bi];
            }
        }
        #pragma unroll
        for (int ks = 0; ks < 2; ks++) {
            const int kk0 = ks * 16;
            uint32_t ah[4][4], al[4][4], bh[2][4], bl[2][4];
            const int arow = wm * 64 + (lane & 15);
            const int ak   = kk0 + (lane >> 4) * 8;
            #pragma unroll
            for (int mi = 0; mi < 4; mi++) {
                ldsm4(ah[mi], &Ah[arow + mi * 16][ak]);
                ldsm4(al[mi], &Al[arow + mi * 16][ak]);
            }
            const int brow = kk0 + (lane & 7) + ((lane >> 3) & 1) * 8;
            const int bcol = wn * 32 + (lane >> 4) * 8;
            #pragma unroll
            for (int nj = 0; nj < 2; nj++) {
                ldsm4t(bh[nj], &Bth[brow][bcol + nj * 16]);
                ldsm4t(bl[nj], &Btl[brow][bcol + nj * 16]);
            }
            #pragma unroll
            for (int mi = 0; mi < 4; mi++)
                #pragma unroll
                for (int nj = 0; nj < 2; nj++)
                    #pragma unroll
                    for (int h2 = 0; h2 < 2; h2++) {
                        float* c = acc[mi][nj * 2 + h2];
                        mma16(c, ah[mi], &bh[nj][h2 * 2]);
                        mma16(c, ah[mi], &bl[nj][h2 * 2]);
                        mma16(c, al[mi], &bh[nj][h2 * 2]);
                    }
        }
        __syncthreads();
    }

    if (z < 2) {
        #pragma unroll
        for (int ni = 0; ni < 4; ni++) {
            int n = j0 + wn * 32 + ni * 8 + 2 * t;
            int h = n >> 6, d = n & 63;
            int c1 = (d & 0x38) + ((d & 3) << 1) + ((d >> 2) & 1);
            float s = (z == 0) ? (ent[h] * 0.125f) : 1.0f;
            #pragma unroll
            for (int mi = 0; mi < 4; mi++) {
                int m = m0 + wm * 64 + mi * 16 + g;
                int l = m & (LL - 1);
                size_t base = (((size_t)(b * NH + h)) * LL + l) * HDIM;
                Out[base + c1]              = tfr(acc[mi][ni][0] * s);
                Out[base + c1 + 2]          = tfr(acc[mi][ni][1] * s);
                Out[base + 8 * HDIM + c1]     = tfr(acc[mi][ni][2] * s);
                Out[base + 8 * HDIM + c1 + 2] = tfr(acc[mi][ni][3] * s);
            }
        }
    } else {
        #pragma unroll
        for (int ni = 0; ni < 4; ni++) {
            int n = j0 + wn * 32 + ni * 8 + 2 * t;
            int h = n >> 6, d = n & 63;
            #pragma unroll
            for (int mi = 0; mi < 4; mi++) {
                int m = m0 + wm * 64 + mi * 16 + g;
                int l = m & (LL - 1);
                int l6 = l & 63;
                int rv = ((l6 >> 3) << 2) + (l6 & 3);
                int bb = (l6 >> 2) & 1;
                size_t base = ((size_t)(b * NH + h)) * LL * HDIM
                            + (size_t)(l >> 6) * 4096 + rv * 128 + 2 * d + bb;
                Out[base]           = tfr(acc[mi][ni][0]);
                Out[base + 2]       = tfr(acc[mi][ni][1]);
                Out[base + 512]     = tfr(acc[mi][ni][2]);   // row l+8 -> rv+4
                Out[base + 512 + 2] = tfr(acc[mi][ni][3]);
            }
        }
    }
}

// ============================================================================
// Kernel 3: flash attention v3 — tf32 mma, each warp owns 32 q-rows (two m16
// tiles) so every K/V fragment load feeds 2 mmas (halves L1 traffic).
// 8 warps x 32 = 256 q-rows per CTA. cp.async double-buffered K/V.
// smem floats: K 2*64*72 + V 2*32*144 + P 8*32*72 = 36864 (144 KB, 1 CTA/SM)
// ============================================================================
#define FL3_SMEM (36864 * 4)

__global__ __launch_bounds__(256, 1) void flash3()
{
    extern __shared__ float sm[];
    float* Ksb0 = sm;
    float* Ksb1 = sm + 4608;
    float* Vsb0 = sm + 9216;
    float* Vsb1 = sm + 13824;
    const int tid = threadIdx.x, lane = tid & 31, g = lane >> 2, t = lane & 3;
    const int warp = tid >> 5;
    float* Pw = sm + 18432 + warp * (32 * 72);

    const int bh = blockIdx.y;
    const size_t head = (size_t)bh * LL * HDIM;
    const float* Qb = g_Q + head;
    const float* Kb = g_K + head;
    const float* Vb = g_V + head;
    const int q0 = blockIdx.x * 256 + warp * 32;

    // Q fragments for both m16 tiles (tf32-rounded, column-permuted in global)
    uint32_t qa[2][8][4];
    #pragma unroll
    for (int mt = 0; mt < 2; mt++)
        #pragma unroll
        for (int ks = 0; ks < 8; ks++) {
            float2 p0 = *(const float2*)&Qb[(size_t)(q0 + mt * 16 + g) * HDIM + ks * 8 + 2 * t];
            float2 p1 = *(const float2*)&Qb[(size_t)(q0 + mt * 16 + 8 + g) * HDIM + ks * 8 + 2 * t];
            qa[mt][ks][0] = __float_as_uint(p0.x); qa[mt][ks][2] = __float_as_uint(p0.y);
            qa[mt][ks][1] = __float_as_uint(p1.x); qa[mt][ks][3] = __float_as_uint(p1.y);
        }

    const int krow = tid >> 4, kcol = (tid & 15) * 4;
    const int vrow = tid >> 5, vcol = (tid & 31) * 4;

    float o[2][8][4] = {};
    float mv[2][2] = {{-1e30f, -1e30f}, {-1e30f, -1e30f}};
    float lv[2][2] = {};

    #pragma unroll
    for (int r = 0; r < 4; r++) {
        cpa16(&Ksb0[(krow + 16 * r) * 72 + kcol], &Kb[(size_t)(krow + 16 * r) * 64 + kcol]);
        cpa16(&Vsb0[(vrow + 8 * r) * 144 + vcol], &Vb[(size_t)(vrow + 8 * r) * 128 + vcol]);
    }
    CP_COMMIT();

    for (int it = 0; it < LL / 64; ++it) {
        CP_WAIT0();
        __syncthreads();
        if (it + 1 < LL / 64) {
            const float* Ksrc = Kb + (size_t)(it + 1) * 4096;
            const float* Vsrc = Vb + (size_t)(it + 1) * 4096;
            float* Kd = ((it + 1) & 1) ? Ksb1 : Ksb0;
            float* Vd = ((it + 1) & 1) ? Vsb1 : Vsb0;
            #pragma unroll
            for (int r = 0; r < 4; r++) {
                cpa16(&Kd[(krow + 16 * r) * 72 + kcol], &Ksrc[(size_t)(krow + 16 * r) * 64 + kcol]);
                cpa16(&Vd[(vrow + 8 * r) * 144 + vcol], &Vsrc[(size_t)(vrow + 8 * r) * 128 + vcol]);
            }
            CP_COMMIT();
        }
        const float* Ksm = (it & 1) ? Ksb1 : Ksb0;
        const float* Vsm = (it & 1) ? Vsb1 : Vsb0;

        // S = Q @ K^T : 32 x 64 per warp; each K fragment feeds both m-tiles
        float s[2][8][4] = {};
        #pragma unroll
        for (int ks = 0; ks < 8; ks++) {
            #pragma unroll
            for (int nt = 0; nt < 8; nt++) {
                float2 bp = *(const float2*)&Ksm[(nt * 8 + g) * 72 + ks * 8 + 2 * t];
                uint32_t bf[2] = { __float_as_uint(bp.x), __float_as_uint(bp.y) };
                mma8(s[0][nt], qa[0][ks], bf);
                mma8(s[1][nt], qa[1][ks], bf);
            }
        }

        // online softmax per m-tile (rows g and g+8, spread over 4 lanes each)
        #pragma unroll
        for (int mt = 0; mt < 2; mt++) {
            float rmax0 = -1e30f, rmax1 = -1e30f;
            #pragma unroll
            for (int nt = 0; nt < 8; nt++) {
                rmax0 = fmaxf(rmax0, fmaxf(s[mt][nt][0], s[mt][nt][1]));
                rmax1 = fmaxf(rmax1, fmaxf(s[mt][nt][2], s[mt][nt][3]));
            }
            rmax0 = fmaxf(rmax0, __shfl_xor_sync(0xffffffffu, rmax0, 1));
            rmax0 = fmaxf(rmax0, __shfl_xor_sync(0xffffffffu, rmax0, 2));
            rmax1 = fmaxf(rmax1, __shfl_xor_sync(0xffffffffu, rmax1, 1));
            rmax1 = fmaxf(rmax1, __shfl_xor_sync(0xffffffffu, rmax1, 2));

            float nm0 = fmaxf(mv[mt][0], rmax0), nm1 = fmaxf(mv[mt][1], rmax1);
            float c0 = __expf(mv[mt][0] - nm0), c1 = __expf(mv[mt][1] - nm1);
            mv[mt][0] = nm0; mv[mt][1] = nm1;

            float sum0 = 0.0f, sum1 = 0.0f;
            #pragma unroll
            for (int nt = 0; nt < 8; nt++) {
                s[mt][nt][0] = __expf(s[mt][nt][0] - nm0); sum0 += s[mt][nt][0];
                s[mt][nt][1] = __expf(s[mt][nt][1] - nm0); sum0 += s[mt][nt][1];
                s[mt][nt][2] = __expf(s[mt][nt][2] - nm1); sum1 += s[mt][nt][2];
                s[mt][nt][3] = __expf(s[mt][nt][3] - nm1); sum1 += s[mt][nt][3];
            }
            sum0 += __shfl_xor_sync(0xffffffffu, sum0, 1);
            sum0 += __shfl_xor_sync(0xffffffffu, sum0, 2);
            sum1 += __shfl_xor_sync(0xffffffffu, sum1, 1);
            sum1 += __shfl_xor_sync(0xffffffffu, sum1, 2);
            lv[mt][0] = lv[mt][0] * c0 + sum0;
            lv[mt][1] = lv[mt][1] * c1 + sum1;

            #pragma unroll
            for (int nt = 0; nt < 8; nt++) {
                o[mt][nt][0] *= c0; o[mt][nt][1] *= c0;
                o[mt][nt][2] *= c1; o[mt][nt][3] *= c1;
            }

            // P -> warp-private smem, tf32-rounded, column-interleaved
            float* Pm = Pw + mt * 16 * 72;
            #pragma unroll
            for (int nt = 0; nt < 8; nt++) {
                int j1 = nt * 8 + 2 * t;
                int cidx = (j1 & 0x38) + ((j1 & 3) << 1) + ((j1 >> 2) & 1);
                Pm[g * 72 + cidx]           = tfr(s[mt][nt][0]);
                Pm[g * 72 + cidx + 2]       = tfr(s[mt][nt][1]);
                Pm[(g + 8) * 72 + cidx]     = tfr(s[mt][nt][2]);
                Pm[(g + 8) * 72 + cidx + 2] = tfr(s[mt][nt][3]);
            }
        }
        __syncwarp();

        // O += P @ V ; each V fragment feeds both m-tiles
        #pragma unroll
        for (int ks = 0; ks < 8; ks++) {
            uint32_t pa[2][4];
            #pragma unroll
            for (int mt = 0; mt < 2; mt++) {
                const float* Pm = Pw + mt * 16 * 72;
                float2 pA = *(const float2*)&Pm[g * 72 + ks * 8 + 2 * t];
                float2 pB = *(const float2*)&Pm[(g + 8) * 72 + ks * 8 + 2 * t];
                pa[mt][0] = __float_as_uint(pA.x); pa[mt][1] = __float_as_uint(pB.x);
                pa[mt][2] = __float_as_uint(pA.y); pa[mt][3] = __float_as_uint(pB.y);
            }
            #pragma unroll
            for (int nt = 0; nt < 8; nt++) {
                float2 bp = *(const float2*)&Vsm[(ks * 4 + t) * 144 + 2 * (nt * 8 + g)];
                uint32_t bf[2] = { __float_as_uint(bp.x), __float_as_uint(bp.y) };
                mma8(o[0][nt], pa[0], bf);
                mma8(o[1][nt], pa[1], bf);
            }
        }
        __syncwarp();
        __syncthreads();
    }

    const int b = bh >> 4, h = bh & 15;
    #pragma unroll
    for (int mt = 0; mt < 2; mt++) {
        float inv0 = 1.0f / lv[mt][0], inv1 = 1.0f / lv[mt][1];
        size_t ob0 = ((size_t)b * LL + q0 + mt * 16 + g) * DD + h * HDIM;
        size_t ob1 = ((size_t)b * LL + q0 + mt * 16 + 8 + g) * DD + h * HDIM;
        #pragma unroll
        for (int nt = 0; nt < 8; nt++) {
            int col = nt * 8 + 2 * t;
            split2(&g_Oh[ob0 + col], &g_Ol[ob0 + col],
                   o[mt][nt][0] * inv0, o[mt][nt][1] * inv0);
            split2(&g_Oh[ob1 + col], &g_Ol[ob1 + col],
                   o[mt][nt][2] * inv1, o[mt][nt][3] * inv1);
        }
    }
}

// ============================================================================
// Kernel 4: Y = O @ Wo^T (NT), bf16x3.
// ============================================================================
__global__ __launch_bounds__(256) void out_b3(float* __restrict__ Y)
{
    __shared__ __align__(16) __nv_bfloat16 Ah[128][AKS], Al[128][AKS];
    __shared__ __align__(16) __nv_bfloat16 Bh[128][AKS], Bl[128][AKS];

    const int tid = threadIdx.x, lane = tid & 31, g = lane >> 2, t = lane & 3;
    const int warp = tid >> 5, wm = warp >> 2, wn = warp & 3;
    const int m0 = blockIdx.y * 128, j0 = blockIdx.x * 128;
    const int ar = tid >> 3, akc = (tid & 7) * 4;

    float acc[4][4][4] = {};
    uint2 pah[4], pal[4], pbh[4], pbl[4];
    #pragma unroll
    for (int r = 0; r < 4; r++) {
        size_t ai = (size_t)(m0 + ar + r * 32) * DD + akc;
        pah[r] = *(const uint2*)&g_Oh[ai];
        pal[r] = *(const uint2*)&g_Ol[ai];
        size_t bi = (size_t)(j0 + ar + r * 32) * DD + akc;
        pbh[r] = *(const uint2*)&g_Woh[bi];
        pbl[r] = *(const uint2*)&g_Wol[bi];
    }

    for (int kt = 0; kt < DD; kt += 32) {
        #pragma unroll
        for (int r = 0; r < 4; r++) {
            *(uint2*)&Ah[ar + r * 32][akc] = pah[r];
            *(uint2*)&Al[ar + r * 32][akc] = pal[r];
            *(uint2*)&Bh[ar + r * 32][akc] = pbh[r];
            *(uint2*)&Bl[ar + r * 32][akc] = pbl[r];
        }
        __syncthreads();
        if (kt + 32 < DD) {
            #pragma unroll
            for (int r = 0; r < 4; r++) {
                size_t ai = (size_t)(m0 + ar + r * 32) * DD + kt + 32 + akc;
                pah[r] = *(const uint2*)&g_Oh[ai];
                pal[r] = *(const uint2*)&g_Ol[ai];
                size_t bi = (size_t)(j0 + ar + r * 32) * DD + kt + 32 + akc;
                pbh[r] = *(const uint2*)&g_Woh[bi];
                pbl[r] = *(const uint2*)&g_Wol[bi];
            }
        }
        #pragma unroll
        for (int ks = 0; ks < 2; ks++) {
            const int kk0 = ks * 16;
            uint32_t ah[4][4], al[4][4], bh[2][4], bl[2][4];
            const int arow = wm * 64 + (lane & 15);
            const int ak   = kk0 + (lane >> 4) * 8;
            #pragma unroll
            for (int mi = 0; mi < 4; mi++) {
                ldsm4(ah[mi], &Ah[arow + mi * 16][ak]);
                ldsm4(al[mi], &Al[arow + mi * 16][ak]);
            }
            const int brow = wn * 32 + (lane & 7) + ((lane >> 4) & 1) * 8;
            const int bk   = kk0 + ((lane >> 3) & 1) * 8;
            #pragma unroll
            for (int nj = 0; nj < 2; nj++) {
                ldsm4(bh[nj], &Bh[brow + nj * 16][bk]);
                ldsm4(bl[nj], &Bl[brow + nj * 16][bk]);
            }
            #pragma unroll
            for (int mi = 0; mi < 4; mi++)
                #pragma unroll
                for (int nj = 0; nj < 2; nj++)
                    #pragma unroll
                    for (int h2 = 0; h2 < 2; h2++) {
                        float* c = acc[mi][nj * 2 + h2];
                        mma16(c, ah[mi], &bh[nj][h2 * 2]);
                        mma16(c, ah[mi], &bl[nj][h2 * 2]);
                        mma16(c, al[mi], &bh[nj][h2 * 2]);
                    }
        }
        __syncthreads();
    }

    #pragma unroll
    for (int mi = 0; mi < 4; mi++) {
        int row0 = m0 + wm * 64 + mi * 16 + g;
        #pragma unroll
        for (int ni = 0; ni < 4; ni++) {
            int col = j0 + wn * 32 + ni * 8 + 2 * t;
            *(float2*)&Y[(size_t)row0 * DD + col] =
                make_float2(acc[mi][ni][0], acc[mi][ni][1]);
            *(float2*)&Y[(size_t)(row0 + 8) * DD + col] =
                make_float2(acc[mi][ni][2], acc[mi][ni][3]);
        }
    }
}

// ============================================================================
// launch
// Inputs: 0=inputs 1=rotation 2=entangle 3=Wq 4=Wk 5=Wv 6=Wo; out (B,L,D) fp32
// ============================================================================
extern "C" void kernel_launch(void* const* d_in, const int* in_sizes, int n_in,
                              void* d_out, int out_size)
{
    const float* X   = (const float*)d_in[0];
    const float* R   = (const float*)d_in[1];
    const float* ent = (const float*)d_in[2];
    const float* Wq  = (const float*)d_in[3];
    const float* Wk  = (const float*)d_in[4];
    const float* Wv  = (const float*)d_in[5];
    const float* Wo  = (const float*)d_in[6];
    float* Y = (float*)d_out;

    cudaFuncSetAttribute(flash3,
                         cudaFuncAttributeMaxDynamicSharedMemorySize, FL3_SMEM);

    convert_inputs<<<1184, 256>>>(X, Wo);
    combine_b3<<<dim3(8, 8, 3), 256>>>(Wq, Wk, Wv, R);
    qkv_b3<<<dim3(8, MTOK / 128, 3), 256>>>(ent);
    flash3<<<dim3(LL / 256, BB * NH), 256, FL3_SMEM>>>();
    out_b3<<<dim3(8, MTOK / 128), 256>>>(Y);
}

// round 11
// speedup vs baseline: 1.2970x; 1.1459x over previous
#include <cuda_runtime.h>
#include <cuda_bf16.h>
#include <cuda_fp16.h>
#include <stdint.h>
#include <math.h>

#define DD   1024
#define NH   16
#define HDIM 64
#define BB   2
#define LL   2048
#define MTOK (BB*LL)   // 4096

#define AKS 40     // [row][k] bf16 smem stride (32 + 8)
#define BKS 136    // [k][n]  bf16 smem stride (128 + 8)

// ---------------- scratch (device globals; no allocations allowed) ----------
__device__ __nv_bfloat16 g_Wch[3][DD*DD], g_Wcl[3][DD*DD];  // combined W^T@R, split
__device__ __nv_bfloat16 g_Xh[MTOK*DD],  g_Xl[MTOK*DD];     // X split
__device__ __nv_bfloat16 g_Woh[DD*DD],   g_Wol[DD*DD];      // Wo split
__device__ __nv_bfloat16 g_Oh[MTOK*DD],  g_Ol[MTOK*DD];     // attn out (B,L,D) split
// fp16 attention operands, mma-fragment-native layouts:
// Q,K: [b][h][l][perm(d)]   perm packs (2t,2t+1,2t+8,2t+9) contiguous per lane
// V:   [b][h][l>>6][d][perm(l&63)]   (transposed per 64-key tile)
__device__ __half g_Qf[BB*NH*LL*HDIM];
__device__ __half g_Kf[BB*NH*LL*HDIM];
__device__ __half g_Vt[BB*NH*LL*HDIM];

// ---------------- helpers ----------------------------------------------------
__device__ __forceinline__ void mma16(float* d, const uint32_t* a, const uint32_t* b) {
    asm volatile(
        "mma.sync.aligned.m16n8k16.row.col.f32.bf16.bf16.f32 "
        "{%0,%1,%2,%3}, {%4,%5,%6,%7}, {%8,%9}, {%0,%1,%2,%3};"
        : "+f"(d[0]), "+f"(d[1]), "+f"(d[2]), "+f"(d[3])
        : "r"(a[0]), "r"(a[1]), "r"(a[2]), "r"(a[3]), "r"(b[0]), "r"(b[1]));
}
__device__ __forceinline__ void mma16h(float* d, const uint32_t* a, const uint32_t* b) {
    asm volatile(
        "mma.sync.aligned.m16n8k16.row.col.f32.f16.f16.f32 "
        "{%0,%1,%2,%3}, {%4,%5,%6,%7}, {%8,%9}, {%0,%1,%2,%3};"
        : "+f"(d[0]), "+f"(d[1]), "+f"(d[2]), "+f"(d[3])
        : "r"(a[0]), "r"(a[1]), "r"(a[2]), "r"(a[3]), "r"(b[0]), "r"(b[1]));
}

__device__ __forceinline__ void ldsm4(uint32_t* r, const void* p) {
    uint32_t a = (uint32_t)__cvta_generic_to_shared(p);
    asm volatile("ldmatrix.sync.aligned.m8n8.x4.shared.b16 {%0,%1,%2,%3}, [%4];"
        : "=r"(r[0]), "=r"(r[1]), "=r"(r[2]), "=r"(r[3]) : "r"(a));
}
__device__ __forceinline__ void ldsm4t(uint32_t* r, const void* p) {
    uint32_t a = (uint32_t)__cvta_generic_to_shared(p);
    asm volatile("ldmatrix.sync.aligned.m8n8.x4.trans.shared.b16 {%0,%1,%2,%3}, [%4];"
        : "=r"(r[0]), "=r"(r[1]), "=r"(r[2]), "=r"(r[3]) : "r"(a));
}

__device__ __forceinline__ void cpa16(void* smem, const void* gmem) {
    uint32_t s = (uint32_t)__cvta_generic_to_shared(smem);
    asm volatile("cp.async.cg.shared.global [%0], [%1], 16;" :: "r"(s), "l"(gmem) : "memory");
}
#define CP_COMMIT() asm volatile("cp.async.commit_group;" ::: "memory")
#define CP_WAIT0()  asm volatile("cp.async.wait_group 0;" ::: "memory")

// split 4 fp32 -> bf16 hi/lo, store 8B to each of hp/lp
__device__ __forceinline__ void sst4(__nv_bfloat16* hp, __nv_bfloat16* lp, float4 v) {
    __nv_bfloat16 hx = __float2bfloat16_rn(v.x), hy = __float2bfloat16_rn(v.y);
    __nv_bfloat16 hz = __float2bfloat16_rn(v.z), hw = __float2bfloat16_rn(v.w);
    __nv_bfloat162* H = (__nv_bfloat162*)hp;
    H[0] = __halves2bfloat162(hx, hy);
    H[1] = __halves2bfloat162(hz, hw);
    __nv_bfloat162* L = (__nv_bfloat162*)lp;
    L[0] = __halves2bfloat162(__float2bfloat16_rn(v.x - __bfloat162float(hx)),
                              __float2bfloat16_rn(v.y - __bfloat162float(hy)));
    L[1] = __halves2bfloat162(__float2bfloat16_rn(v.z - __bfloat162float(hz)),
                              __float2bfloat16_rn(v.w - __bfloat162float(hw)));
}

__device__ __forceinline__ void split2(__nv_bfloat16* hp, __nv_bfloat16* lp, float a, float b) {
    __nv_bfloat16 ha = __float2bfloat16_rn(a), hb = __float2bfloat16_rn(b);
    *(__nv_bfloat162*)hp = __halves2bfloat162(ha, hb);
    *(__nv_bfloat162*)lp = __halves2bfloat162(
        __float2bfloat16_rn(a - __bfloat162float(ha)),
        __float2bfloat16_rn(b - __bfloat162float(hb)));
}

// ============================================================================
// Kernel 0: split X and Wo into bf16 hi/lo.
// ============================================================================
__global__ __launch_bounds__(256) void convert_inputs(
    const float* __restrict__ X, const float* __restrict__ Wo)
{
    int i0 = blockIdx.x * blockDim.x + threadIdx.x;
    int st = gridDim.x * blockDim.x;
    for (int i = i0; i < MTOK * DD / 4; i += st) {
        float4 v = ((const float4*)X)[i];
        sst4(&g_Xh[i * 4], &g_Xl[i * 4], v);
    }
    for (int i = i0; i < DD * DD / 4; i += st) {
        float4 v = ((const float4*)Wo)[i];
        sst4(&g_Woh[i * 4], &g_Wol[i * 4], v);
    }
}

// ============================================================================
// Kernel 1: Wc[z] = W[z]^T @ R  (TN), bf16x3 + ldmatrix.trans both operands.
// ============================================================================
__global__ __launch_bounds__(256) void combine_b3(
    const float* __restrict__ Wq, const float* __restrict__ Wk,
    const float* __restrict__ Wv, const float* __restrict__ R)
{
    const int z = blockIdx.z;
    const float* W = (z == 0) ? Wq : ((z == 1) ? Wk : Wv);

    __shared__ __align__(16) __nv_bfloat16 Ath[32][BKS], Atl[32][BKS];
    __shared__ __align__(16) __nv_bfloat16 Bth[32][BKS], Btl[32][BKS];

    const int tid = threadIdx.x, lane = tid & 31, g = lane >> 2, t = lane & 3;
    const int warp = tid >> 5, wm = warp >> 2, wn = warp & 3;
    const int i0 = blockIdx.y * 128, j0 = blockIdx.x * 128;
    const int kr = tid >> 5, cc = (tid & 31) * 4;

    float acc[4][4][4] = {};
    float4 pa[4], pb[4];
    #pragma unroll
    for (int r = 0; r < 4; r++) {
        pa[r] = *(const float4*)&W[(size_t)(kr + r * 8) * DD + i0 + cc];
        pb[r] = *(const float4*)&R[(size_t)(kr + r * 8) * DD + j0 + cc];
    }

    for (int kt = 0; kt < DD; kt += 32) {
        #pragma unroll
        for (int r = 0; r < 4; r++) {
            sst4(&Ath[kr + r * 8][cc], &Atl[kr + r * 8][cc], pa[r]);
            sst4(&Bth[kr + r * 8][cc], &Btl[kr + r * 8][cc], pb[r]);
        }
        __syncthreads();
        if (kt + 32 < DD) {
            #pragma unroll
            for (int r = 0; r < 4; r++) {
                pa[r] = *(const float4*)&W[(size_t)(kt + 32 + kr + r * 8) * DD + i0 + cc];
                pb[r] = *(const float4*)&R[(size_t)(kt + 32 + kr + r * 8) * DD + j0 + cc];
            }
        }
        #pragma unroll
        for (int ks = 0; ks < 2; ks++) {
            const int kk0 = ks * 16;
            uint32_t ah[4][4], al[4][4], bh[2][4], bl[2][4];
            const int arow = kk0 + (lane >> 4) * 8 + (lane & 7);
            const int acol = wm * 64 + ((lane >> 3) & 1) * 8;
            #pragma unroll
            for (int mi = 0; mi < 4; mi++) {
                ldsm4t(ah[mi], &Ath[arow][acol + mi * 16]);
                ldsm4t(al[mi], &Atl[arow][acol + mi * 16]);
            }
            const int brow = kk0 + (lane & 7) + ((lane >> 3) & 1) * 8;
            const int bcol = wn * 32 + (lane >> 4) * 8;
            #pragma unroll
            for (int nj = 0; nj < 2; nj++) {
                ldsm4t(bh[nj], &Bth[brow][bcol + nj * 16]);
                ldsm4t(bl[nj], &Btl[brow][bcol + nj * 16]);
            }
            #pragma unroll
            for (int mi = 0; mi < 4; mi++)
                #pragma unroll
                for (int nj = 0; nj < 2; nj++)
                    #pragma unroll
                    for (int h2 = 0; h2 < 2; h2++) {
                        float* c = acc[mi][nj * 2 + h2];
                        mma16(c, ah[mi], &bh[nj][h2 * 2]);
                        mma16(c, ah[mi], &bl[nj][h2 * 2]);
                        mma16(c, al[mi], &bh[nj][h2 * 2]);
                    }
        }
        __syncthreads();
    }

    __nv_bfloat16* Ch = g_Wch[z];
    __nv_bfloat16* Cl = g_Wcl[z];
    #pragma unroll
    for (int mi = 0; mi < 4; mi++) {
        int row0 = i0 + wm * 64 + mi * 16 + g;
        #pragma unroll
        for (int ni = 0; ni < 4; ni++) {
            int col = j0 + wn * 32 + ni * 8 + 2 * t;
            split2(&Ch[(size_t)row0 * DD + col], &Cl[(size_t)row0 * DD + col],
                   acc[mi][ni][0], acc[mi][ni][1]);
            split2(&Ch[(size_t)(row0 + 8) * DD + col], &Cl[(size_t)(row0 + 8) * DD + col],
                   acc[mi][ni][2], acc[mi][ni][3]);
        }
    }
}

// ============================================================================
// Kernel 2: P = X @ Wc[z] (NN), bf16x3, scatter into fp16 flash layouts:
//  z=0/1 (Q,K): [b][h][l][perm(d)], Q scaled by ent/8.
//  z=2   (V)  : [b][h][l>>6][d][perm(l&63)]  (transposed per key-tile).
// ============================================================================
__global__ __launch_bounds__(256) void qkv_b3(const float* __restrict__ ent)
{
    const int z = blockIdx.z;
    const __nv_bfloat16* Wh = g_Wch[z];
    const __nv_bfloat16* Wl = g_Wcl[z];

    __shared__ __align__(16) __nv_bfloat16 Ah[128][AKS], Al[128][AKS];
    __shared__ __align__(16) __nv_bfloat16 Bth[32][BKS], Btl[32][BKS];

    const int tid = threadIdx.x, lane = tid & 31, g = lane >> 2, t = lane & 3;
    const int warp = tid >> 5, wm = warp >> 2, wn = warp & 3;
    const int m0 = blockIdx.y * 128, j0 = blockIdx.x * 128;
    const int b = m0 >> 11;
    const int ar = tid >> 3, akc = (tid & 7) * 4;
    const int kr = tid >> 5, cc = (tid & 31) * 4;

    float acc[4][4][4] = {};
    uint2 pah[4], pal[4], pbh[4], pbl[4];
    #pragma unroll
    for (int r = 0; r < 4; r++) {
        size_t ai = (size_t)(m0 + ar + r * 32) * DD + akc;
        pah[r] = *(const uint2*)&g_Xh[ai];
        pal[r] = *(const uint2*)&g_Xl[ai];
        size_t bi = (size_t)(kr + r * 8) * DD + j0 + cc;
        pbh[r] = *(const uint2*)&Wh[bi];
        pbl[r] = *(const uint2*)&Wl[bi];
    }

    for (int kt = 0; kt < DD; kt += 32) {
        #pragma unroll
        for (int r = 0; r < 4; r++) {
            *(uint2*)&Ah[ar + r * 32][akc] = pah[r];
            *(uint2*)&Al[ar + r * 32][akc] = pal[r];
            *(uint2*)&Bth[kr + r * 8][cc]  = pbh[r];
            *(uint2*)&Btl[kr + r * 8][cc]  = pbl[r];
        }
        __syncthreads();
        if (kt + 32 < DD) {
            #pragma unroll
            for (int r = 0; r < 4; r++) {
                size_t ai = (size_t)(m0 + ar + r * 32) * DD + kt + 32 + akc;
                pah[r] = *(const uint2*)&g_Xh[ai];
                pal[r] = *(const uint2*)&g_Xl[ai];
                size_t bi = (size_t)(kt + 32 + kr + r * 8) * DD + j0 + cc;
                pbh[r] = *(const uint2*)&Wh[bi];
                pbl[r] = *(const uint2*)&Wl[bi];
            }
        }
        #pragma unroll
        for (int ks = 0; ks < 2; ks++) {
            const int kk0 = ks * 16;
            uint32_t ah[4][4], al[4][4], bh[2][4], bl[2][4];
            const int arow = wm * 64 + (lane & 15);
            const int ak   = kk0 + (lane >> 4) * 8;
            #pragma unroll
            for (int mi = 0; mi < 4; mi++) {
                ldsm4(ah[mi], &Ah[arow + mi * 16][ak]);
                ldsm4(al[mi], &Al[arow + mi * 16][ak]);
            }
            const int brow = kk0 + (lane & 7) + ((lane >> 3) & 1) * 8;
            const int bcol = wn * 32 + (lane >> 4) * 8;
            #pragma unroll
            for (int nj = 0; nj < 2; nj++) {
                ldsm4t(bh[nj], &Bth[brow][bcol + nj * 16]);
                ldsm4t(bl[nj], &Btl[brow][bcol + nj * 16]);
            }
            #pragma unroll
            for (int mi = 0; mi < 4; mi++)
                #pragma unroll
                for (int nj = 0; nj < 2; nj++)
                    #pragma unroll
                    for (int h2 = 0; h2 < 2; h2++) {
                        float* c = acc[mi][nj * 2 + h2];
                        mma16(c, ah[mi], &bh[nj][h2 * 2]);
                        mma16(c, ah[mi], &bl[nj][h2 * 2]);
                        mma16(c, al[mi], &bh[nj][h2 * 2]);
                    }
        }
        __syncthreads();
    }

    if (z < 2) {
        __half* OutH = (z == 0) ? g_Qf : g_Kf;
        #pragma unroll
        for (int ni = 0; ni < 4; ni++) {
            int n = j0 + wn * 32 + ni * 8 + 2 * t;    // even
            int h = n >> 6, d = n & 63;
            int pos = (d & 0x30) | ((d & 6) << 1) | ((d & 8) >> 2);
            float s = (z == 0) ? (ent[h] * 0.125f) : 1.0f;
            #pragma unroll
            for (int mi = 0; mi < 4; mi++) {
                int m = m0 + wm * 64 + mi * 16 + g;
                int l = m & (LL - 1);
                size_t base = ((size_t)(b * NH + h) * LL + l) * HDIM + pos;
                *(__half2*)&OutH[base] =
                    __floats2half2_rn(acc[mi][ni][0] * s, acc[mi][ni][1] * s);
                *(__half2*)&OutH[base + 8 * HDIM] =
                    __floats2half2_rn(acc[mi][ni][2] * s, acc[mi][ni][3] * s);
            }
        }
    } else {
        #pragma unroll
        for (int ni = 0; ni < 4; ni++) {
            int n = j0 + wn * 32 + ni * 8 + 2 * t;
            int h = n >> 6, d = n & 63;               // d even
            #pragma unroll
            for (int mi = 0; mi < 4; mi++) {
                int m = m0 + wm * 64 + mi * 16 + g;
                int l = m & (LL - 1);
                int l6 = l & 63;                      // < 56, so +8 stays in tile
                int pos = (l6 & 0x30) | ((l6 & 6) << 1) | ((l6 & 8) >> 2) | (l6 & 1);
                size_t base = (size_t)(b * NH + h) * LL * HDIM
                            + (size_t)(l >> 6) * 4096 + (size_t)d * 64;
                g_Vt[base + pos]          = __float2half_rn(acc[mi][ni][0]);
                g_Vt[base + 64 + pos]     = __float2half_rn(acc[mi][ni][1]);
                g_Vt[base + pos + 2]      = __float2half_rn(acc[mi][ni][2]);  // row l+8
                g_Vt[base + 64 + pos + 2] = __float2half_rn(acc[mi][ni][3]);
            }
        }
    }
}

// ============================================================================
// Kernel 3: flash attention v4 — fp16 m16n8k16 mma (same 11-bit mantissa as
// tf32, 2x rate, K=16/instr). Each warp owns 32 q-rows; fragment-native fp16
// layouts make every operand fetch a single LDS.64. cp.async double-buffered.
// smem: K 2*64*80 + Vt 2*64*80 + P 8*32*80 halfwords = 40960 hw = 80 KB.
// ============================================================================
#define FQS 80
#define FL4_SMEM (40960 * 2)

__global__ __launch_bounds__(256, 1) void flash4()
{
    extern __shared__ __half hsm[];
    const int tid = threadIdx.x, lane = tid & 31, g = lane >> 2, t = lane & 3;
    const int warp = tid >> 5;
    __half* Pb = hsm + 20480 + warp * (32 * FQS);

    const int bh = blockIdx.y;
    const size_t head = (size_t)bh * LL * HDIM;
    const int q0 = blockIdx.x * 256 + warp * 32;

    // Q fragments: qa[mt][kc] = {a0,a1,a2,a3} for m16n8k16
    uint32_t qa[2][4][4];
    #pragma unroll
    for (int mt = 0; mt < 2; mt++)
        #pragma unroll
        for (int kc = 0; kc < 4; kc++) {
            const __half* qp = &g_Qf[head + (size_t)(q0 + mt * 16 + g) * HDIM + kc * 16 + t * 4];
            uint2 u0 = *(const uint2*)qp;
            uint2 u1 = *(const uint2*)(qp + 8 * HDIM);
            qa[mt][kc][0] = u0.x; qa[mt][kc][1] = u1.x;
            qa[mt][kc][2] = u0.y; qa[mt][kc][3] = u1.y;
        }

    const int frow = tid >> 2;          // 0..63
    const int fch  = (tid & 3) * 2;     // 0,2,4,6

    float o[2][8][4] = {};
    float mv[2][2] = {{-1e30f, -1e30f}, {-1e30f, -1e30f}};
    float lv[2][2] = {};

    // prologue: tile 0 -> buffer 0
    {
        const __half* Ks = g_Kf + head;
        const __half* Vs = g_Vt + head;
        #pragma unroll
        for (int i = 0; i < 2; i++) {
            int ch = fch + i;
            cpa16(&hsm[frow * FQS + ch * 8],         &Ks[frow * 64 + ch * 8]);
            cpa16(&hsm[10240 + frow * FQS + ch * 8], &Vs[frow * 64 + ch * 8]);
        }
    }
    CP_COMMIT();

    for (int it = 0; it < LL / 64; ++it) {
        CP_WAIT0();
        __syncthreads();
        if (it + 1 < LL / 64) {
            const __half* Ks = g_Kf + head + (size_t)(it + 1) * 64 * 64;
            const __half* Vs = g_Vt + head + (size_t)(it + 1) * 4096;
            __half* Kd = hsm + ((it + 1) & 1) * 5120;
            __half* Vd = hsm + 10240 + ((it + 1) & 1) * 5120;
            #pragma unroll
            for (int i = 0; i < 2; i++) {
                int ch = fch + i;
                cpa16(&Kd[frow * FQS + ch * 8], &Ks[frow * 64 + ch * 8]);
                cpa16(&Vd[frow * FQS + ch * 8], &Vs[frow * 64 + ch * 8]);
            }
            CP_COMMIT();
        }
        const __half* Ksm = hsm + (it & 1) * 5120;
        const __half* Vsm = hsm + 10240 + (it & 1) * 5120;

        // S = Q @ K^T : 32 x 64 per warp; one LDS.64 per B fragment, 2 mmas each
        float s[2][8][4] = {};
        #pragma unroll
        for (int kc = 0; kc < 4; kc++) {
            #pragma unroll
            for (int nt = 0; nt < 8; nt++) {
                uint2 bv = *(const uint2*)&Ksm[(nt * 8 + g) * FQS + kc * 16 + t * 4];
                uint32_t bf[2] = { bv.x, bv.y };
                mma16h(s[0][nt], qa[0][kc], bf);
                mma16h(s[1][nt], qa[1][kc], bf);
            }
        }

        // online softmax per m-tile (rows g, g+8 spread over 4 lanes)
        #pragma unroll
        for (int mt = 0; mt < 2; mt++) {
            float rmax0 = -1e30f, rmax1 = -1e30f;
            #pragma unroll
            for (int nt = 0; nt < 8; nt++) {
                rmax0 = fmaxf(rmax0, fmaxf(s[mt][nt][0], s[mt][nt][1]));
                rmax1 = fmaxf(rmax1, fmaxf(s[mt][nt][2], s[mt][nt][3]));
            }
            rmax0 = fmaxf(rmax0, __shfl_xor_sync(0xffffffffu, rmax0, 1));
            rmax0 = fmaxf(rmax0, __shfl_xor_sync(0xffffffffu, rmax0, 2));
            rmax1 = fmaxf(rmax1, __shfl_xor_sync(0xffffffffu, rmax1, 1));
            rmax1 = fmaxf(rmax1, __shfl_xor_sync(0xffffffffu, rmax1, 2));

            float nm0 = fmaxf(mv[mt][0], rmax0), nm1 = fmaxf(mv[mt][1], rmax1);
            float c0 = __expf(mv[mt][0] - nm0), c1 = __expf(mv[mt][1] - nm1);
            mv[mt][0] = nm0; mv[mt][1] = nm1;

            float sum0 = 0.0f, sum1 = 0.0f;
            #pragma unroll
            for (int nt = 0; nt < 8; nt++) {
                s[mt][nt][0] = __expf(s[mt][nt][0] - nm0); sum0 += s[mt][nt][0];
                s[mt][nt][1] = __expf(s[mt][nt][1] - nm0); sum0 += s[mt][nt][1];
                s[mt][nt][2] = __expf(s[mt][nt][2] - nm1); sum1 += s[mt][nt][2];
                s[mt][nt][3] = __expf(s[mt][nt][3] - nm1); sum1 += s[mt][nt][3];
            }
            sum0 += __shfl_xor_sync(0xffffffffu, sum0, 1);
            sum0 += __shfl_xor_sync(0xffffffffu, sum0, 2);
            sum1 += __shfl_xor_sync(0xffffffffu, sum1, 1);
            sum1 += __shfl_xor_sync(0xffffffffu, sum1, 2);
            lv[mt][0] = lv[mt][0] * c0 + sum0;
            lv[mt][1] = lv[mt][1] * c1 + sum1;

            #pragma unroll
            for (int nt = 0; nt < 8; nt++) {
                o[mt][nt][0] *= c0; o[mt][nt][1] *= c0;
                o[mt][nt][2] *= c1; o[mt][nt][3] *= c1;
            }

            // P -> warp-private smem as fp16 in A-fragment-native layout
            __half* Pm = Pb + mt * 16 * FQS;
            #pragma unroll
            for (int nt = 0; nt < 8; nt++) {
                int pos = (nt >> 1) * 16 + t * 4 + (nt & 1) * 2;
                *(__half2*)&Pm[g * FQS + pos] =
                    __floats2half2_rn(s[mt][nt][0], s[mt][nt][1]);
                *(__half2*)&Pm[(g + 8) * FQS + pos] =
                    __floats2half2_rn(s[mt][nt][2], s[mt][nt][3]);
            }
        }
        __syncwarp();

        // O += P @ V ; one LDS.64 per V fragment, 2 mmas each
        #pragma unroll
        for (int kc = 0; kc < 4; kc++) {
            uint32_t pa[2][4];
            #pragma unroll
            for (int mt = 0; mt < 2; mt++) {
                const __half* Pm = Pb + mt * 16 * FQS;
                uint2 p0 = *(const uint2*)&Pm[g * FQS + kc * 16 + t * 4];
                uint2 p1 = *(const uint2*)&Pm[(g + 8) * FQS + kc * 16 + t * 4];
                pa[mt][0] = p0.x; pa[mt][1] = p1.x;
                pa[mt][2] = p0.y; pa[mt][3] = p1.y;
            }
            #pragma unroll
            for (int nt = 0; nt < 8; nt++) {
                uint2 bv = *(const uint2*)&Vsm[(nt * 8 + g) * FQS + kc * 16 + t * 4];
                uint32_t bf[2] = { bv.x, bv.y };
                mma16h(o[0][nt], pa[0], bf);
                mma16h(o[1][nt], pa[1], bf);
            }
        }
        __syncwarp();
    }

    const int b = bh >> 4, h = bh & 15;
    #pragma unroll
    for (int mt = 0; mt < 2; mt++) {
        float inv0 = 1.0f / lv[mt][0], inv1 = 1.0f / lv[mt][1];
        size_t ob0 = ((size_t)b * LL + q0 + mt * 16 + g) * DD + h * HDIM;
        size_t ob1 = ((size_t)b * LL + q0 + mt * 16 + 8 + g) * DD + h * HDIM;
        #pragma unroll
        for (int nt = 0; nt < 8; nt++) {
            int col = nt * 8 + 2 * t;
            split2(&g_Oh[ob0 + col], &g_Ol[ob0 + col],
                   o[mt][nt][0] * inv0, o[mt][nt][1] * inv0);
            split2(&g_Oh[ob1 + col], &g_Ol[ob1 + col],
                   o[mt][nt][2] * inv1, o[mt][nt][3] * inv1);
        }
    }
}

// ============================================================================
// Kernel 4: Y = O @ Wo^T (NT), bf16x3.
// ============================================================================
__global__ __launch_bounds__(256) void out_b3(float* __restrict__ Y)
{
    __shared__ __align__(16) __nv_bfloat16 Ah[128][AKS], Al[128][AKS];
    __shared__ __align__(16) __nv_bfloat16 Bh[128][AKS], Bl[128][AKS];

    const int tid = threadIdx.x, lane = tid & 31, g = lane >> 2, t = lane & 3;
    const int warp = tid >> 5, wm = warp >> 2, wn = warp & 3;
    const int m0 = blockIdx.y * 128, j0 = blockIdx.x * 128;
    const int ar = tid >> 3, akc = (tid & 7) * 4;

    float acc[4][4][4] = {};
    uint2 pah[4], pal[4], pbh[4], pbl[4];
    #pragma unroll
    for (int r = 0; r < 4; r++) {
        size_t ai = (size_t)(m0 + ar + r * 32) * DD + akc;
        pah[r] = *(const uint2*)&g_Oh[ai];
        pal[r] = *(const uint2*)&g_Ol[ai];
        size_t bi = (size_t)(j0 + ar + r * 32) * DD + akc;
        pbh[r] = *(const uint2*)&g_Woh[bi];
        pbl[r] = *(const uint2*)&g_Wol[bi];
    }

    for (int kt = 0; kt < DD; kt += 32) {
        #pragma unroll
        for (int r = 0; r < 4; r++) {
            *(uint2*)&Ah[ar + r * 32][akc] = pah[r];
            *(uint2*)&Al[ar + r * 32][akc] = pal[r];
            *(uint2*)&Bh[ar + r * 32][akc] = pbh[r];
            *(uint2*)&Bl[ar + r * 32][akc] = pbl[r];
        }
        __syncthreads();
        if (kt + 32 < DD) {
            #pragma unroll
            for (int r = 0; r < 4; r++) {
                size_t ai = (size_t)(m0 + ar + r * 32) * DD + kt + 32 + akc;
                pah[r] = *(const uint2*)&g_Oh[ai];
                pal[r] = *(const uint2*)&g_Ol[ai];
                size_t bi = (size_t)(j0 + ar + r * 32) * DD + kt + 32 + akc;
                pbh[r] = *(const uint2*)&g_Woh[bi];
                pbl[r] = *(const uint2*)&g_Wol[bi];
            }
        }
        #pragma unroll
        for (int ks = 0; ks < 2; ks++) {
            const int kk0 = ks * 16;
            uint32_t ah[4][4], al[4][4], bh[2][4], bl[2][4];
            const int arow = wm * 64 + (lane & 15);
            const int ak   = kk0 + (lane >> 4) * 8;
            #pragma unroll
            for (int mi = 0; mi < 4; mi++) {
                ldsm4(ah[mi], &Ah[arow + mi * 16][ak]);
                ldsm4(al[mi], &Al[arow + mi * 16][ak]);
            }
            const int brow = wn * 32 + (lane & 7) + ((lane >> 4) & 1) * 8;
            const int bk   = kk0 + ((lane >> 3) & 1) * 8;
            #pragma unroll
            for (int nj = 0; nj < 2; nj++) {
                ldsm4(bh[nj], &Bh[brow + nj * 16][bk]);
                ldsm4(bl[nj], &Bl[brow + nj * 16][bk]);
            }
            #pragma unroll
            for (int mi = 0; mi < 4; mi++)
                #pragma unroll
                for (int nj = 0; nj < 2; nj++)
                    #pragma unroll
                    for (int h2 = 0; h2 < 2; h2++) {
                        float* c = acc[mi][nj * 2 + h2];
                        mma16(c, ah[mi], &bh[nj][h2 * 2]);
                        mma16(c, ah[mi], &bl[nj][h2 * 2]);
                        mma16(c, al[mi], &bh[nj][h2 * 2]);
                    }
        }
        __syncthreads();
    }

    #pragma unroll
    for (int mi = 0; mi < 4; mi++) {
        int row0 = m0 + wm * 64 + mi * 16 + g;
        #pragma unroll
        for (int ni = 0; ni < 4; ni++) {
            int col = j0 + wn * 32 + ni * 8 + 2 * t;
            *(float2*)&Y[(size_t)row0 * DD + col] =
                make_float2(acc[mi][ni][0], acc[mi][ni][1]);
            *(float2*)&Y[(size_t)(row0 + 8) * DD + col] =
                make_float2(acc[mi][ni][2], acc[mi][ni][3]);
        }
    }
}

// ============================================================================
// launch
// Inputs: 0=inputs 1=rotation 2=entangle 3=Wq 4=Wk 5=Wv 6=Wo; out (B,L,D) fp32
// ============================================================================
extern "C" void kernel_launch(void* const* d_in, const int* in_sizes, int n_in,
                              void* d_out, int out_size)
{
    const float* X   = (const float*)d_in[0];
    const float* R   = (const float*)d_in[1];
    const float* ent = (const float*)d_in[2];
    const float* Wq  = (const float*)d_in[3];
    const float* Wk  = (const float*)d_in[4];
    const float* Wv  = (const float*)d_in[5];
    const float* Wo  = (const float*)d_in[6];
    float* Y = (float*)d_out;

    cudaFuncSetAttribute(flash4,
                         cudaFuncAttributeMaxDynamicSharedMemorySize, FL4_SMEM);

    convert_inputs<<<1184, 256>>>(X, Wo);
    combine_b3<<<dim3(8, 8, 3), 256>>>(Wq, Wk, Wv, R);
    qkv_b3<<<dim3(8, MTOK / 128, 3), 256>>>(ent);
    flash4<<<dim3(LL / 256, BB * NH), 256, FL4_SMEM>>>();
    out_b3<<<dim3(8, MTOK / 128), 256>>>(Y);
}

// round 12
// speedup vs baseline: 1.6198x; 1.2489x over previous
#include <cuda_runtime.h>
#include <cuda_bf16.h>
#include <cuda_fp16.h>
#include <stdint.h>
#include <math.h>

#define DD   1024
#define NH   16
#define HDIM 64
#define BB   2
#define LL   2048
#define MTOK (BB*LL)   // 4096

#define AKS 40     // [row][k] 16-bit smem stride (32 + 8)
#define BKS 136    // [k][n]  16-bit smem stride (128 + 8)

#define LOG2E  1.4426950408889634f
#define INV32  0.03125f

// ---------------- scratch (device globals; no allocations allowed) ----------
__device__ __half g_Wch[3][DD*DD], g_Wcl[3][DD*DD];  // 32*(W^T@R) fp16 split [k][n]
__device__ __half g_Xf[MTOK*DD];                     // X fp16 [m][k]
__device__ __half g_Woh[DD*DD],  g_Wol[DD*DD];       // 32*Wo fp16 split [n][k]
__device__ __half g_Of[MTOK*DD];                     // attn out fp16 (B,L,D)
// fp16 attention operands, mma-fragment-native layouts:
// Q,K: [b][h][l][perm(d)]; Q pre-scaled by ent/8*log2e. V: [b][h][l>>6][d][perm(l&63)]
__device__ __half g_Qf[BB*NH*LL*HDIM];
__device__ __half g_Kf[BB*NH*LL*HDIM];
__device__ __half g_Vt[BB*NH*LL*HDIM];

// ---------------- helpers ----------------------------------------------------
__device__ __forceinline__ float ex2(float x) {
    float y;
    asm("ex2.approx.f32 %0, %1;" : "=f"(y) : "f"(x));
    return y;
}

__device__ __forceinline__ void mma16(float* d, const uint32_t* a, const uint32_t* b) {
    asm volatile(
        "mma.sync.aligned.m16n8k16.row.col.f32.bf16.bf16.f32 "
        "{%0,%1,%2,%3}, {%4,%5,%6,%7}, {%8,%9}, {%0,%1,%2,%3};"
        : "+f"(d[0]), "+f"(d[1]), "+f"(d[2]), "+f"(d[3])
        : "r"(a[0]), "r"(a[1]), "r"(a[2]), "r"(a[3]), "r"(b[0]), "r"(b[1]));
}
__device__ __forceinline__ void mma16h(float* d, const uint32_t* a, const uint32_t* b) {
    asm volatile(
        "mma.sync.aligned.m16n8k16.row.col.f32.f16.f16.f32 "
        "{%0,%1,%2,%3}, {%4,%5,%6,%7}, {%8,%9}, {%0,%1,%2,%3};"
        : "+f"(d[0]), "+f"(d[1]), "+f"(d[2]), "+f"(d[3])
        : "r"(a[0]), "r"(a[1]), "r"(a[2]), "r"(a[3]), "r"(b[0]), "r"(b[1]));
}

__device__ __forceinline__ void ldsm4(uint32_t* r, const void* p) {
    uint32_t a = (uint32_t)__cvta_generic_to_shared(p);
    asm volatile("ldmatrix.sync.aligned.m8n8.x4.shared.b16 {%0,%1,%2,%3}, [%4];"
        : "=r"(r[0]), "=r"(r[1]), "=r"(r[2]), "=r"(r[3]) : "r"(a));
}
__device__ __forceinline__ void ldsm4t(uint32_t* r, const void* p) {
    uint32_t a = (uint32_t)__cvta_generic_to_shared(p);
    asm volatile("ldmatrix.sync.aligned.m8n8.x4.trans.shared.b16 {%0,%1,%2,%3}, [%4];"
        : "=r"(r[0]), "=r"(r[1]), "=r"(r[2]), "=r"(r[3]) : "r"(a));
}

__device__ __forceinline__ void cpa16(void* smem, const void* gmem) {
    uint32_t s = (uint32_t)__cvta_generic_to_shared(smem);
    asm volatile("cp.async.cg.shared.global [%0], [%1], 16;" :: "r"(s), "l"(gmem) : "memory");
}
#define CP_COMMIT() asm volatile("cp.async.commit_group;" ::: "memory")
#define CP_WAIT0()  asm volatile("cp.async.wait_group 0;" ::: "memory")

// split 4 fp32 -> bf16 hi/lo (combine's smem staging)
__device__ __forceinline__ void sst4(__nv_bfloat16* hp, __nv_bfloat16* lp, float4 v) {
    __nv_bfloat16 hx = __float2bfloat16_rn(v.x), hy = __float2bfloat16_rn(v.y);
    __nv_bfloat16 hz = __float2bfloat16_rn(v.z), hw = __float2bfloat16_rn(v.w);
    __nv_bfloat162* H = (__nv_bfloat162*)hp;
    H[0] = __halves2bfloat162(hx, hy);
    H[1] = __halves2bfloat162(hz, hw);
    __nv_bfloat162* L = (__nv_bfloat162*)lp;
    L[0] = __halves2bfloat162(__float2bfloat16_rn(v.x - __bfloat162float(hx)),
                              __float2bfloat16_rn(v.y - __bfloat162float(hy)));
    L[1] = __halves2bfloat162(__float2bfloat16_rn(v.z - __bfloat162float(hz)),
                              __float2bfloat16_rn(v.w - __bfloat162float(hw)));
}

// split scalar fp32 -> fp16 hi/lo
__device__ __forceinline__ void sp1h(__half* ph, __half* pl, float v) {
    __half h = __float2half_rn(v);
    *ph = h;
    *pl = __float2half_rn(v - __half2float(h));
}

// ============================================================================
// Kernel 0: X -> fp16; Wo*32 -> fp16 hi/lo.
// ============================================================================
__global__ __launch_bounds__(256) void convert_inputs(
    const float* __restrict__ X, const float* __restrict__ Wo)
{
    int i0 = blockIdx.x * blockDim.x + threadIdx.x;
    int st = gridDim.x * blockDim.x;
    for (int i = i0; i < MTOK * DD / 4; i += st) {
        float4 v = ((const float4*)X)[i];
        __half2* H = (__half2*)&g_Xf[i * 4];
        H[0] = __floats2half2_rn(v.x, v.y);
        H[1] = __floats2half2_rn(v.z, v.w);
    }
    for (int i = i0; i < DD * DD / 4; i += st) {
        float4 v = ((const float4*)Wo)[i];
        sp1h(&g_Woh[i * 4 + 0], &g_Wol[i * 4 + 0], v.x * 32.0f);
        sp1h(&g_Woh[i * 4 + 1], &g_Wol[i * 4 + 1], v.y * 32.0f);
        sp1h(&g_Woh[i * 4 + 2], &g_Wol[i * 4 + 2], v.z * 32.0f);
        sp1h(&g_Woh[i * 4 + 3], &g_Wol[i * 4 + 3], v.w * 32.0f);
    }
}

// ============================================================================
// Kernel 1: Wc[z] = W[z]^T @ R  (TN), bf16x3 (accurate). Epilogue stores
// 32*Wc as fp16 hi/lo in [k][n] layout.
// ============================================================================
__global__ __launch_bounds__(256) void combine_b3(
    const float* __restrict__ Wq, const float* __restrict__ Wk,
    const float* __restrict__ Wv, const float* __restrict__ R)
{
    const int z = blockIdx.z;
    const float* W = (z == 0) ? Wq : ((z == 1) ? Wk : Wv);

    __shared__ __align__(16) __nv_bfloat16 Ath[32][BKS], Atl[32][BKS];
    __shared__ __align__(16) __nv_bfloat16 Bth[32][BKS], Btl[32][BKS];

    const int tid = threadIdx.x, lane = tid & 31, g = lane >> 2, t = lane & 3;
    const int warp = tid >> 5, wm = warp >> 2, wn = warp & 3;
    const int i0 = blockIdx.y * 128, j0 = blockIdx.x * 128;
    const int kr = tid >> 5, cc = (tid & 31) * 4;

    float acc[4][4][4] = {};
    float4 pa[4], pb[4];
    #pragma unroll
    for (int r = 0; r < 4; r++) {
        pa[r] = *(const float4*)&W[(size_t)(kr + r * 8) * DD + i0 + cc];
        pb[r] = *(const float4*)&R[(size_t)(kr + r * 8) * DD + j0 + cc];
    }

    for (int kt = 0; kt < DD; kt += 32) {
        #pragma unroll
        for (int r = 0; r < 4; r++) {
            sst4(&Ath[kr + r * 8][cc], &Atl[kr + r * 8][cc], pa[r]);
            sst4(&Bth[kr + r * 8][cc], &Btl[kr + r * 8][cc], pb[r]);
        }
        __syncthreads();
        if (kt + 32 < DD) {
            #pragma unroll
            for (int r = 0; r < 4; r++) {
                pa[r] = *(const float4*)&W[(size_t)(kt + 32 + kr + r * 8) * DD + i0 + cc];
                pb[r] = *(const float4*)&R[(size_t)(kt + 32 + kr + r * 8) * DD + j0 + cc];
            }
        }
        #pragma unroll
        for (int ks = 0; ks < 2; ks++) {
            const int kk0 = ks * 16;
            uint32_t ah[4][4], al[4][4], bh[2][4], bl[2][4];
            const int arow = kk0 + (lane >> 4) * 8 + (lane & 7);
            const int acol = wm * 64 + ((lane >> 3) & 1) * 8;
            #pragma unroll
            for (int mi = 0; mi < 4; mi++) {
                ldsm4t(ah[mi], &Ath[arow][acol + mi * 16]);
                ldsm4t(al[mi], &Atl[arow][acol + mi * 16]);
            }
            const int brow = kk0 + (lane & 7) + ((lane >> 3) & 1) * 8;
            const int bcol = wn * 32 + (lane >> 4) * 8;
            #pragma unroll
            for (int nj = 0; nj < 2; nj++) {
                ldsm4t(bh[nj], &Bth[brow][bcol + nj * 16]);
                ldsm4t(bl[nj], &Btl[brow][bcol + nj * 16]);
            }
            #pragma unroll
            for (int mi = 0; mi < 4; mi++)
                #pragma unroll
                for (int nj = 0; nj < 2; nj++)
                    #pragma unroll
                    for (int h2 = 0; h2 < 2; h2++) {
                        float* c = acc[mi][nj * 2 + h2];
                        mma16(c, ah[mi], &bh[nj][h2 * 2]);
                        mma16(c, ah[mi], &bl[nj][h2 * 2]);
                        mma16(c, al[mi], &bh[nj][h2 * 2]);
                    }
        }
        __syncthreads();
    }

    __half* Ch = g_Wch[z];
    __half* Cl = g_Wcl[z];
    #pragma unroll
    for (int mi = 0; mi < 4; mi++) {
        int row0 = i0 + wm * 64 + mi * 16 + g;      // k index of Wc
        #pragma unroll
        for (int ni = 0; ni < 4; ni++) {
            int col = j0 + wn * 32 + ni * 8 + 2 * t; // n index of Wc
            sp1h(&Ch[(size_t)row0 * DD + col],     &Cl[(size_t)row0 * DD + col],
                 acc[mi][ni][0] * 32.0f);
            sp1h(&Ch[(size_t)row0 * DD + col + 1], &Cl[(size_t)row0 * DD + col + 1],
                 acc[mi][ni][1] * 32.0f);
            sp1h(&Ch[(size_t)(row0 + 8) * DD + col],     &Cl[(size_t)(row0 + 8) * DD + col],
                 acc[mi][ni][2] * 32.0f);
            sp1h(&Ch[(size_t)(row0 + 8) * DD + col + 1], &Cl[(size_t)(row0 + 8) * DD + col + 1],
                 acc[mi][ni][3] * 32.0f);
        }
    }
}

// ============================================================================
// Kernel 2: P = X @ (32*Wc[z]) (NN), fp16x2 (A single, B split), scatter into
// fp16 flash layouts with 1/32 folded into the epilogue scales.
// ============================================================================
__global__ __launch_bounds__(256) void qkv_f2(const float* __restrict__ ent)
{
    const int z = blockIdx.z;
    const __half* Wh = g_Wch[z];
    const __half* Wl = g_Wcl[z];

    __shared__ __align__(16) __half Ah[128][AKS];
    __shared__ __align__(16) __half Bth[32][BKS], Btl[32][BKS];

    const int tid = threadIdx.x, lane = tid & 31, g = lane >> 2, t = lane & 3;
    const int warp = tid >> 5, wm = warp >> 2, wn = warp & 3;
    const int m0 = blockIdx.y * 128, j0 = blockIdx.x * 128;
    const int b = m0 >> 11;
    const int ar = tid >> 3, akc = (tid & 7) * 4;
    const int kr = tid >> 5, cc = (tid & 31) * 4;

    float acc[4][4][4] = {};
    uint2 pah[4], pbh[4], pbl[4];
    #pragma unroll
    for (int r = 0; r < 4; r++) {
        pah[r] = *(const uint2*)&g_Xf[(size_t)(m0 + ar + r * 32) * DD + akc];
        size_t bi = (size_t)(kr + r * 8) * DD + j0 + cc;
        pbh[r] = *(const uint2*)&Wh[bi];
        pbl[r] = *(const uint2*)&Wl[bi];
    }

    for (int kt = 0; kt < DD; kt += 32) {
        #pragma unroll
        for (int r = 0; r < 4; r++) {
            *(uint2*)&Ah[ar + r * 32][akc] = pah[r];
            *(uint2*)&Bth[kr + r * 8][cc]  = pbh[r];
            *(uint2*)&Btl[kr + r * 8][cc]  = pbl[r];
        }
        __syncthreads();
        if (kt + 32 < DD) {
            #pragma unroll
            for (int r = 0; r < 4; r++) {
                pah[r] = *(const uint2*)&g_Xf[(size_t)(m0 + ar + r * 32) * DD + kt + 32 + akc];
                size_t bi = (size_t)(kt + 32 + kr + r * 8) * DD + j0 + cc;
                pbh[r] = *(const uint2*)&Wh[bi];
                pbl[r] = *(const uint2*)&Wl[bi];
            }
        }
        #pragma unroll
        for (int ks = 0; ks < 2; ks++) {
            const int kk0 = ks * 16;
            uint32_t ah[4][4], bh[2][4], bl[2][4];
            const int arow = wm * 64 + (lane & 15);
            const int ak   = kk0 + (lane >> 4) * 8;
            #pragma unroll
            for (int mi = 0; mi < 4; mi++)
                ldsm4(ah[mi], &Ah[arow + mi * 16][ak]);
            const int brow = kk0 + (lane & 7) + ((lane >> 3) & 1) * 8;
            const int bcol = wn * 32 + (lane >> 4) * 8;
            #pragma unroll
            for (int nj = 0; nj < 2; nj++) {
                ldsm4t(bh[nj], &Bth[brow][bcol + nj * 16]);
                ldsm4t(bl[nj], &Btl[brow][bcol + nj * 16]);
            }
            #pragma unroll
            for (int mi = 0; mi < 4; mi++)
                #pragma unroll
                for (int nj = 0; nj < 2; nj++)
                    #pragma unroll
                    for (int h2 = 0; h2 < 2; h2++) {
                        float* c = acc[mi][nj * 2 + h2];
                        mma16h(c, ah[mi], &bh[nj][h2 * 2]);
                        mma16h(c, ah[mi], &bl[nj][h2 * 2]);
                    }
        }
        __syncthreads();
    }

    if (z < 2) {
        __half* OutH = (z == 0) ? g_Qf : g_Kf;
        #pragma unroll
        for (int ni = 0; ni < 4; ni++) {
            int n = j0 + wn * 32 + ni * 8 + 2 * t;    // even
            int h = n >> 6, d = n & 63;
            int pos = (d & 0x30) | ((d & 6) << 1) | ((d & 8) >> 2);
            float s = (z == 0) ? (ent[h] * 0.125f * LOG2E * INV32) : INV32;
            #pragma unroll
            for (int mi = 0; mi < 4; mi++) {
                int m = m0 + wm * 64 + mi * 16 + g;
                int l = m & (LL - 1);
                size_t base = ((size_t)(b * NH + h) * LL + l) * HDIM + pos;
                *(__half2*)&OutH[base] =
                    __floats2half2_rn(acc[mi][ni][0] * s, acc[mi][ni][1] * s);
                *(__half2*)&OutH[base + 8 * HDIM] =
                    __floats2half2_rn(acc[mi][ni][2] * s, acc[mi][ni][3] * s);
            }
        }
    } else {
        #pragma unroll
        for (int ni = 0; ni < 4; ni++) {
            int n = j0 + wn * 32 + ni * 8 + 2 * t;
            int h = n >> 6, d = n & 63;               // d even
            #pragma unroll
            for (int mi = 0; mi < 4; mi++) {
                int m = m0 + wm * 64 + mi * 16 + g;
                int l = m & (LL - 1);
                int l6 = l & 63;
                int pos = (l6 & 0x30) | ((l6 & 6) << 1) | ((l6 & 8) >> 2) | (l6 & 1);
                size_t base = (size_t)(b * NH + h) * LL * HDIM
                            + (size_t)(l >> 6) * 4096 + (size_t)d * 64;
                g_Vt[base + pos]          = __float2half_rn(acc[mi][ni][0] * INV32);
                g_Vt[base + 64 + pos]     = __float2half_rn(acc[mi][ni][1] * INV32);
                g_Vt[base + pos + 2]      = __float2half_rn(acc[mi][ni][2] * INV32);
                g_Vt[base + 64 + pos + 2] = __float2half_rn(acc[mi][ni][3] * INV32);
            }
        }
    }
}

// ============================================================================
// Kernel 3: flash attention v5 — fp16 m16n8k16, base-2 softmax (log2e folded
// into Q), single-fp16 O epilogue. Layouts/pipeline identical to v4.
// ============================================================================
#define FQS 80
#define FL5_SMEM (40960 * 2)

__global__ __launch_bounds__(256, 1) void flash5()
{
    extern __shared__ __half hsm[];
    const int tid = threadIdx.x, lane = tid & 31, g = lane >> 2, t = lane & 3;
    const int warp = tid >> 5;
    __half* Pb = hsm + 20480 + warp * (32 * FQS);

    const int bh = blockIdx.y;
    const size_t head = (size_t)bh * LL * HDIM;
    const int q0 = blockIdx.x * 256 + warp * 32;

    uint32_t qa[2][4][4];
    #pragma unroll
    for (int mt = 0; mt < 2; mt++)
        #pragma unroll
        for (int kc = 0; kc < 4; kc++) {
            const __half* qp = &g_Qf[head + (size_t)(q0 + mt * 16 + g) * HDIM + kc * 16 + t * 4];
            uint2 u0 = *(const uint2*)qp;
            uint2 u1 = *(const uint2*)(qp + 8 * HDIM);
            qa[mt][kc][0] = u0.x; qa[mt][kc][1] = u1.x;
            qa[mt][kc][2] = u0.y; qa[mt][kc][3] = u1.y;
        }

    const int frow = tid >> 2;
    const int fch  = (tid & 3) * 2;

    float o[2][8][4] = {};
    float mv[2][2] = {{-1e30f, -1e30f}, {-1e30f, -1e30f}};
    float lv[2][2] = {};

    {
        const __half* Ks = g_Kf + head;
        const __half* Vs = g_Vt + head;
        #pragma unroll
        for (int i = 0; i < 2; i++) {
            int ch = fch + i;
            cpa16(&hsm[frow * FQS + ch * 8],         &Ks[frow * 64 + ch * 8]);
            cpa16(&hsm[10240 + frow * FQS + ch * 8], &Vs[frow * 64 + ch * 8]);
        }
    }
    CP_COMMIT();

    for (int it = 0; it < LL / 64; ++it) {
        CP_WAIT0();
        __syncthreads();
        if (it + 1 < LL / 64) {
            const __half* Ks = g_Kf + head + (size_t)(it + 1) * 4096;
            const __half* Vs = g_Vt + head + (size_t)(it + 1) * 4096;
            __half* Kd = hsm + ((it + 1) & 1) * 5120;
            __half* Vd = hsm + 10240 + ((it + 1) & 1) * 5120;
            #pragma unroll
            for (int i = 0; i < 2; i++) {
                int ch = fch + i;
                cpa16(&Kd[frow * FQS + ch * 8], &Ks[frow * 64 + ch * 8]);
                cpa16(&Vd[frow * FQS + ch * 8], &Vs[frow * 64 + ch * 8]);
            }
            CP_COMMIT();
        }
        const __half* Ksm = hsm + (it & 1) * 5120;
        const __half* Vsm = hsm + 10240 + (it & 1) * 5120;

        float s[2][8][4] = {};
        #pragma unroll
        for (int kc = 0; kc < 4; kc++) {
            #pragma unroll
            for (int nt = 0; nt < 8; nt++) {
                uint2 bv = *(const uint2*)&Ksm[(nt * 8 + g) * FQS + kc * 16 + t * 4];
                uint32_t bf[2] = { bv.x, bv.y };
                mma16h(s[0][nt], qa[0][kc], bf);
                mma16h(s[1][nt], qa[1][kc], bf);
            }
        }

        #pragma unroll
        for (int mt = 0; mt < 2; mt++) {
            float rmax0 = -1e30f, rmax1 = -1e30f;
            #pragma unroll
            for (int nt = 0; nt < 8; nt++) {
                rmax0 = fmaxf(rmax0, fmaxf(s[mt][nt][0], s[mt][nt][1]));
                rmax1 = fmaxf(rmax1, fmaxf(s[mt][nt][2], s[mt][nt][3]));
            }
            rmax0 = fmaxf(rmax0, __shfl_xor_sync(0xffffffffu, rmax0, 1));
            rmax0 = fmaxf(rmax0, __shfl_xor_sync(0xffffffffu, rmax0, 2));
            rmax1 = fmaxf(rmax1, __shfl_xor_sync(0xffffffffu, rmax1, 1));
            rmax1 = fmaxf(rmax1, __shfl_xor_sync(0xffffffffu, rmax1, 2));

            float nm0 = fmaxf(mv[mt][0], rmax0), nm1 = fmaxf(mv[mt][1], rmax1);
            float c0 = ex2(mv[mt][0] - nm0), c1 = ex2(mv[mt][1] - nm1);
            mv[mt][0] = nm0; mv[mt][1] = nm1;

            float sum0 = 0.0f, sum1 = 0.0f;
            #pragma unroll
            for (int nt = 0; nt < 8; nt++) {
                s[mt][nt][0] = ex2(s[mt][nt][0] - nm0); sum0 += s[mt][nt][0];
                s[mt][nt][1] = ex2(s[mt][nt][1] - nm0); sum0 += s[mt][nt][1];
                s[mt][nt][2] = ex2(s[mt][nt][2] - nm1); sum1 += s[mt][nt][2];
                s[mt][nt][3] = ex2(s[mt][nt][3] - nm1); sum1 += s[mt][nt][3];
            }
            sum0 += __shfl_xor_sync(0xffffffffu, sum0, 1);
            sum0 += __shfl_xor_sync(0xffffffffu, sum0, 2);
            sum1 += __shfl_xor_sync(0xffffffffu, sum1, 1);
            sum1 += __shfl_xor_sync(0xffffffffu, sum1, 2);
            lv[mt][0] = lv[mt][0] * c0 + sum0;
            lv[mt][1] = lv[mt][1] * c1 + sum1;

            #pragma unroll
            for (int nt = 0; nt < 8; nt++) {
                o[mt][nt][0] *= c0; o[mt][nt][1] *= c0;
                o[mt][nt][2] *= c1; o[mt][nt][3] *= c1;
            }

            __half* Pm = Pb + mt * 16 * FQS;
            #pragma unroll
            for (int nt = 0; nt < 8; nt++) {
                int pos = (nt >> 1) * 16 + t * 4 + (nt & 1) * 2;
                *(__half2*)&Pm[g * FQS + pos] =
                    __floats2half2_rn(s[mt][nt][0], s[mt][nt][1]);
                *(__half2*)&Pm[(g + 8) * FQS + pos] =
                    __floats2half2_rn(s[mt][nt][2], s[mt][nt][3]);
            }
        }
        __syncwarp();

        #pragma unroll
        for (int kc = 0; kc < 4; kc++) {
            uint32_t pa[2][4];
            #pragma unroll
            for (int mt = 0; mt < 2; mt++) {
                const __half* Pm = Pb + mt * 16 * FQS;
                uint2 p0 = *(const uint2*)&Pm[g * FQS + kc * 16 + t * 4];
                uint2 p1 = *(const uint2*)&Pm[(g + 8) * FQS + kc * 16 + t * 4];
                pa[mt][0] = p0.x; pa[mt][1] = p1.x;
                pa[mt][2] = p0.y; pa[mt][3] = p1.y;
            }
            #pragma unroll
            for (int nt = 0; nt < 8; nt++) {
                uint2 bv = *(const uint2*)&Vsm[(nt * 8 + g) * FQS + kc * 16 + t * 4];
                uint32_t bf[2] = { bv.x, bv.y };
                mma16h(o[0][nt], pa[0], bf);
                mma16h(o[1][nt], pa[1], bf);
            }
        }
        __syncwarp();
    }

    const int b = bh >> 4, h = bh & 15;
    #pragma unroll
    for (int mt = 0; mt < 2; mt++) {
        float inv0 = 1.0f / lv[mt][0], inv1 = 1.0f / lv[mt][1];
        size_t ob0 = ((size_t)b * LL + q0 + mt * 16 + g) * DD + h * HDIM;
        size_t ob1 = ((size_t)b * LL + q0 + mt * 16 + 8 + g) * DD + h * HDIM;
        #pragma unroll
        for (int nt = 0; nt < 8; nt++) {
            int col = nt * 8 + 2 * t;
            *(__half2*)&g_Of[ob0 + col] =
                __floats2half2_rn(o[mt][nt][0] * inv0, o[mt][nt][1] * inv0);
            *(__half2*)&g_Of[ob1 + col] =
                __floats2half2_rn(o[mt][nt][2] * inv1, o[mt][nt][3] * inv1);
        }
    }
}

// ============================================================================
// Kernel 4: Y = O @ (32*Wo)^T / 32 (NT), fp16x2 (A single, B split).
// ============================================================================
__global__ __launch_bounds__(256) void out_f2(float* __restrict__ Y)
{
    __shared__ __align__(16) __half Ah[128][AKS];
    __shared__ __align__(16) __half Bh[128][AKS], Bl[128][AKS];

    const int tid = threadIdx.x, lane = tid & 31, g = lane >> 2, t = lane & 3;
    const int warp = tid >> 5, wm = warp >> 2, wn = warp & 3;
    const int m0 = blockIdx.y * 128, j0 = blockIdx.x * 128;
    const int ar = tid >> 3, akc = (tid & 7) * 4;

    float acc[4][4][4] = {};
    uint2 pah[4], pbh[4], pbl[4];
    #pragma unroll
    for (int r = 0; r < 4; r++) {
        pah[r] = *(const uint2*)&g_Of[(size_t)(m0 + ar + r * 32) * DD + akc];
        size_t bi = (size_t)(j0 + ar + r * 32) * DD + akc;
        pbh[r] = *(const uint2*)&g_Woh[bi];
        pbl[r] = *(const uint2*)&g_Wol[bi];
    }

    for (int kt = 0; kt < DD; kt += 32) {
        #pragma unroll
        for (int r = 0; r < 4; r++) {
            *(uint2*)&Ah[ar + r * 32][akc] = pah[r];
            *(uint2*)&Bh[ar + r * 32][akc] = pbh[r];
            *(uint2*)&Bl[ar + r * 32][akc] = pbl[r];
        }
        __syncthreads();
        if (kt + 32 < DD) {
            #pragma unroll
            for (int r = 0; r < 4; r++) {
                pah[r] = *(const uint2*)&g_Of[(size_t)(m0 + ar + r * 32) * DD + kt + 32 + akc];
                size_t bi = (size_t)(j0 + ar + r * 32) * DD + kt + 32 + akc;
                pbh[r] = *(const uint2*)&g_Woh[bi];
                pbl[r] = *(const uint2*)&g_Wol[bi];
            }
        }
        #pragma unroll
        for (int ks = 0; ks < 2; ks++) {
            const int kk0 = ks * 16;
            uint32_t ah[4][4], bh[2][4], bl[2][4];
            const int arow = wm * 64 + (lane & 15);
            const int ak   = kk0 + (lane >> 4) * 8;
            #pragma unroll
            for (int mi = 0; mi < 4; mi++)
                ldsm4(ah[mi], &Ah[arow + mi * 16][ak]);
            const int brow = wn * 32 + (lane & 7) + ((lane >> 4) & 1) * 8;
            const int bk   = kk0 + ((lane >> 3) & 1) * 8;
            #pragma unroll
            for (int nj = 0; nj < 2; nj++) {
                ldsm4(bh[nj], &Bh[brow + nj * 16][bk]);
                ldsm4(bl[nj], &Bl[brow + nj * 16][bk]);
            }
            #pragma unroll
            for (int mi = 0; mi < 4; mi++)
                #pragma unroll
                for (int nj = 0; nj < 2; nj++)
                    #pragma unroll
                    for (int h2 = 0; h2 < 2; h2++) {
                        float* c = acc[mi][nj * 2 + h2];
                        mma16h(c, ah[mi], &bh[nj][h2 * 2]);
                        mma16h(c, ah[mi], &bl[nj][h2 * 2]);
                    }
        }
        __syncthreads();
    }

    #pragma unroll
    for (int mi = 0; mi < 4; mi++) {
        int row0 = m0 + wm * 64 + mi * 16 + g;
        #pragma unroll
        for (int ni = 0; ni < 4; ni++) {
            int col = j0 + wn * 32 + ni * 8 + 2 * t;
            *(float2*)&Y[(size_t)row0 * DD + col] =
                make_float2(acc[mi][ni][0] * INV32, acc[mi][ni][1] * INV32);
            *(float2*)&Y[(size_t)(row0 + 8) * DD + col] =
                make_float2(acc[mi][ni][2] * INV32, acc[mi][ni][3] * INV32);
        }
    }
}

// ============================================================================
// launch
// Inputs: 0=inputs 1=rotation 2=entangle 3=Wq 4=Wk 5=Wv 6=Wo; out (B,L,D) fp32
// ============================================================================
extern "C" void kernel_launch(void* const* d_in, const int* in_sizes, int n_in,
                              void* d_out, int out_size)
{
    const float* X   = (const float*)d_in[0];
    const float* R   = (const float*)d_in[1];
    const float* ent = (const float*)d_in[2];
    const float* Wq  = (const float*)d_in[3];
    const float* Wk  = (const float*)d_in[4];
    const float* Wv  = (const float*)d_in[5];
    const float* Wo  = (const float*)d_in[6];
    float* Y = (float*)d_out;

    cudaFuncSetAttribute(flash5,
                         cudaFuncAttributeMaxDynamicSharedMemorySize, FL5_SMEM);

    convert_inputs<<<1184, 256>>>(X, Wo);
    combine_b3<<<dim3(8, 8, 3), 256>>>(Wq, Wk, Wv, R);
    qkv_f2<<<dim3(8, MTOK / 128, 3), 256>>>(ent);
    flash5<<<dim3(LL / 256, BB * NH), 256, FL5_SMEM>>>();
    out_f2<<<dim3(8, MTOK / 128), 256>>>(Y);
}

// round 13
// speedup vs baseline: 1.7937x; 1.1074x over previous
#include <cuda_runtime.h>
#include <cuda_bf16.h>
#include <cuda_fp16.h>
#include <stdint.h>
#include <math.h>

#define DD   1024
#define NH   16
#define HDIM 64
#define BB   2
#define LL   2048
#define MTOK (BB*LL)   // 4096

#define AKS 40     // [row][k] 16-bit smem stride (32 + 8)
#define BKS 136    // [k][n]  16-bit smem stride (128 + 8)

#define LOG2E  1.4426950408889634f
#define INV32  0.03125f

// ---------------- scratch (device globals; no allocations allowed) ----------
__device__ __half g_Wch[3][DD*DD], g_Wcl[3][DD*DD];  // 32*(W^T@R) fp16 split [k][n]
__device__ __half g_Xf[MTOK*DD];                     // X fp16 [m][k]
__device__ __half g_Woh[DD*DD],  g_Wol[DD*DD];       // 32*Wo fp16 split [n][k]
__device__ __half g_Of[MTOK*DD];                     // attn out fp16 (B,L,D)
// fp16 attention operands, mma-fragment-native layouts:
// Q,K: [b][h][l][perm(d)]; Q pre-scaled by ent/8*log2e. V: [b][h][l>>6][d][perm(l&63)]
__device__ __half g_Qf[BB*NH*LL*HDIM];
__device__ __half g_Kf[BB*NH*LL*HDIM];
__device__ __half g_Vt[BB*NH*LL*HDIM];

// ---------------- helpers ----------------------------------------------------
__device__ __forceinline__ float ex2(float x) {
    float y;
    asm("ex2.approx.f32 %0, %1;" : "=f"(y) : "f"(x));
    return y;
}
__device__ __forceinline__ uint32_t packh2(float a, float b) {
    __half2 h = __floats2half2_rn(a, b);
    return *(uint32_t*)&h;
}

__device__ __forceinline__ void mma16(float* d, const uint32_t* a, const uint32_t* b) {
    asm volatile(
        "mma.sync.aligned.m16n8k16.row.col.f32.bf16.bf16.f32 "
        "{%0,%1,%2,%3}, {%4,%5,%6,%7}, {%8,%9}, {%0,%1,%2,%3};"
        : "+f"(d[0]), "+f"(d[1]), "+f"(d[2]), "+f"(d[3])
        : "r"(a[0]), "r"(a[1]), "r"(a[2]), "r"(a[3]), "r"(b[0]), "r"(b[1]));
}
__device__ __forceinline__ void mma16h(float* d, const uint32_t* a, const uint32_t* b) {
    asm volatile(
        "mma.sync.aligned.m16n8k16.row.col.f32.f16.f16.f32 "
        "{%0,%1,%2,%3}, {%4,%5,%6,%7}, {%8,%9}, {%0,%1,%2,%3};"
        : "+f"(d[0]), "+f"(d[1]), "+f"(d[2]), "+f"(d[3])
        : "r"(a[0]), "r"(a[1]), "r"(a[2]), "r"(a[3]), "r"(b[0]), "r"(b[1]));
}

__device__ __forceinline__ void ldsm4(uint32_t* r, const void* p) {
    uint32_t a = (uint32_t)__cvta_generic_to_shared(p);
    asm volatile("ldmatrix.sync.aligned.m8n8.x4.shared.b16 {%0,%1,%2,%3}, [%4];"
        : "=r"(r[0]), "=r"(r[1]), "=r"(r[2]), "=r"(r[3]) : "r"(a));
}
__device__ __forceinline__ void ldsm4t(uint32_t* r, const void* p) {
    uint32_t a = (uint32_t)__cvta_generic_to_shared(p);
    asm volatile("ldmatrix.sync.aligned.m8n8.x4.trans.shared.b16 {%0,%1,%2,%3}, [%4];"
        : "=r"(r[0]), "=r"(r[1]), "=r"(r[2]), "=r"(r[3]) : "r"(a));
}

__device__ __forceinline__ void cpa16(void* smem, const void* gmem) {
    uint32_t s = (uint32_t)__cvta_generic_to_shared(smem);
    asm volatile("cp.async.cg.shared.global [%0], [%1], 16;" :: "r"(s), "l"(gmem) : "memory");
}
#define CP_COMMIT() asm volatile("cp.async.commit_group;" ::: "memory")
#define CP_WAIT0()  asm volatile("cp.async.wait_group 0;" ::: "memory")
#define CP_WAIT1()  asm volatile("cp.async.wait_group 1;" ::: "memory")

// split 4 fp32 -> bf16 hi/lo (combine's smem staging)
__device__ __forceinline__ void sst4(__nv_bfloat16* hp, __nv_bfloat16* lp, float4 v) {
    __nv_bfloat16 hx = __float2bfloat16_rn(v.x), hy = __float2bfloat16_rn(v.y);
    __nv_bfloat16 hz = __float2bfloat16_rn(v.z), hw = __float2bfloat16_rn(v.w);
    __nv_bfloat162* H = (__nv_bfloat162*)hp;
    H[0] = __halves2bfloat162(hx, hy);
    H[1] = __halves2bfloat162(hz, hw);
    __nv_bfloat162* L = (__nv_bfloat162*)lp;
    L[0] = __halves2bfloat162(__float2bfloat16_rn(v.x - __bfloat162float(hx)),
                              __float2bfloat16_rn(v.y - __bfloat162float(hy)));
    L[1] = __halves2bfloat162(__float2bfloat16_rn(v.z - __bfloat162float(hz)),
                              __float2bfloat16_rn(v.w - __bfloat162float(hw)));
}

// split scalar fp32 -> fp16 hi/lo
__device__ __forceinline__ void sp1h(__half* ph, __half* pl, float v) {
    __half h = __float2half_rn(v);
    *ph = h;
    *pl = __float2half_rn(v - __half2float(h));
}

// ============================================================================
// Kernel 0: X -> fp16; Wo*32 -> fp16 hi/lo.
// ============================================================================
__global__ __launch_bounds__(256) void convert_inputs(
    const float* __restrict__ X, const float* __restrict__ Wo)
{
    int i0 = blockIdx.x * blockDim.x + threadIdx.x;
    int st = gridDim.x * blockDim.x;
    for (int i = i0; i < MTOK * DD / 4; i += st) {
        float4 v = ((const float4*)X)[i];
        __half2* H = (__half2*)&g_Xf[i * 4];
        H[0] = __floats2half2_rn(v.x, v.y);
        H[1] = __floats2half2_rn(v.z, v.w);
    }
    for (int i = i0; i < DD * DD / 4; i += st) {
        float4 v = ((const float4*)Wo)[i];
        sp1h(&g_Woh[i * 4 + 0], &g_Wol[i * 4 + 0], v.x * 32.0f);
        sp1h(&g_Woh[i * 4 + 1], &g_Wol[i * 4 + 1], v.y * 32.0f);
        sp1h(&g_Woh[i * 4 + 2], &g_Wol[i * 4 + 2], v.z * 32.0f);
        sp1h(&g_Woh[i * 4 + 3], &g_Wol[i * 4 + 3], v.w * 32.0f);
    }
}

// ============================================================================
// Kernel 1: Wc[z] = W[z]^T @ R  (TN), bf16x3 (accurate). Epilogue stores
// 32*Wc as fp16 hi/lo in [k][n] layout.
// ============================================================================
__global__ __launch_bounds__(256) void combine_b3(
    const float* __restrict__ Wq, const float* __restrict__ Wk,
    const float* __restrict__ Wv, const float* __restrict__ R)
{
    const int z = blockIdx.z;
    const float* W = (z == 0) ? Wq : ((z == 1) ? Wk : Wv);

    __shared__ __align__(16) __nv_bfloat16 Ath[32][BKS], Atl[32][BKS];
    __shared__ __align__(16) __nv_bfloat16 Bth[32][BKS], Btl[32][BKS];

    const int tid = threadIdx.x, lane = tid & 31, g = lane >> 2, t = lane & 3;
    const int warp = tid >> 5, wm = warp >> 2, wn = warp & 3;
    const int i0 = blockIdx.y * 128, j0 = blockIdx.x * 128;
    const int kr = tid >> 5, cc = (tid & 31) * 4;

    float acc[4][4][4] = {};
    float4 pa[4], pb[4];
    #pragma unroll
    for (int r = 0; r < 4; r++) {
        pa[r] = *(const float4*)&W[(size_t)(kr + r * 8) * DD + i0 + cc];
        pb[r] = *(const float4*)&R[(size_t)(kr + r * 8) * DD + j0 + cc];
    }

    for (int kt = 0; kt < DD; kt += 32) {
        #pragma unroll
        for (int r = 0; r < 4; r++) {
            sst4(&Ath[kr + r * 8][cc], &Atl[kr + r * 8][cc], pa[r]);
            sst4(&Bth[kr + r * 8][cc], &Btl[kr + r * 8][cc], pb[r]);
        }
        __syncthreads();
        if (kt + 32 < DD) {
            #pragma unroll
            for (int r = 0; r < 4; r++) {
                pa[r] = *(const float4*)&W[(size_t)(kt + 32 + kr + r * 8) * DD + i0 + cc];
                pb[r] = *(const float4*)&R[(size_t)(kt + 32 + kr + r * 8) * DD + j0 + cc];
            }
        }
        #pragma unroll
        for (int ks = 0; ks < 2; ks++) {
            const int kk0 = ks * 16;
            uint32_t ah[4][4], al[4][4], bh[2][4], bl[2][4];
            const int arow = kk0 + (lane >> 4) * 8 + (lane & 7);
            const int acol = wm * 64 + ((lane >> 3) & 1) * 8;
            #pragma unroll
            for (int mi = 0; mi < 4; mi++) {
                ldsm4t(ah[mi], &Ath[arow][acol + mi * 16]);
                ldsm4t(al[mi], &Atl[arow][acol + mi * 16]);
            }
            const int brow = kk0 + (lane & 7) + ((lane >> 3) & 1) * 8;
            const int bcol = wn * 32 + (lane >> 4) * 8;
            #pragma unroll
            for (int nj = 0; nj < 2; nj++) {
                ldsm4t(bh[nj], &Bth[brow][bcol + nj * 16]);
                ldsm4t(bl[nj], &Btl[brow][bcol + nj * 16]);
            }
            #pragma unroll
            for (int mi = 0; mi < 4; mi++)
                #pragma unroll
                for (int nj = 0; nj < 2; nj++)
                    #pragma unroll
                    for (int h2 = 0; h2 < 2; h2++) {
                        float* c = acc[mi][nj * 2 + h2];
                        mma16(c, ah[mi], &bh[nj][h2 * 2]);
                        mma16(c, ah[mi], &bl[nj][h2 * 2]);
                        mma16(c, al[mi], &bh[nj][h2 * 2]);
                    }
        }
        __syncthreads();
    }

    __half* Ch = g_Wch[z];
    __half* Cl = g_Wcl[z];
    #pragma unroll
    for (int mi = 0; mi < 4; mi++) {
        int row0 = i0 + wm * 64 + mi * 16 + g;      // k index of Wc
        #pragma unroll
        for (int ni = 0; ni < 4; ni++) {
            int col = j0 + wn * 32 + ni * 8 + 2 * t; // n index of Wc
            sp1h(&Ch[(size_t)row0 * DD + col],     &Cl[(size_t)row0 * DD + col],
                 acc[mi][ni][0] * 32.0f);
            sp1h(&Ch[(size_t)row0 * DD + col + 1], &Cl[(size_t)row0 * DD + col + 1],
                 acc[mi][ni][1] * 32.0f);
            sp1h(&Ch[(size_t)(row0 + 8) * DD + col],     &Cl[(size_t)(row0 + 8) * DD + col],
                 acc[mi][ni][2] * 32.0f);
            sp1h(&Ch[(size_t)(row0 + 8) * DD + col + 1], &Cl[(size_t)(row0 + 8) * DD + col + 1],
                 acc[mi][ni][3] * 32.0f);
        }
    }
}

// ============================================================================
// Kernel 2: P = X @ (32*Wc[z]) (NN), fp16x2, cp.async double-buffered smem,
// 2 CTAs/SM. Scatter into fp16 flash layouts (1/32 folded into scales).
// dyn smem: 2 * (A 128x40 + Bh 32x136 + Bl 32x136) halfs = 55296 B
// ============================================================================
#define QA_BUF 5120
#define QB_BUF 4352
#define QBUF   (QA_BUF + 2 * QB_BUF)
#define QKV_SMEM (2 * QBUF * 2)

__global__ __launch_bounds__(256, 2) void qkv_f2(const float* __restrict__ ent)
{
    extern __shared__ __half qsm[];
    const int z = blockIdx.z;
    const __half* Wh = g_Wch[z];
    const __half* Wl = g_Wcl[z];

    const int tid = threadIdx.x, lane = tid & 31, g = lane >> 2, t = lane & 3;
    const int warp = tid >> 5, wm = warp >> 2, wn = warp & 3;
    const int m0 = blockIdx.y * 128, j0 = blockIdx.x * 128;
    const int b = m0 >> 11;

    auto fill = [&](int bi, int kt) {
        __half* A  = qsm + bi * QBUF;
        __half* Bh = A + QA_BUF;
        __half* Bl = Bh + QB_BUF;
        #pragma unroll
        for (int i = 0; i < 2; i++) {
            int idx = tid + i * 256;
            int row = idx >> 2, ch = idx & 3;
            cpa16(&A[row * AKS + ch * 8], &g_Xf[(size_t)(m0 + row) * DD + kt + ch * 8]);
        }
        #pragma unroll
        for (int i = 0; i < 2; i++) {
            int idx = tid + i * 256;
            int row = idx >> 4, ch = idx & 15;
            size_t src = (size_t)(kt + row) * DD + j0 + ch * 8;
            cpa16(&Bh[row * BKS + ch * 8], &Wh[src]);
            cpa16(&Bl[row * BKS + ch * 8], &Wl[src]);
        }
    };

    float acc[4][4][4] = {};

    fill(0, 0);  CP_COMMIT();
    fill(1, 32); CP_COMMIT();

    const int NT = DD / 32;
    for (int it = 0; it < NT; ++it) {
        if (it == NT - 1) { CP_WAIT0(); } else { CP_WAIT1(); }
        __syncthreads();
        const __half* A  = qsm + (it & 1) * QBUF;
        const __half* Bh = A + QA_BUF;
        const __half* Bl = Bh + QB_BUF;
        #pragma unroll
        for (int ks = 0; ks < 2; ks++) {
            const int kk0 = ks * 16;
            uint32_t ah[4][4], bh[2][4], bl[2][4];
            const int arow = wm * 64 + (lane & 15);
            const int ak   = kk0 + (lane >> 4) * 8;
            #pragma unroll
            for (int mi = 0; mi < 4; mi++)
                ldsm4(ah[mi], &A[(arow + mi * 16) * AKS + ak]);
            const int brow = kk0 + (lane & 7) + ((lane >> 3) & 1) * 8;
            const int bcol = wn * 32 + (lane >> 4) * 8;
            #pragma unroll
            for (int nj = 0; nj < 2; nj++) {
                ldsm4t(bh[nj], &Bh[brow * BKS + bcol + nj * 16]);
                ldsm4t(bl[nj], &Bl[brow * BKS + bcol + nj * 16]);
            }
            #pragma unroll
            for (int mi = 0; mi < 4; mi++)
                #pragma unroll
                for (int nj = 0; nj < 2; nj++)
                    #pragma unroll
                    for (int h2 = 0; h2 < 2; h2++) {
                        float* c = acc[mi][nj * 2 + h2];
                        mma16h(c, ah[mi], &bh[nj][h2 * 2]);
                        mma16h(c, ah[mi], &bl[nj][h2 * 2]);
                    }
        }
        __syncthreads();
        if (it + 2 < NT) { fill(it & 1, (it + 2) * 32); CP_COMMIT(); }
    }

    if (z < 2) {
        __half* OutH = (z == 0) ? g_Qf : g_Kf;
        #pragma unroll
        for (int ni = 0; ni < 4; ni++) {
            int n = j0 + wn * 32 + ni * 8 + 2 * t;    // even
            int h = n >> 6, d = n & 63;
            int pos = (d & 0x30) | ((d & 6) << 1) | ((d & 8) >> 2);
            float s = (z == 0) ? (ent[h] * 0.125f * LOG2E * INV32) : INV32;
            #pragma unroll
            for (int mi = 0; mi < 4; mi++) {
                int m = m0 + wm * 64 + mi * 16 + g;
                int l = m & (LL - 1);
                size_t base = ((size_t)(b * NH + h) * LL + l) * HDIM + pos;
                *(__half2*)&OutH[base] =
                    __floats2half2_rn(acc[mi][ni][0] * s, acc[mi][ni][1] * s);
                *(__half2*)&OutH[base + 8 * HDIM] =
                    __floats2half2_rn(acc[mi][ni][2] * s, acc[mi][ni][3] * s);
            }
        }
    } else {
        #pragma unroll
        for (int ni = 0; ni < 4; ni++) {
            int n = j0 + wn * 32 + ni * 8 + 2 * t;
            int h = n >> 6, d = n & 63;               // d even
            #pragma unroll
            for (int mi = 0; mi < 4; mi++) {
                int m = m0 + wm * 64 + mi * 16 + g;
                int l = m & (LL - 1);
                int l6 = l & 63;
                int pos = (l6 & 0x30) | ((l6 & 6) << 1) | ((l6 & 8) >> 2) | (l6 & 1);
                size_t base = (size_t)(b * NH + h) * LL * HDIM
                            + (size_t)(l >> 6) * 4096 + (size_t)d * 64;
                g_Vt[base + pos]          = __float2half_rn(acc[mi][ni][0] * INV32);
                g_Vt[base + 64 + pos]     = __float2half_rn(acc[mi][ni][1] * INV32);
                g_Vt[base + pos + 2]      = __float2half_rn(acc[mi][ni][2] * INV32);
                g_Vt[base + 64 + pos + 2] = __float2half_rn(acc[mi][ni][3] * INV32);
            }
        }
    }
}

// ============================================================================
// Kernel 3: flash attention v6 — fp16 m16n8k16, base-2 softmax. The P smem
// round-trip is GONE: the S C-fragment IS the P A-fragment (cols of nt=2kc,
// 2kc+1 are exactly A-frag cols of chunk kc) — pure register packing.
// smem: K 2x64x80 + V 2x64x80 halfs = 40 KB.
// ============================================================================
#define FQS 80
#define FL6_SMEM (20480 * 2)

__global__ __launch_bounds__(256, 1) void flash6()
{
    extern __shared__ __half hsm[];
    const int tid = threadIdx.x, lane = tid & 31, g = lane >> 2, t = lane & 3;
    const int warp = tid >> 5;

    const int bh = blockIdx.y;
    const size_t head = (size_t)bh * LL * HDIM;
    const int q0 = blockIdx.x * 256 + warp * 32;

    uint32_t qa[2][4][4];
    #pragma unroll
    for (int mt = 0; mt < 2; mt++)
        #pragma unroll
        for (int kc = 0; kc < 4; kc++) {
            const __half* qp = &g_Qf[head + (size_t)(q0 + mt * 16 + g) * HDIM + kc * 16 + t * 4];
            uint2 u0 = *(const uint2*)qp;
            uint2 u1 = *(const uint2*)(qp + 8 * HDIM);
            qa[mt][kc][0] = u0.x; qa[mt][kc][1] = u1.x;
            qa[mt][kc][2] = u0.y; qa[mt][kc][3] = u1.y;
        }

    const int frow = tid >> 2;
    const int fch  = (tid & 3) * 2;

    float o[2][8][4] = {};
    float mv[2][2] = {{-1e30f, -1e30f}, {-1e30f, -1e30f}};
    float lv[2][2] = {};

    {
        const __half* Ks = g_Kf + head;
        const __half* Vs = g_Vt + head;
        #pragma unroll
        for (int i = 0; i < 2; i++) {
            int ch = fch + i;
            cpa16(&hsm[frow * FQS + ch * 8],         &Ks[frow * 64 + ch * 8]);
            cpa16(&hsm[10240 + frow * FQS + ch * 8], &Vs[frow * 64 + ch * 8]);
        }
    }
    CP_COMMIT();

    for (int it = 0; it < LL / 64; ++it) {
        CP_WAIT0();
        __syncthreads();
        if (it + 1 < LL / 64) {
            const __half* Ks = g_Kf + head + (size_t)(it + 1) * 4096;
            const __half* Vs = g_Vt + head + (size_t)(it + 1) * 4096;
            __half* Kd = hsm + ((it + 1) & 1) * 5120;
            __half* Vd = hsm + 10240 + ((it + 1) & 1) * 5120;
            #pragma unroll
            for (int i = 0; i < 2; i++) {
                int ch = fch + i;
                cpa16(&Kd[frow * FQS + ch * 8], &Ks[frow * 64 + ch * 8]);
                cpa16(&Vd[frow * FQS + ch * 8], &Vs[frow * 64 + ch * 8]);
            }
            CP_COMMIT();
        }
        const __half* Ksm = hsm + (it & 1) * 5120;
        const __half* Vsm = hsm + 10240 + (it & 1) * 5120;

        // S = Q @ K^T : 32 x 64 per warp
        float s[2][8][4] = {};
        #pragma unroll
        for (int kc = 0; kc < 4; kc++) {
            #pragma unroll
            for (int nt = 0; nt < 8; nt++) {
                uint2 bv = *(const uint2*)&Ksm[(nt * 8 + g) * FQS + kc * 16 + t * 4];
                uint32_t bf[2] = { bv.x, bv.y };
                mma16h(s[0][nt], qa[0][kc], bf);
                mma16h(s[1][nt], qa[1][kc], bf);
            }
        }

        // online softmax per m-tile (base-2; log2e pre-folded into Q)
        #pragma unroll
        for (int mt = 0; mt < 2; mt++) {
            float rmax0 = -1e30f, rmax1 = -1e30f;
            #pragma unroll
            for (int nt = 0; nt < 8; nt++) {
                rmax0 = fmaxf(rmax0, fmaxf(s[mt][nt][0], s[mt][nt][1]));
                rmax1 = fmaxf(rmax1, fmaxf(s[mt][nt][2], s[mt][nt][3]));
            }
            rmax0 = fmaxf(rmax0, __shfl_xor_sync(0xffffffffu, rmax0, 1));
            rmax0 = fmaxf(rmax0, __shfl_xor_sync(0xffffffffu, rmax0, 2));
            rmax1 = fmaxf(rmax1, __shfl_xor_sync(0xffffffffu, rmax1, 1));
            rmax1 = fmaxf(rmax1, __shfl_xor_sync(0xffffffffu, rmax1, 2));

            float nm0 = fmaxf(mv[mt][0], rmax0), nm1 = fmaxf(mv[mt][1], rmax1);
            float c0 = ex2(mv[mt][0] - nm0), c1 = ex2(mv[mt][1] - nm1);
            mv[mt][0] = nm0; mv[mt][1] = nm1;

            float sum0 = 0.0f, sum1 = 0.0f;
            #pragma unroll
            for (int nt = 0; nt < 8; nt++) {
                s[mt][nt][0] = ex2(s[mt][nt][0] - nm0); sum0 += s[mt][nt][0];
                s[mt][nt][1] = ex2(s[mt][nt][1] - nm0); sum0 += s[mt][nt][1];
                s[mt][nt][2] = ex2(s[mt][nt][2] - nm1); sum1 += s[mt][nt][2];
                s[mt][nt][3] = ex2(s[mt][nt][3] - nm1); sum1 += s[mt][nt][3];
            }
            sum0 += __shfl_xor_sync(0xffffffffu, sum0, 1);
            sum0 += __shfl_xor_sync(0xffffffffu, sum0, 2);
            sum1 += __shfl_xor_sync(0xffffffffu, sum1, 1);
            sum1 += __shfl_xor_sync(0xffffffffu, sum1, 2);
            lv[mt][0] = lv[mt][0] * c0 + sum0;
            lv[mt][1] = lv[mt][1] * c1 + sum1;

            #pragma unroll
            for (int nt = 0; nt < 8; nt++) {
                o[mt][nt][0] *= c0; o[mt][nt][1] *= c0;
                o[mt][nt][2] *= c1; o[mt][nt][3] *= c1;
            }
        }

        // O += P @ V : P A-fragments packed directly from S C-fragments
        #pragma unroll
        for (int kc = 0; kc < 4; kc++) {
            uint32_t pa[2][4];
            #pragma unroll
            for (int mt = 0; mt < 2; mt++) {
                pa[mt][0] = packh2(s[mt][2 * kc][0],     s[mt][2 * kc][1]);
                pa[mt][1] = packh2(s[mt][2 * kc][2],     s[mt][2 * kc][3]);
                pa[mt][2] = packh2(s[mt][2 * kc + 1][0], s[mt][2 * kc + 1][1]);
                pa[mt][3] = packh2(s[mt][2 * kc + 1][2], s[mt][2 * kc + 1][3]);
            }
            #pragma unroll
            for (int nt = 0; nt < 8; nt++) {
                uint2 bv = *(const uint2*)&Vsm[(nt * 8 + g) * FQS + kc * 16 + t * 4];
                uint32_t bf[2] = { bv.x, bv.y };
                mma16h(o[0][nt], pa[0], bf);
                mma16h(o[1][nt], pa[1], bf);
            }
        }
    }

    const int b = bh >> 4, h = bh & 15;
    #pragma unroll
    for (int mt = 0; mt < 2; mt++) {
        float inv0 = 1.0f / lv[mt][0], inv1 = 1.0f / lv[mt][1];
        size_t ob0 = ((size_t)b * LL + q0 + mt * 16 + g) * DD + h * HDIM;
        size_t ob1 = ((size_t)b * LL + q0 + mt * 16 + 8 + g) * DD + h * HDIM;
        #pragma unroll
        for (int nt = 0; nt < 8; nt++) {
            int col = nt * 8 + 2 * t;
            *(__half2*)&g_Of[ob0 + col] =
                __floats2half2_rn(o[mt][nt][0] * inv0, o[mt][nt][1] * inv0);
            *(__half2*)&g_Of[ob1 + col] =
                __floats2half2_rn(o[mt][nt][2] * inv1, o[mt][nt][3] * inv1);
        }
    }
}

// ============================================================================
// Kernel 4: Y = O @ (32*Wo)^T / 32 (NT), fp16x2, cp.async double-buffered,
// 2 CTAs/SM. dyn smem: 2 * 3 * (128x40) halfs = 61440 B.
// ============================================================================
#define OBUF (3 * 5120)
#define OUT_SMEM (2 * OBUF * 2)

__global__ __launch_bounds__(256, 2) void out_f2(float* __restrict__ Y)
{
    extern __shared__ __half osm[];
    const int tid = threadIdx.x, lane = tid & 31, g = lane >> 2, t = lane & 3;
    const int warp = tid >> 5, wm = warp >> 2, wn = warp & 3;
    const int m0 = blockIdx.y * 128, j0 = blockIdx.x * 128;

    auto fill = [&](int bi, int kt) {
        __half* A  = osm + bi * OBUF;
        __half* Bh = A + 5120;
        __half* Bl = Bh + 5120;
        #pragma unroll
        for (int i = 0; i < 2; i++) {
            int idx = tid + i * 256;
            int row = idx >> 2, ch = idx & 3;
            cpa16(&A[row * AKS + ch * 8], &g_Of[(size_t)(m0 + row) * DD + kt + ch * 8]);
            size_t src = (size_t)(j0 + row) * DD + kt + ch * 8;
            cpa16(&Bh[row * AKS + ch * 8], &g_Woh[src]);
            cpa16(&Bl[row * AKS + ch * 8], &g_Wol[src]);
        }
    };

    float acc[4][4][4] = {};

    fill(0, 0);  CP_COMMIT();
    fill(1, 32); CP_COMMIT();

    const int NT = DD / 32;
    for (int it = 0; it < NT; ++it) {
        if (it == NT - 1) { CP_WAIT0(); } else { CP_WAIT1(); }
        __syncthreads();
        const __half* A  = osm + (it & 1) * OBUF;
        const __half* Bh = A + 5120;
        const __half* Bl = Bh + 5120;
        #pragma unroll
        for (int ks = 0; ks < 2; ks++) {
            const int kk0 = ks * 16;
            uint32_t ah[4][4], bh[2][4], bl[2][4];
            const int arow = wm * 64 + (lane & 15);
            const int ak   = kk0 + (lane >> 4) * 8;
            #pragma unroll
            for (int mi = 0; mi < 4; mi++)
                ldsm4(ah[mi], &A[(arow + mi * 16) * AKS + ak]);
            const int brow = wn * 32 + (lane & 7) + ((lane >> 4) & 1) * 8;
            const int bk   = kk0 + ((lane >> 3) & 1) * 8;
            #pragma unroll
            for (int nj = 0; nj < 2; nj++) {
                ldsm4(bh[nj], &Bh[(brow + nj * 16) * AKS + bk]);
                ldsm4(bl[nj], &Bl[(brow + nj * 16) * AKS + bk]);
            }
            #pragma unroll
            for (int mi = 0; mi < 4; mi++)
                #pragma unroll
                for (int nj = 0; nj < 2; nj++)
                    #pragma unroll
                    for (int h2 = 0; h2 < 2; h2++) {
                        float* c = acc[mi][nj * 2 + h2];
                        mma16h(c, ah[mi], &bh[nj][h2 * 2]);
                        mma16h(c, ah[mi], &bl[nj][h2 * 2]);
                    }
        }
        __syncthreads();
        if (it + 2 < NT) { fill(it & 1, (it + 2) * 32); CP_COMMIT(); }
    }

    #pragma unroll
    for (int mi = 0; mi < 4; mi++) {
        int row0 = m0 + wm * 64 + mi * 16 + g;
        #pragma unroll
        for (int ni = 0; ni < 4; ni++) {
            int col = j0 + wn * 32 + ni * 8 + 2 * t;
            *(float2*)&Y[(size_t)row0 * DD + col] =
                make_float2(acc[mi][ni][0] * INV32, acc[mi][ni][1] * INV32);
            *(float2*)&Y[(size_t)(row0 + 8) * DD + col] =
                make_float2(acc[mi][ni][2] * INV32, acc[mi][ni][3] * INV32);
        }
    }
}

// ============================================================================
// launch
// Inputs: 0=inputs 1=rotation 2=entangle 3=Wq 4=Wk 5=Wv 6=Wo; out (B,L,D) fp32
// ============================================================================
extern "C" void kernel_launch(void* const* d_in, const int* in_sizes, int n_in,
                              void* d_out, int out_size)
{
    const float* X   = (const float*)d_in[0];
    const float* R   = (const float*)d_in[1];
    const float* ent = (const float*)d_in[2];
    const float* Wq  = (const float*)d_in[3];
    const float* Wk  = (const float*)d_in[4];
    const float* Wv  = (const float*)d_in[5];
    const float* Wo  = (const float*)d_in[6];
    float* Y = (float*)d_out;

    cudaFuncSetAttribute(flash6, cudaFuncAttributeMaxDynamicSharedMemorySize, FL6_SMEM);
    cudaFuncSetAttribute(qkv_f2, cudaFuncAttributeMaxDynamicSharedMemorySize, QKV_SMEM);
    cudaFuncSetAttribute(out_f2, cudaFuncAttributeMaxDynamicSharedMemorySize, OUT_SMEM);

    convert_inputs<<<1184, 256>>>(X, Wo);
    combine_b3<<<dim3(8, 8, 3), 256>>>(Wq, Wk, Wv, R);
    qkv_f2<<<dim3(8, MTOK / 128, 3), 256, QKV_SMEM>>>(ent);
    flash6<<<dim3(LL / 256, BB * NH), 256, FL6_SMEM>>>();
    out_f2<<<dim3(8, MTOK / 128), 256, OUT_SMEM>>>(Y);
}

// round 14
// speedup vs baseline: 1.8229x; 1.0162x over previous
#include <cuda_runtime.h>
#include <cuda_bf16.h>
#include <cuda_fp16.h>
#include <stdint.h>
#include <math.h>

#define DD   1024
#define NH   16
#define HDIM 64
#define BB   2
#define LL   2048
#define MTOK (BB*LL)   // 4096

#define AKS 40     // [row][k] 16-bit smem stride (32 + 8)
#define BKS 136    // [k][n]  16-bit smem stride (128 + 8)

#define LOG2E  1.4426950408889634f
#define INV32  0.03125f

// ---------------- scratch (device globals; no allocations allowed) ----------
__device__ __half g_Wch[3][DD*DD], g_Wcl[3][DD*DD];  // 32*(W^T@R) fp16 split [k][n]
__device__ __half g_Xf[MTOK*DD];                     // X fp16 [m][k]
__device__ __half g_Woh[DD*DD],  g_Wol[DD*DD];       // 32*Wo fp16 split [n][k]
__device__ __half g_Of[MTOK*DD];                     // attn out fp16 (B,L,D)
// fp16 attention operands, mma-fragment-native layouts:
// Q,K: [b][h][l][perm(d)]; Q pre-scaled by ent/8*log2e. V: [b][h][l>>6][d][perm(l&63)]
__device__ __half g_Qf[BB*NH*LL*HDIM];
__device__ __half g_Kf[BB*NH*LL*HDIM];
__device__ __half g_Vt[BB*NH*LL*HDIM];

// ---------------- helpers ----------------------------------------------------
__device__ __forceinline__ float ex2(float x) {
    float y;
    asm("ex2.approx.f32 %0, %1;" : "=f"(y) : "f"(x));
    return y;
}
__device__ __forceinline__ uint32_t ex2h2(float a, float b) {
    __half2 h = __floats2half2_rn(a, b);
    uint32_t r;
    asm("ex2.approx.f16x2 %0, %1;" : "=r"(r) : "r"(*(uint32_t*)&h));
    return r;
}

__device__ __forceinline__ void mma16(float* d, const uint32_t* a, const uint32_t* b) {
    asm volatile(
        "mma.sync.aligned.m16n8k16.row.col.f32.bf16.bf16.f32 "
        "{%0,%1,%2,%3}, {%4,%5,%6,%7}, {%8,%9}, {%0,%1,%2,%3};"
        : "+f"(d[0]), "+f"(d[1]), "+f"(d[2]), "+f"(d[3])
        : "r"(a[0]), "r"(a[1]), "r"(a[2]), "r"(a[3]), "r"(b[0]), "r"(b[1]));
}
__device__ __forceinline__ void mma16h(float* d, const uint32_t* a, const uint32_t* b) {
    asm volatile(
        "mma.sync.aligned.m16n8k16.row.col.f32.f16.f16.f32 "
        "{%0,%1,%2,%3}, {%4,%5,%6,%7}, {%8,%9}, {%0,%1,%2,%3};"
        : "+f"(d[0]), "+f"(d[1]), "+f"(d[2]), "+f"(d[3])
        : "r"(a[0]), "r"(a[1]), "r"(a[2]), "r"(a[3]), "r"(b[0]), "r"(b[1]));
}

__device__ __forceinline__ void ldsm4(uint32_t* r, const void* p) {
    uint32_t a = (uint32_t)__cvta_generic_to_shared(p);
    asm volatile("ldmatrix.sync.aligned.m8n8.x4.shared.b16 {%0,%1,%2,%3}, [%4];"
        : "=r"(r[0]), "=r"(r[1]), "=r"(r[2]), "=r"(r[3]) : "r"(a));
}
__device__ __forceinline__ void ldsm4t(uint32_t* r, const void* p) {
    uint32_t a = (uint32_t)__cvta_generic_to_shared(p);
    asm volatile("ldmatrix.sync.aligned.m8n8.x4.trans.shared.b16 {%0,%1,%2,%3}, [%4];"
        : "=r"(r[0]), "=r"(r[1]), "=r"(r[2]), "=r"(r[3]) : "r"(a));
}

__device__ __forceinline__ void cpa16(void* smem, const void* gmem) {
    uint32_t s = (uint32_t)__cvta_generic_to_shared(smem);
    asm volatile("cp.async.cg.shared.global [%0], [%1], 16;" :: "r"(s), "l"(gmem) : "memory");
}
#define CP_COMMIT() asm volatile("cp.async.commit_group;" ::: "memory")
#define CP_WAIT0()  asm volatile("cp.async.wait_group 0;" ::: "memory")
#define CP_WAIT1()  asm volatile("cp.async.wait_group 1;" ::: "memory")

// split 4 fp32 -> bf16 hi/lo (combine's smem staging)
__device__ __forceinline__ void sst4(__nv_bfloat16* hp, __nv_bfloat16* lp, float4 v) {
    __nv_bfloat16 hx = __float2bfloat16_rn(v.x), hy = __float2bfloat16_rn(v.y);
    __nv_bfloat16 hz = __float2bfloat16_rn(v.z), hw = __float2bfloat16_rn(v.w);
    __nv_bfloat162* H = (__nv_bfloat162*)hp;
    H[0] = __halves2bfloat162(hx, hy);
    H[1] = __halves2bfloat162(hz, hw);
    __nv_bfloat162* L = (__nv_bfloat162*)lp;
    L[0] = __halves2bfloat162(__float2bfloat16_rn(v.x - __bfloat162float(hx)),
                              __float2bfloat16_rn(v.y - __bfloat162float(hy)));
    L[1] = __halves2bfloat162(__float2bfloat16_rn(v.z - __bfloat162float(hz)),
                              __float2bfloat16_rn(v.w - __bfloat162float(hw)));
}

// split scalar fp32 -> fp16 hi/lo
__device__ __forceinline__ void sp1h(__half* ph, __half* pl, float v) {
    __half h = __float2half_rn(v);
    *ph = h;
    *pl = __float2half_rn(v - __half2float(h));
}

// ============================================================================
// Kernel 0: X -> fp16; Wo*32 -> fp16 hi/lo.
// ============================================================================
__global__ __launch_bounds__(256) void convert_inputs(
    const float* __restrict__ X, const float* __restrict__ Wo)
{
    int i0 = blockIdx.x * blockDim.x + threadIdx.x;
    int st = gridDim.x * blockDim.x;
    for (int i = i0; i < MTOK * DD / 4; i += st) {
        float4 v = ((const float4*)X)[i];
        __half2* H = (__half2*)&g_Xf[i * 4];
        H[0] = __floats2half2_rn(v.x, v.y);
        H[1] = __floats2half2_rn(v.z, v.w);
    }
    for (int i = i0; i < DD * DD / 4; i += st) {
        float4 v = ((const float4*)Wo)[i];
        sp1h(&g_Woh[i * 4 + 0], &g_Wol[i * 4 + 0], v.x * 32.0f);
        sp1h(&g_Woh[i * 4 + 1], &g_Wol[i * 4 + 1], v.y * 32.0f);
        sp1h(&g_Woh[i * 4 + 2], &g_Wol[i * 4 + 2], v.z * 32.0f);
        sp1h(&g_Woh[i * 4 + 3], &g_Wol[i * 4 + 3], v.w * 32.0f);
    }
}

// ============================================================================
// Kernel 1: Wc[z] = W[z]^T @ R  (TN), bf16x3 (accurate). Epilogue stores
// 32*Wc as fp16 hi/lo in [k][n] layout.
// ============================================================================
__global__ __launch_bounds__(256) void combine_b3(
    const float* __restrict__ Wq, const float* __restrict__ Wk,
    const float* __restrict__ Wv, const float* __restrict__ R)
{
    const int z = blockIdx.z;
    const float* W = (z == 0) ? Wq : ((z == 1) ? Wk : Wv);

    __shared__ __align__(16) __nv_bfloat16 Ath[32][BKS], Atl[32][BKS];
    __shared__ __align__(16) __nv_bfloat16 Bth[32][BKS], Btl[32][BKS];

    const int tid = threadIdx.x, lane = tid & 31, g = lane >> 2, t = lane & 3;
    const int warp = tid >> 5, wm = warp >> 2, wn = warp & 3;
    const int i0 = blockIdx.y * 128, j0 = blockIdx.x * 128;
    const int kr = tid >> 5, cc = (tid & 31) * 4;

    float acc[4][4][4] = {};
    float4 pa[4], pb[4];
    #pragma unroll
    for (int r = 0; r < 4; r++) {
        pa[r] = *(const float4*)&W[(size_t)(kr + r * 8) * DD + i0 + cc];
        pb[r] = *(const float4*)&R[(size_t)(kr + r * 8) * DD + j0 + cc];
    }

    for (int kt = 0; kt < DD; kt += 32) {
        #pragma unroll
        for (int r = 0; r < 4; r++) {
            sst4(&Ath[kr + r * 8][cc], &Atl[kr + r * 8][cc], pa[r]);
            sst4(&Bth[kr + r * 8][cc], &Btl[kr + r * 8][cc], pb[r]);
        }
        __syncthreads();
        if (kt + 32 < DD) {
            #pragma unroll
            for (int r = 0; r < 4; r++) {
                pa[r] = *(const float4*)&W[(size_t)(kt + 32 + kr + r * 8) * DD + i0 + cc];
                pb[r] = *(const float4*)&R[(size_t)(kt + 32 + kr + r * 8) * DD + j0 + cc];
            }
        }
        #pragma unroll
        for (int ks = 0; ks < 2; ks++) {
            const int kk0 = ks * 16;
            uint32_t ah[4][4], al[4][4], bh[2][4], bl[2][4];
            const int arow = kk0 + (lane >> 4) * 8 + (lane & 7);
            const int acol = wm * 64 + ((lane >> 3) & 1) * 8;
            #pragma unroll
            for (int mi = 0; mi < 4; mi++) {
                ldsm4t(ah[mi], &Ath[arow][acol + mi * 16]);
                ldsm4t(al[mi], &Atl[arow][acol + mi * 16]);
            }
            const int brow = kk0 + (lane & 7) + ((lane >> 3) & 1) * 8;
            const int bcol = wn * 32 + (lane >> 4) * 8;
            #pragma unroll
            for (int nj = 0; nj < 2; nj++) {
                ldsm4t(bh[nj], &Bth[brow][bcol + nj * 16]);
                ldsm4t(bl[nj], &Btl[brow][bcol + nj * 16]);
            }
            #pragma unroll
            for (int mi = 0; mi < 4; mi++)
                #pragma unroll
                for (int nj = 0; nj < 2; nj++)
                    #pragma unroll
                    for (int h2 = 0; h2 < 2; h2++) {
                        float* c = acc[mi][nj * 2 + h2];
                        mma16(c, ah[mi], &bh[nj][h2 * 2]);
                        mma16(c, ah[mi], &bl[nj][h2 * 2]);
                        mma16(c, al[mi], &bh[nj][h2 * 2]);
                    }
        }
        __syncthreads();
    }

    __half* Ch = g_Wch[z];
    __half* Cl = g_Wcl[z];
    #pragma unroll
    for (int mi = 0; mi < 4; mi++) {
        int row0 = i0 + wm * 64 + mi * 16 + g;      // k index of Wc
        #pragma unroll
        for (int ni = 0; ni < 4; ni++) {
            int col = j0 + wn * 32 + ni * 8 + 2 * t; // n index of Wc
            sp1h(&Ch[(size_t)row0 * DD + col],     &Cl[(size_t)row0 * DD + col],
                 acc[mi][ni][0] * 32.0f);
            sp1h(&Ch[(size_t)row0 * DD + col + 1], &Cl[(size_t)row0 * DD + col + 1],
                 acc[mi][ni][1] * 32.0f);
            sp1h(&Ch[(size_t)(row0 + 8) * DD + col],     &Cl[(size_t)(row0 + 8) * DD + col],
                 acc[mi][ni][2] * 32.0f);
            sp1h(&Ch[(size_t)(row0 + 8) * DD + col + 1], &Cl[(size_t)(row0 + 8) * DD + col + 1],
                 acc[mi][ni][3] * 32.0f);
        }
    }
}

// ============================================================================
// Kernel 2: P = X @ (32*Wc[z]) (NN), fp16x2, cp.async double-buffered smem,
// 2 CTAs/SM. Scatter into fp16 flash layouts (1/32 folded into scales).
// ============================================================================
#define QA_BUF 5120
#define QB_BUF 4352
#define QBUF   (QA_BUF + 2 * QB_BUF)
#define QKV_SMEM (2 * QBUF * 2)

__global__ __launch_bounds__(256, 2) void qkv_f2(const float* __restrict__ ent)
{
    extern __shared__ __half qsm[];
    const int z = blockIdx.z;
    const __half* Wh = g_Wch[z];
    const __half* Wl = g_Wcl[z];

    const int tid = threadIdx.x, lane = tid & 31, g = lane >> 2, t = lane & 3;
    const int warp = tid >> 5, wm = warp >> 2, wn = warp & 3;
    const int m0 = blockIdx.y * 128, j0 = blockIdx.x * 128;
    const int b = m0 >> 11;

    auto fill = [&](int bi, int kt) {
        __half* A  = qsm + bi * QBUF;
        __half* Bh = A + QA_BUF;
        __half* Bl = Bh + QB_BUF;
        #pragma unroll
        for (int i = 0; i < 2; i++) {
            int idx = tid + i * 256;
            int row = idx >> 2, ch = idx & 3;
            cpa16(&A[row * AKS + ch * 8], &g_Xf[(size_t)(m0 + row) * DD + kt + ch * 8]);
        }
        #pragma unroll
        for (int i = 0; i < 2; i++) {
            int idx = tid + i * 256;
            int row = idx >> 4, ch = idx & 15;
            size_t src = (size_t)(kt + row) * DD + j0 + ch * 8;
            cpa16(&Bh[row * BKS + ch * 8], &Wh[src]);
            cpa16(&Bl[row * BKS + ch * 8], &Wl[src]);
        }
    };

    float acc[4][4][4] = {};

    fill(0, 0);  CP_COMMIT();
    fill(1, 32); CP_COMMIT();

    const int NT = DD / 32;
    for (int it = 0; it < NT; ++it) {
        if (it == NT - 1) { CP_WAIT0(); } else { CP_WAIT1(); }
        __syncthreads();
        const __half* A  = qsm + (it & 1) * QBUF;
        const __half* Bh = A + QA_BUF;
        const __half* Bl = Bh + QB_BUF;
        #pragma unroll
        for (int ks = 0; ks < 2; ks++) {
            const int kk0 = ks * 16;
            uint32_t ah[4][4], bh[2][4], bl[2][4];
            const int arow = wm * 64 + (lane & 15);
            const int ak   = kk0 + (lane >> 4) * 8;
            #pragma unroll
            for (int mi = 0; mi < 4; mi++)
                ldsm4(ah[mi], &A[(arow + mi * 16) * AKS + ak]);
            const int brow = kk0 + (lane & 7) + ((lane >> 3) & 1) * 8;
            const int bcol = wn * 32 + (lane >> 4) * 8;
            #pragma unroll
            for (int nj = 0; nj < 2; nj++) {
                ldsm4t(bh[nj], &Bh[brow * BKS + bcol + nj * 16]);
                ldsm4t(bl[nj], &Bl[brow * BKS + bcol + nj * 16]);
            }
            #pragma unroll
            for (int mi = 0; mi < 4; mi++)
                #pragma unroll
                for (int nj = 0; nj < 2; nj++)
                    #pragma unroll
                    for (int h2 = 0; h2 < 2; h2++) {
                        float* c = acc[mi][nj * 2 + h2];
                        mma16h(c, ah[mi], &bh[nj][h2 * 2]);
                        mma16h(c, ah[mi], &bl[nj][h2 * 2]);
                    }
        }
        __syncthreads();
        if (it + 2 < NT) { fill(it & 1, (it + 2) * 32); CP_COMMIT(); }
    }

    if (z < 2) {
        __half* OutH = (z == 0) ? g_Qf : g_Kf;
        #pragma unroll
        for (int ni = 0; ni < 4; ni++) {
            int n = j0 + wn * 32 + ni * 8 + 2 * t;    // even
            int h = n >> 6, d = n & 63;
            int pos = (d & 0x30) | ((d & 6) << 1) | ((d & 8) >> 2);
            float s = (z == 0) ? (ent[h] * 0.125f * LOG2E * INV32) : INV32;
            #pragma unroll
            for (int mi = 0; mi < 4; mi++) {
                int m = m0 + wm * 64 + mi * 16 + g;
                int l = m & (LL - 1);
                size_t base = ((size_t)(b * NH + h) * LL + l) * HDIM + pos;
                *(__half2*)&OutH[base] =
                    __floats2half2_rn(acc[mi][ni][0] * s, acc[mi][ni][1] * s);
                *(__half2*)&OutH[base + 8 * HDIM] =
                    __floats2half2_rn(acc[mi][ni][2] * s, acc[mi][ni][3] * s);
            }
        }
    } else {
        #pragma unroll
        for (int ni = 0; ni < 4; ni++) {
            int n = j0 + wn * 32 + ni * 8 + 2 * t;
            int h = n >> 6, d = n & 63;               // d even
            #pragma unroll
            for (int mi = 0; mi < 4; mi++) {
                int m = m0 + wm * 64 + mi * 16 + g;
                int l = m & (LL - 1);
                int l6 = l & 63;
                int pos = (l6 & 0x30) | ((l6 & 6) << 1) | ((l6 & 8) >> 2) | (l6 & 1);
                size_t base = (size_t)(b * NH + h) * LL * HDIM
                            + (size_t)(l >> 6) * 4096 + (size_t)d * 64;
                g_Vt[base + pos]          = __float2half_rn(acc[mi][ni][0] * INV32);
                g_Vt[base + 64 + pos]     = __float2half_rn(acc[mi][ni][1] * INV32);
                g_Vt[base + pos + 2]      = __float2half_rn(acc[mi][ni][2] * INV32);
                g_Vt[base + 64 + pos + 2] = __float2half_rn(acc[mi][ni][3] * INV32);
            }
        }
    }
}

// ============================================================================
// Kernel 3: flash attention v7 — fp16 mma; softmax datapath restructured:
//  * ex2.approx.f16x2 on packed (s - max) pairs (halves MUFU; output IS the
//    P A-fragment)
//  * l carried as a 65th V dim: ones-row mma accumulates row sums into a
//    C-fragment 'oe', rescaled by the same online correction as O.
// smem: K 2x64x80 + V 2x72x80 halfs = 43520 B.
// ============================================================================
#define FQS   80
#define KBUF  5120
#define VBUF  5760
#define VBASE 10240
#define FL7_SMEM ((2 * KBUF + 2 * VBUF) * 2)

__global__ __launch_bounds__(256, 1) void flash7()
{
    extern __shared__ __half hsm[];
    const int tid = threadIdx.x, lane = tid & 31, g = lane >> 2, t = lane & 3;
    const int warp = tid >> 5;

    const int bh = blockIdx.y;
    const size_t head = (size_t)bh * LL * HDIM;
    const int q0 = blockIdx.x * 256 + warp * 32;

    uint32_t qa[2][4][4];
    #pragma unroll
    for (int mt = 0; mt < 2; mt++)
        #pragma unroll
        for (int kc = 0; kc < 4; kc++) {
            const __half* qp = &g_Qf[head + (size_t)(q0 + mt * 16 + g) * HDIM + kc * 16 + t * 4];
            uint2 u0 = *(const uint2*)qp;
            uint2 u1 = *(const uint2*)(qp + 8 * HDIM);
            qa[mt][kc][0] = u0.x; qa[mt][kc][1] = u1.x;
            qa[mt][kc][2] = u0.y; qa[mt][kc][3] = u1.y;
        }

    const int frow = tid >> 2;
    const int fch  = (tid & 3) * 2;

    float o[2][8][4] = {};
    float oe[2][4] = {};   // l rides here (ones-row mma output)
    float mv[2][2] = {{-1e30f, -1e30f}, {-1e30f, -1e30f}};

    // ones row (Vt row 64) + zero rows 65-71, both buffers; cp.async never
    // touches rows >= 64, so these persist for the whole kernel.
    for (int i = tid; i < 2 * 8 * FQS; i += 256) {
        int bi = i / (8 * FQS), rc = i % (8 * FQS);
        int r = rc / FQS, c = rc % FQS;
        hsm[VBASE + bi * VBUF + (64 + r) * FQS + c] =
            __float2half(r == 0 ? 1.0f : 0.0f);
    }

    {
        const __half* Ks = g_Kf + head;
        const __half* Vs = g_Vt + head;
        #pragma unroll
        for (int i = 0; i < 2; i++) {
            int ch = fch + i;
            cpa16(&hsm[frow * FQS + ch * 8],         &Ks[frow * 64 + ch * 8]);
            cpa16(&hsm[VBASE + frow * FQS + ch * 8], &Vs[frow * 64 + ch * 8]);
        }
    }
    CP_COMMIT();

    for (int it = 0; it < LL / 64; ++it) {
        CP_WAIT0();
        __syncthreads();
        if (it + 1 < LL / 64) {
            const __half* Ks = g_Kf + head + (size_t)(it + 1) * 4096;
            const __half* Vs = g_Vt + head + (size_t)(it + 1) * 4096;
            __half* Kd = hsm + ((it + 1) & 1) * KBUF;
            __half* Vd = hsm + VBASE + ((it + 1) & 1) * VBUF;
            #pragma unroll
            for (int i = 0; i < 2; i++) {
                int ch = fch + i;
                cpa16(&Kd[frow * FQS + ch * 8], &Ks[frow * 64 + ch * 8]);
                cpa16(&Vd[frow * FQS + ch * 8], &Vs[frow * 64 + ch * 8]);
            }
            CP_COMMIT();
        }
        const __half* Ksm = hsm + (it & 1) * KBUF;
        const __half* Vsm = hsm + VBASE + (it & 1) * VBUF;

        // S = Q @ K^T : 32 x 64 per warp
        float s[2][8][4] = {};
        #pragma unroll
        for (int kc = 0; kc < 4; kc++) {
            #pragma unroll
            for (int nt = 0; nt < 8; nt++) {
                uint2 bv = *(const uint2*)&Ksm[(nt * 8 + g) * FQS + kc * 16 + t * 4];
                uint32_t bf[2] = { bv.x, bv.y };
                mma16h(s[0][nt], qa[0][kc], bf);
                mma16h(s[1][nt], qa[1][kc], bf);
            }
        }

        // online softmax (base-2); P fragments produced by f16x2 ex2
        uint32_t pr[2][8][2];
        #pragma unroll
        for (int mt = 0; mt < 2; mt++) {
            float rmax0 = -1e30f, rmax1 = -1e30f;
            #pragma unroll
            for (int nt = 0; nt < 8; nt++) {
                rmax0 = fmaxf(rmax0, fmaxf(s[mt][nt][0], s[mt][nt][1]));
                rmax1 = fmaxf(rmax1, fmaxf(s[mt][nt][2], s[mt][nt][3]));
            }
            rmax0 = fmaxf(rmax0, __shfl_xor_sync(0xffffffffu, rmax0, 1));
            rmax0 = fmaxf(rmax0, __shfl_xor_sync(0xffffffffu, rmax0, 2));
            rmax1 = fmaxf(rmax1, __shfl_xor_sync(0xffffffffu, rmax1, 1));
            rmax1 = fmaxf(rmax1, __shfl_xor_sync(0xffffffffu, rmax1, 2));

            float nm0 = fmaxf(mv[mt][0], rmax0), nm1 = fmaxf(mv[mt][1], rmax1);
            float c0 = ex2(mv[mt][0] - nm0), c1 = ex2(mv[mt][1] - nm1);
            mv[mt][0] = nm0; mv[mt][1] = nm1;

            #pragma unroll
            for (int nt = 0; nt < 8; nt++) {
                o[mt][nt][0] *= c0; o[mt][nt][1] *= c0;
                o[mt][nt][2] *= c1; o[mt][nt][3] *= c1;
            }
            oe[mt][0] *= c0; oe[mt][1] *= c0;
            oe[mt][2] *= c1; oe[mt][3] *= c1;

            #pragma unroll
            for (int nt = 0; nt < 8; nt++) {
                pr[mt][nt][0] = ex2h2(s[mt][nt][0] - nm0, s[mt][nt][1] - nm0);
                pr[mt][nt][1] = ex2h2(s[mt][nt][2] - nm1, s[mt][nt][3] - nm1);
            }
        }

        // O += P @ V ; l += P @ ones (Vt row 64)
        #pragma unroll
        for (int kc = 0; kc < 4; kc++) {
            uint32_t pa[2][4];
            #pragma unroll
            for (int mt = 0; mt < 2; mt++) {
                pa[mt][0] = pr[mt][2 * kc][0];
                pa[mt][1] = pr[mt][2 * kc][1];
                pa[mt][2] = pr[mt][2 * kc + 1][0];
                pa[mt][3] = pr[mt][2 * kc + 1][1];
            }
            #pragma unroll
            for (int nt = 0; nt < 8; nt++) {
                uint2 bv = *(const uint2*)&Vsm[(nt * 8 + g) * FQS + kc * 16 + t * 4];
                uint32_t bf[2] = { bv.x, bv.y };
                mma16h(o[0][nt], pa[0], bf);
                mma16h(o[1][nt], pa[1], bf);
            }
            uint2 ev = *(const uint2*)&Vsm[(64 + g) * FQS + kc * 16 + t * 4];
            uint32_t ef[2] = { ev.x, ev.y };
            mma16h(oe[0], pa[0], ef);
            mma16h(oe[1], pa[1], ef);
        }
    }

    const int b = bh >> 4, h = bh & 15;
    #pragma unroll
    for (int mt = 0; mt < 2; mt++) {
        float l0 = __shfl_sync(0xffffffffu, oe[mt][0], lane & 28);
        float l1 = __shfl_sync(0xffffffffu, oe[mt][2], lane & 28);
        float inv0 = 1.0f / l0, inv1 = 1.0f / l1;
        size_t ob0 = ((size_t)b * LL + q0 + mt * 16 + g) * DD + h * HDIM;
        size_t ob1 = ((size_t)b * LL + q0 + mt * 16 + 8 + g) * DD + h * HDIM;
        #pragma unroll
        for (int nt = 0; nt < 8; nt++) {
            int col = nt * 8 + 2 * t;
            *(__half2*)&g_Of[ob0 + col] =
                __floats2half2_rn(o[mt][nt][0] * inv0, o[mt][nt][1] * inv0);
            *(__half2*)&g_Of[ob1 + col] =
                __floats2half2_rn(o[mt][nt][2] * inv1, o[mt][nt][3] * inv1);
        }
    }
}

// ============================================================================
// Kernel 4: Y = O @ (32*Wo)^T / 32 (NT), fp16x2, cp.async double-buffered,
// 2 CTAs/SM.
// ============================================================================
#define OBUF (3 * 5120)
#define OUT_SMEM (2 * OBUF * 2)

__global__ __launch_bounds__(256, 2) void out_f2(float* __restrict__ Y)
{
    extern __shared__ __half osm[];
    const int tid = threadIdx.x, lane = tid & 31, g = lane >> 2, t = lane & 3;
    const int warp = tid >> 5, wm = warp >> 2, wn = warp & 3;
    const int m0 = blockIdx.y * 128, j0 = blockIdx.x * 128;

    auto fill = [&](int bi, int kt) {
        __half* A  = osm + bi * OBUF;
        __half* Bh = A + 5120;
        __half* Bl = Bh + 5120;
        #pragma unroll
        for (int i = 0; i < 2; i++) {
            int idx = tid + i * 256;
            int row = idx >> 2, ch = idx & 3;
            cpa16(&A[row * AKS + ch * 8], &g_Of[(size_t)(m0 + row) * DD + kt + ch * 8]);
            size_t src = (size_t)(j0 + row) * DD + kt + ch * 8;
            cpa16(&Bh[row * AKS + ch * 8], &g_Woh[src]);
            cpa16(&Bl[row * AKS + ch * 8], &g_Wol[src]);
        }
    };

    float acc[4][4][4] = {};

    fill(0, 0);  CP_COMMIT();
    fill(1, 32); CP_COMMIT();

    const int NT = DD / 32;
    for (int it = 0; it < NT; ++it) {
        if (it == NT - 1) { CP_WAIT0(); } else { CP_WAIT1(); }
        __syncthreads();
        const __half* A  = osm + (it & 1) * OBUF;
        const __half* Bh = A + 5120;
        const __half* Bl = Bh + 5120;
        #pragma unroll
        for (int ks = 0; ks < 2; ks++) {
            const int kk0 = ks * 16;
            uint32_t ah[4][4], bh[2][4], bl[2][4];
            const int arow = wm * 64 + (lane & 15);
            const int ak   = kk0 + (lane >> 4) * 8;
            #pragma unroll
            for (int mi = 0; mi < 4; mi++)
                ldsm4(ah[mi], &A[(arow + mi * 16) * AKS + ak]);
            const int brow = wn * 32 + (lane & 7) + ((lane >> 4) & 1) * 8;
            const int bk   = kk0 + ((lane >> 3) & 1) * 8;
            #pragma unroll
            for (int nj = 0; nj < 2; nj++) {
                ldsm4(bh[nj], &Bh[(brow + nj * 16) * AKS + bk]);
                ldsm4(bl[nj], &Bl[(brow + nj * 16) * AKS + bk]);
            }
            #pragma unroll
            for (int mi = 0; mi < 4; mi++)
                #pragma unroll
                for (int nj = 0; nj < 2; nj++)
                    #pragma unroll
                    for (int h2 = 0; h2 < 2; h2++) {
                        float* c = acc[mi][nj * 2 + h2];
                        mma16h(c, ah[mi], &bh[nj][h2 * 2]);
                        mma16h(c, ah[mi], &bl[nj][h2 * 2]);
                    }
        }
        __syncthreads();
        if (it + 2 < NT) { fill(it & 1, (it + 2) * 32); CP_COMMIT(); }
    }

    #pragma unroll
    for (int mi = 0; mi < 4; mi++) {
        int row0 = m0 + wm * 64 + mi * 16 + g;
        #pragma unroll
        for (int ni = 0; ni < 4; ni++) {
            int col = j0 + wn * 32 + ni * 8 + 2 * t;
            *(float2*)&Y[(size_t)row0 * DD + col] =
                make_float2(acc[mi][ni][0] * INV32, acc[mi][ni][1] * INV32);
            *(float2*)&Y[(size_t)(row0 + 8) * DD + col] =
                make_float2(acc[mi][ni][2] * INV32, acc[mi][ni][3] * INV32);
        }
    }
}

// ============================================================================
// launch
// Inputs: 0=inputs 1=rotation 2=entangle 3=Wq 4=Wk 5=Wv 6=Wo; out (B,L,D) fp32
// ============================================================================
extern "C" void kernel_launch(void* const* d_in, const int* in_sizes, int n_in,
                              void* d_out, int out_size)
{
    const float* X   = (const float*)d_in[0];
    const float* R   = (const float*)d_in[1];
    const float* ent = (const float*)d_in[2];
    const float* Wq  = (const float*)d_in[3];
    const float* Wk  = (const float*)d_in[4];
    const float* Wv  = (const float*)d_in[5];
    const float* Wo  = (const float*)d_in[6];
    float* Y = (float*)d_out;

    cudaFuncSetAttribute(flash7, cudaFuncAttributeMaxDynamicSharedMemorySize, FL7_SMEM);
    cudaFuncSetAttribute(qkv_f2, cudaFuncAttributeMaxDynamicSharedMemorySize, QKV_SMEM);
    cudaFuncSetAttribute(out_f2, cudaFuncAttributeMaxDynamicSharedMemorySize, OUT_SMEM);

    convert_inputs<<<1184, 256>>>(X, Wo);
    combine_b3<<<dim3(8, 8, 3), 256>>>(Wq, Wk, Wv, R);
    qkv_f2<<<dim3(8, MTOK / 128, 3), 256, QKV_SMEM>>>(ent);
    flash7<<<dim3(LL / 256, BB * NH), 256, FL7_SMEM>>>();
    out_f2<<<dim3(8, MTOK / 128), 256, OUT_SMEM>>>(Y);
}

// round 15
// speedup vs baseline: 1.8810x; 1.0319x over previous
#include <cuda_runtime.h>
#include <cuda_bf16.h>
#include <cuda_fp16.h>
#include <stdint.h>
#include <math.h>

#define DD   1024
#define NH   16
#define HDIM 64
#define BB   2
#define LL   2048
#define MTOK (BB*LL)   // 4096

#define AKS 40     // legacy [row][k32] stride (combine staging uses BKS only)
#define AK64 72    // [row][k64] 16-bit smem stride (64 + 8)
#define BKS 136    // [k][n]  16-bit smem stride (128 + 8)

#define LOG2E  1.4426950408889634f
#define INV32  0.03125f

// ---------------- scratch (device globals; no allocations allowed) ----------
__device__ __half g_Wch[3][DD*DD], g_Wcl[3][DD*DD];  // 32*(W^T@R) fp16 split [k][n]
__device__ __half g_Xf[MTOK*DD];                     // X fp16 [m][k]
__device__ __half g_Woh[DD*DD],  g_Wol[DD*DD];       // 32*Wo fp16 split [n][k]
__device__ __half g_Of[MTOK*DD];                     // attn out fp16 (B,L,D)
// fp16 attention operands, mma-fragment-native layouts:
// Q,K: [b][h][l][perm(d)]; Q pre-scaled by ent/8*log2e. V: [b][h][l>>6][d][perm(l&63)]
__device__ __half g_Qf[BB*NH*LL*HDIM];
__device__ __half g_Kf[BB*NH*LL*HDIM];
__device__ __half g_Vt[BB*NH*LL*HDIM];

// ---------------- helpers ----------------------------------------------------
__device__ __forceinline__ float ex2(float x) {
    float y;
    asm("ex2.approx.f32 %0, %1;" : "=f"(y) : "f"(x));
    return y;
}
__device__ __forceinline__ uint32_t ex2h2(float a, float b) {
    __half2 h = __floats2half2_rn(a, b);
    uint32_t r;
    asm("ex2.approx.f16x2 %0, %1;" : "=r"(r) : "r"(*(uint32_t*)&h));
    return r;
}

__device__ __forceinline__ void mma16(float* d, const uint32_t* a, const uint32_t* b) {
    asm volatile(
        "mma.sync.aligned.m16n8k16.row.col.f32.bf16.bf16.f32 "
        "{%0,%1,%2,%3}, {%4,%5,%6,%7}, {%8,%9}, {%0,%1,%2,%3};"
        : "+f"(d[0]), "+f"(d[1]), "+f"(d[2]), "+f"(d[3])
        : "r"(a[0]), "r"(a[1]), "r"(a[2]), "r"(a[3]), "r"(b[0]), "r"(b[1]));
}
__device__ __forceinline__ void mma16h(float* d, const uint32_t* a, const uint32_t* b) {
    asm volatile(
        "mma.sync.aligned.m16n8k16.row.col.f32.f16.f16.f32 "
        "{%0,%1,%2,%3}, {%4,%5,%6,%7}, {%8,%9}, {%0,%1,%2,%3};"
        : "+f"(d[0]), "+f"(d[1]), "+f"(d[2]), "+f"(d[3])
        : "r"(a[0]), "r"(a[1]), "r"(a[2]), "r"(a[3]), "r"(b[0]), "r"(b[1]));
}

__device__ __forceinline__ void ldsm4(uint32_t* r, const void* p) {
    uint32_t a = (uint32_t)__cvta_generic_to_shared(p);
    asm volatile("ldmatrix.sync.aligned.m8n8.x4.shared.b16 {%0,%1,%2,%3}, [%4];"
        : "=r"(r[0]), "=r"(r[1]), "=r"(r[2]), "=r"(r[3]) : "r"(a));
}
__device__ __forceinline__ void ldsm4t(uint32_t* r, const void* p) {
    uint32_t a = (uint32_t)__cvta_generic_to_shared(p);
    asm volatile("ldmatrix.sync.aligned.m8n8.x4.trans.shared.b16 {%0,%1,%2,%3}, [%4];"
        : "=r"(r[0]), "=r"(r[1]), "=r"(r[2]), "=r"(r[3]) : "r"(a));
}

__device__ __forceinline__ void cpa16(void* smem, const void* gmem) {
    uint32_t s = (uint32_t)__cvta_generic_to_shared(smem);
    asm volatile("cp.async.cg.shared.global [%0], [%1], 16;" :: "r"(s), "l"(gmem) : "memory");
}
#define CP_COMMIT() asm volatile("cp.async.commit_group;" ::: "memory")
#define CP_WAIT0()  asm volatile("cp.async.wait_group 0;" ::: "memory")
#define CP_WAIT1()  asm volatile("cp.async.wait_group 1;" ::: "memory")

// split 4 fp32 -> bf16 hi/lo (combine's smem staging)
__device__ __forceinline__ void sst4(__nv_bfloat16* hp, __nv_bfloat16* lp, float4 v) {
    __nv_bfloat16 hx = __float2bfloat16_rn(v.x), hy = __float2bfloat16_rn(v.y);
    __nv_bfloat16 hz = __float2bfloat16_rn(v.z), hw = __float2bfloat16_rn(v.w);
    __nv_bfloat162* H = (__nv_bfloat162*)hp;
    H[0] = __halves2bfloat162(hx, hy);
    H[1] = __halves2bfloat162(hz, hw);
    __nv_bfloat162* L = (__nv_bfloat162*)lp;
    L[0] = __halves2bfloat162(__float2bfloat16_rn(v.x - __bfloat162float(hx)),
                              __float2bfloat16_rn(v.y - __bfloat162float(hy)));
    L[1] = __halves2bfloat162(__float2bfloat16_rn(v.z - __bfloat162float(hz)),
                              __float2bfloat16_rn(v.w - __bfloat162float(hw)));
}

// split scalar fp32 -> fp16 hi/lo
__device__ __forceinline__ void sp1h(__half* ph, __half* pl, float v) {
    __half h = __float2half_rn(v);
    *ph = h;
    *pl = __float2half_rn(v - __half2float(h));
}

// ============================================================================
// Kernel 1: Wc[z] = W[z]^T @ R  (TN), bf16x3 (accurate); stores 32*Wc as fp16
// hi/lo [k][n]. FUSED PROLOGUE: converts X -> fp16 and Wo*32 -> fp16 hi/lo
// (grid-strided across all 192 CTAs; outputs are independent of this kernel's
// own inputs, consumers run in later kernels).
// ============================================================================
__global__ __launch_bounds__(256) void combine_b3(
    const float* __restrict__ Wq, const float* __restrict__ Wk,
    const float* __restrict__ Wv, const float* __restrict__ R,
    const float* __restrict__ X, const float* __restrict__ Wo)
{
    const int tid = threadIdx.x;

    // ---- fused convert (X, Wo) ----
    {
        int cid = blockIdx.x + (blockIdx.y << 3) + (blockIdx.z << 6); // 0..191
        int i0 = cid * 256 + tid;
        int st = 192 * 256;
        for (int i = i0; i < MTOK * DD / 4; i += st) {
            float4 v = ((const float4*)X)[i];
            __half2* H = (__half2*)&g_Xf[i * 4];
            H[0] = __floats2half2_rn(v.x, v.y);
            H[1] = __floats2half2_rn(v.z, v.w);
        }
        for (int i = i0; i < DD * DD / 4; i += st) {
            float4 v = ((const float4*)Wo)[i];
            sp1h(&g_Woh[i * 4 + 0], &g_Wol[i * 4 + 0], v.x * 32.0f);
            sp1h(&g_Woh[i * 4 + 1], &g_Wol[i * 4 + 1], v.y * 32.0f);
            sp1h(&g_Woh[i * 4 + 2], &g_Wol[i * 4 + 2], v.z * 32.0f);
            sp1h(&g_Woh[i * 4 + 3], &g_Wol[i * 4 + 3], v.w * 32.0f);
        }
    }

    const int z = blockIdx.z;
    const float* W = (z == 0) ? Wq : ((z == 1) ? Wk : Wv);

    __shared__ __align__(16) __nv_bfloat16 Ath[32][BKS], Atl[32][BKS];
    __shared__ __align__(16) __nv_bfloat16 Bth[32][BKS], Btl[32][BKS];

    const int lane = tid & 31, g = lane >> 2, t = lane & 3;
    const int warp = tid >> 5, wm = warp >> 2, wn = warp & 3;
    const int i0 = blockIdx.y * 128, j0 = blockIdx.x * 128;
    const int kr = tid >> 5, cc = (tid & 31) * 4;

    float acc[4][4][4] = {};
    float4 pa[4], pb[4];
    #pragma unroll
    for (int r = 0; r < 4; r++) {
        pa[r] = *(const float4*)&W[(size_t)(kr + r * 8) * DD + i0 + cc];
        pb[r] = *(const float4*)&R[(size_t)(kr + r * 8) * DD + j0 + cc];
    }

    for (int kt = 0; kt < DD; kt += 32) {
        #pragma unroll
        for (int r = 0; r < 4; r++) {
            sst4(&Ath[kr + r * 8][cc], &Atl[kr + r * 8][cc], pa[r]);
            sst4(&Bth[kr + r * 8][cc], &Btl[kr + r * 8][cc], pb[r]);
        }
        __syncthreads();
        if (kt + 32 < DD) {
            #pragma unroll
            for (int r = 0; r < 4; r++) {
                pa[r] = *(const float4*)&W[(size_t)(kt + 32 + kr + r * 8) * DD + i0 + cc];
                pb[r] = *(const float4*)&R[(size_t)(kt + 32 + kr + r * 8) * DD + j0 + cc];
            }
        }
        #pragma unroll
        for (int ks = 0; ks < 2; ks++) {
            const int kk0 = ks * 16;
            uint32_t ah[4][4], al[4][4], bh[2][4], bl[2][4];
            const int arow = kk0 + (lane >> 4) * 8 + (lane & 7);
            const int acol = wm * 64 + ((lane >> 3) & 1) * 8;
            #pragma unroll
            for (int mi = 0; mi < 4; mi++) {
                ldsm4t(ah[mi], &Ath[arow][acol + mi * 16]);
                ldsm4t(al[mi], &Atl[arow][acol + mi * 16]);
            }
            const int brow = kk0 + (lane & 7) + ((lane >> 3) & 1) * 8;
            const int bcol = wn * 32 + (lane >> 4) * 8;
            #pragma unroll
            for (int nj = 0; nj < 2; nj++) {
                ldsm4t(bh[nj], &Bth[brow][bcol + nj * 16]);
                ldsm4t(bl[nj], &Btl[brow][bcol + nj * 16]);
            }
            #pragma unroll
            for (int mi = 0; mi < 4; mi++)
                #pragma unroll
                for (int nj = 0; nj < 2; nj++)
                    #pragma unroll
                    for (int h2 = 0; h2 < 2; h2++) {
                        float* c = acc[mi][nj * 2 + h2];
                        mma16(c, ah[mi], &bh[nj][h2 * 2]);
                        mma16(c, ah[mi], &bl[nj][h2 * 2]);
                        mma16(c, al[mi], &bh[nj][h2 * 2]);
                    }
        }
        __syncthreads();
    }

    __half* Ch = g_Wch[z];
    __half* Cl = g_Wcl[z];
    #pragma unroll
    for (int mi = 0; mi < 4; mi++) {
        int row0 = i0 + wm * 64 + mi * 16 + g;      // k index of Wc
        #pragma unroll
        for (int ni = 0; ni < 4; ni++) {
            int col = j0 + wn * 32 + ni * 8 + 2 * t; // n index of Wc
            sp1h(&Ch[(size_t)row0 * DD + col],     &Cl[(size_t)row0 * DD + col],
                 acc[mi][ni][0] * 32.0f);
            sp1h(&Ch[(size_t)row0 * DD + col + 1], &Cl[(size_t)row0 * DD + col + 1],
                 acc[mi][ni][1] * 32.0f);
            sp1h(&Ch[(size_t)(row0 + 8) * DD + col],     &Cl[(size_t)(row0 + 8) * DD + col],
                 acc[mi][ni][2] * 32.0f);
            sp1h(&Ch[(size_t)(row0 + 8) * DD + col + 1], &Cl[(size_t)(row0 + 8) * DD + col + 1],
                 acc[mi][ni][3] * 32.0f);
        }
    }
}

// ============================================================================
// Kernel 2: P = X @ (32*Wc[z]) (NN), fp16x2, K64 double-buffered cp.async,
// 2 CTAs/SM. Scatter into fp16 flash layouts (1/32 folded into scales).
// buffer: A 128x72 + Bh 64x136 + Bl 64x136 = 26624 halfs = 53.25 KB
// ============================================================================
#define QA_BUF 9216
#define QB_BUF 8704
#define QBUF   (QA_BUF + 2 * QB_BUF)
#define QKV_SMEM (2 * QBUF * 2)

__global__ __launch_bounds__(256, 2) void qkv_f2(const float* __restrict__ ent)
{
    extern __shared__ __half qsm[];
    const int z = blockIdx.z;
    const __half* Wh = g_Wch[z];
    const __half* Wl = g_Wcl[z];

    const int tid = threadIdx.x, lane = tid & 31, g = lane >> 2, t = lane & 3;
    const int warp = tid >> 5, wm = warp >> 2, wn = warp & 3;
    const int m0 = blockIdx.y * 128, j0 = blockIdx.x * 128;
    const int b = m0 >> 11;

    auto fill = [&](int bi, int kt) {
        __half* A  = qsm + bi * QBUF;
        __half* Bh = A + QA_BUF;
        __half* Bl = Bh + QB_BUF;
        #pragma unroll
        for (int i = 0; i < 4; i++) {
            int idx = tid + i * 256;
            int row = idx >> 3, ch = idx & 7;       // A: 128 rows x 64 cols
            cpa16(&A[row * AK64 + ch * 8], &g_Xf[(size_t)(m0 + row) * DD + kt + ch * 8]);
        }
        #pragma unroll
        for (int i = 0; i < 4; i++) {
            int idx = tid + i * 256;
            int row = idx >> 4, ch = idx & 15;      // B: 64 k-rows x 128 cols
            size_t src = (size_t)(kt + row) * DD + j0 + ch * 8;
            cpa16(&Bh[row * BKS + ch * 8], &Wh[src]);
            cpa16(&Bl[row * BKS + ch * 8], &Wl[src]);
        }
    };

    float acc[4][4][4] = {};

    fill(0, 0);  CP_COMMIT();
    fill(1, 64); CP_COMMIT();

    const int NT = DD / 64;   // 16
    for (int it = 0; it < NT; ++it) {
        if (it == NT - 1) { CP_WAIT0(); } else { CP_WAIT1(); }
        __syncthreads();
        const __half* A  = qsm + (it & 1) * QBUF;
        const __half* Bh = A + QA_BUF;
        const __half* Bl = Bh + QB_BUF;
        #pragma unroll
        for (int ks = 0; ks < 4; ks++) {
            const int kk0 = ks * 16;
            uint32_t ah[4][4], bh[2][4], bl[2][4];
            const int arow = wm * 64 + (lane & 15);
            const int ak   = kk0 + (lane >> 4) * 8;
            #pragma unroll
            for (int mi = 0; mi < 4; mi++)
                ldsm4(ah[mi], &A[(arow + mi * 16) * AK64 + ak]);
            const int brow = kk0 + (lane & 7) + ((lane >> 3) & 1) * 8;
            const int bcol = wn * 32 + (lane >> 4) * 8;
            #pragma unroll
            for (int nj = 0; nj < 2; nj++) {
                ldsm4t(bh[nj], &Bh[brow * BKS + bcol + nj * 16]);
                ldsm4t(bl[nj], &Bl[brow * BKS + bcol + nj * 16]);
            }
            #pragma unroll
            for (int mi = 0; mi < 4; mi++)
                #pragma unroll
                for (int nj = 0; nj < 2; nj++)
                    #pragma unroll
                    for (int h2 = 0; h2 < 2; h2++) {
                        float* c = acc[mi][nj * 2 + h2];
                        mma16h(c, ah[mi], &bh[nj][h2 * 2]);
                        mma16h(c, ah[mi], &bl[nj][h2 * 2]);
                    }
        }
        __syncthreads();
        if (it + 2 < NT) { fill(it & 1, (it + 2) * 64); CP_COMMIT(); }
    }

    if (z < 2) {
        __half* OutH = (z == 0) ? g_Qf : g_Kf;
        #pragma unroll
        for (int ni = 0; ni < 4; ni++) {
            int n = j0 + wn * 32 + ni * 8 + 2 * t;    // even
            int h = n >> 6, d = n & 63;
            int pos = (d & 0x30) | ((d & 6) << 1) | ((d & 8) >> 2);
            float s = (z == 0) ? (ent[h] * 0.125f * LOG2E * INV32) : INV32;
            #pragma unroll
            for (int mi = 0; mi < 4; mi++) {
                int m = m0 + wm * 64 + mi * 16 + g;
                int l = m & (LL - 1);
                size_t base = ((size_t)(b * NH + h) * LL + l) * HDIM + pos;
                *(__half2*)&OutH[base] =
                    __floats2half2_rn(acc[mi][ni][0] * s, acc[mi][ni][1] * s);
                *(__half2*)&OutH[base + 8 * HDIM] =
                    __floats2half2_rn(acc[mi][ni][2] * s, acc[mi][ni][3] * s);
            }
        }
    } else {
        #pragma unroll
        for (int ni = 0; ni < 4; ni++) {
            int n = j0 + wn * 32 + ni * 8 + 2 * t;
            int h = n >> 6, d = n & 63;               // d even
            #pragma unroll
            for (int mi = 0; mi < 4; mi++) {
                int m = m0 + wm * 64 + mi * 16 + g;
                int l = m & (LL - 1);
                int l6 = l & 63;
                int pos = (l6 & 0x30) | ((l6 & 6) << 1) | ((l6 & 8) >> 2) | (l6 & 1);
                size_t base = (size_t)(b * NH + h) * LL * HDIM
                            + (size_t)(l >> 6) * 4096 + (size_t)d * 64;
                g_Vt[base + pos]          = __float2half_rn(acc[mi][ni][0] * INV32);
                g_Vt[base + 64 + pos]     = __float2half_rn(acc[mi][ni][1] * INV32);
                g_Vt[base + pos + 2]      = __float2half_rn(acc[mi][ni][2] * INV32);
                g_Vt[base + 64 + pos + 2] = __float2half_rn(acc[mi][ni][3] * INV32);
            }
        }
    }
}

// ============================================================================
// Kernel 3: flash attention v7 — fp16 mma; f16x2 ex2 softmax; l carried as a
// 65th V dim (ones-row mma). Unchanged from R14.
// smem: K 2x64x80 + V 2x72x80 halfs = 43520 B.
// ============================================================================
#define FQS   80
#define KBUF  5120
#define VBUF  5760
#define VBASE 10240
#define FL7_SMEM ((2 * KBUF + 2 * VBUF) * 2)

__global__ __launch_bounds__(256, 1) void flash7()
{
    extern __shared__ __half hsm[];
    const int tid = threadIdx.x, lane = tid & 31, g = lane >> 2, t = lane & 3;
    const int warp = tid >> 5;

    const int bh = blockIdx.y;
    const size_t head = (size_t)bh * LL * HDIM;
    const int q0 = blockIdx.x * 256 + warp * 32;

    uint32_t qa[2][4][4];
    #pragma unroll
    for (int mt = 0; mt < 2; mt++)
        #pragma unroll
        for (int kc = 0; kc < 4; kc++) {
            const __half* qp = &g_Qf[head + (size_t)(q0 + mt * 16 + g) * HDIM + kc * 16 + t * 4];
            uint2 u0 = *(const uint2*)qp;
            uint2 u1 = *(const uint2*)(qp + 8 * HDIM);
            qa[mt][kc][0] = u0.x; qa[mt][kc][1] = u1.x;
            qa[mt][kc][2] = u0.y; qa[mt][kc][3] = u1.y;
        }

    const int frow = tid >> 2;
    const int fch  = (tid & 3) * 2;

    float o[2][8][4] = {};
    float oe[2][4] = {};   // l rides here (ones-row mma output)
    float mv[2][2] = {{-1e30f, -1e30f}, {-1e30f, -1e30f}};

    for (int i = tid; i < 2 * 8 * FQS; i += 256) {
        int bi = i / (8 * FQS), rc = i % (8 * FQS);
        int r = rc / FQS, c = rc % FQS;
        hsm[VBASE + bi * VBUF + (64 + r) * FQS + c] =
            __float2half(r == 0 ? 1.0f : 0.0f);
    }

    {
        const __half* Ks = g_Kf + head;
        const __half* Vs = g_Vt + head;
        #pragma unroll
        for (int i = 0; i < 2; i++) {
            int ch = fch + i;
            cpa16(&hsm[frow * FQS + ch * 8],         &Ks[frow * 64 + ch * 8]);
            cpa16(&hsm[VBASE + frow * FQS + ch * 8], &Vs[frow * 64 + ch * 8]);
        }
    }
    CP_COMMIT();

    for (int it = 0; it < LL / 64; ++it) {
        CP_WAIT0();
        __syncthreads();
        if (it + 1 < LL / 64) {
            const __half* Ks = g_Kf + head + (size_t)(it + 1) * 4096;
            const __half* Vs = g_Vt + head + (size_t)(it + 1) * 4096;
            __half* Kd = hsm + ((it + 1) & 1) * KBUF;
            __half* Vd = hsm + VBASE + ((it + 1) & 1) * VBUF;
            #pragma unroll
            for (int i = 0; i < 2; i++) {
                int ch = fch + i;
                cpa16(&Kd[frow * FQS + ch * 8], &Ks[frow * 64 + ch * 8]);
                cpa16(&Vd[frow * FQS + ch * 8], &Vs[frow * 64 + ch * 8]);
            }
            CP_COMMIT();
        }
        const __half* Ksm = hsm + (it & 1) * KBUF;
        const __half* Vsm = hsm + VBASE + (it & 1) * VBUF;

        float s[2][8][4] = {};
        #pragma unroll
        for (int kc = 0; kc < 4; kc++) {
            #pragma unroll
            for (int nt = 0; nt < 8; nt++) {
                uint2 bv = *(const uint2*)&Ksm[(nt * 8 + g) * FQS + kc * 16 + t * 4];
                uint32_t bf[2] = { bv.x, bv.y };
                mma16h(s[0][nt], qa[0][kc], bf);
                mma16h(s[1][nt], qa[1][kc], bf);
            }
        }

        uint32_t pr[2][8][2];
        #pragma unroll
        for (int mt = 0; mt < 2; mt++) {
            float rmax0 = -1e30f, rmax1 = -1e30f;
            #pragma unroll
            for (int nt = 0; nt < 8; nt++) {
                rmax0 = fmaxf(rmax0, fmaxf(s[mt][nt][0], s[mt][nt][1]));
                rmax1 = fmaxf(rmax1, fmaxf(s[mt][nt][2], s[mt][nt][3]));
            }
            rmax0 = fmaxf(rmax0, __shfl_xor_sync(0xffffffffu, rmax0, 1));
            rmax0 = fmaxf(rmax0, __shfl_xor_sync(0xffffffffu, rmax0, 2));
            rmax1 = fmaxf(rmax1, __shfl_xor_sync(0xffffffffu, rmax1, 1));
            rmax1 = fmaxf(rmax1, __shfl_xor_sync(0xffffffffu, rmax1, 2));

            float nm0 = fmaxf(mv[mt][0], rmax0), nm1 = fmaxf(mv[mt][1], rmax1);
            float c0 = ex2(mv[mt][0] - nm0), c1 = ex2(mv[mt][1] - nm1);
            mv[mt][0] = nm0; mv[mt][1] = nm1;

            #pragma unroll
            for (int nt = 0; nt < 8; nt++) {
                o[mt][nt][0] *= c0; o[mt][nt][1] *= c0;
                o[mt][nt][2] *= c1; o[mt][nt][3] *= c1;
            }
            oe[mt][0] *= c0; oe[mt][1] *= c0;
            oe[mt][2] *= c1; oe[mt][3] *= c1;

            #pragma unroll
            for (int nt = 0; nt < 8; nt++) {
                pr[mt][nt][0] = ex2h2(s[mt][nt][0] - nm0, s[mt][nt][1] - nm0);
                pr[mt][nt][1] = ex2h2(s[mt][nt][2] - nm1, s[mt][nt][3] - nm1);
            }
        }

        #pragma unroll
        for (int kc = 0; kc < 4; kc++) {
            uint32_t pa[2][4];
            #pragma unroll
            for (int mt = 0; mt < 2; mt++) {
                pa[mt][0] = pr[mt][2 * kc][0];
                pa[mt][1] = pr[mt][2 * kc][1];
                pa[mt][2] = pr[mt][2 * kc + 1][0];
                pa[mt][3] = pr[mt][2 * kc + 1][1];
            }
            #pragma unroll
            for (int nt = 0; nt < 8; nt++) {
                uint2 bv = *(const uint2*)&Vsm[(nt * 8 + g) * FQS + kc * 16 + t * 4];
                uint32_t bf[2] = { bv.x, bv.y };
                mma16h(o[0][nt], pa[0], bf);
                mma16h(o[1][nt], pa[1], bf);
            }
            uint2 ev = *(const uint2*)&Vsm[(64 + g) * FQS + kc * 16 + t * 4];
            uint32_t ef[2] = { ev.x, ev.y };
            mma16h(oe[0], pa[0], ef);
            mma16h(oe[1], pa[1], ef);
        }
    }

    const int b = bh >> 4, h = bh & 15;
    #pragma unroll
    for (int mt = 0; mt < 2; mt++) {
        float l0 = __shfl_sync(0xffffffffu, oe[mt][0], lane & 28);
        float l1 = __shfl_sync(0xffffffffu, oe[mt][2], lane & 28);
        float inv0 = 1.0f / l0, inv1 = 1.0f / l1;
        size_t ob0 = ((size_t)b * LL + q0 + mt * 16 + g) * DD + h * HDIM;
        size_t ob1 = ((size_t)b * LL + q0 + mt * 16 + 8 + g) * DD + h * HDIM;
        #pragma unroll
        for (int nt = 0; nt < 8; nt++) {
            int col = nt * 8 + 2 * t;
            *(__half2*)&g_Of[ob0 + col] =
                __floats2half2_rn(o[mt][nt][0] * inv0, o[mt][nt][1] * inv0);
            *(__half2*)&g_Of[ob1 + col] =
                __floats2half2_rn(o[mt][nt][2] * inv1, o[mt][nt][3] * inv1);
        }
    }
}

// ============================================================================
// Kernel 4: Y = O @ (32*Wo)^T / 32 (NT), fp16x2, K64 double-buffered cp.async,
// 2 CTAs/SM. buffer: A 128x72 + Bh 128x72 + Bl 128x72 = 27648 halfs = 55.3 KB
// ============================================================================
#define OBUF (3 * 9216)
#define OUT_SMEM (2 * OBUF * 2)

__global__ __launch_bounds__(256, 2) void out_f2(float* __restrict__ Y)
{
    extern __shared__ __half osm[];
    const int tid = threadIdx.x, lane = tid & 31, g = lane >> 2, t = lane & 3;
    const int warp = tid >> 5, wm = warp >> 2, wn = warp & 3;
    const int m0 = blockIdx.y * 128, j0 = blockIdx.x * 128;

    auto fill = [&](int bi, int kt) {
        __half* A  = osm + bi * OBUF;
        __half* Bh = A + 9216;
        __half* Bl = Bh + 9216;
        #pragma unroll
        for (int i = 0; i < 4; i++) {
            int idx = tid + i * 256;
            int row = idx >> 3, ch = idx & 7;   // 128 rows x 64 cols
            cpa16(&A[row * AK64 + ch * 8], &g_Of[(size_t)(m0 + row) * DD + kt + ch * 8]);
            size_t src = (size_t)(j0 + row) * DD + kt + ch * 8;
            cpa16(&Bh[row * AK64 + ch * 8], &g_Woh[src]);
            cpa16(&Bl[row * AK64 + ch * 8], &g_Wol[src]);
        }
    };

    float acc[4][4][4] = {};

    fill(0, 0);  CP_COMMIT();
    fill(1, 64); CP_COMMIT();

    const int NT = DD / 64;   // 16
    for (int it = 0; it < NT; ++it) {
        if (it == NT - 1) { CP_WAIT0(); } else { CP_WAIT1(); }
        __syncthreads();
        const __half* A  = osm + (it & 1) * OBUF;
        const __half* Bh = A + 9216;
        const __half* Bl = Bh + 9216;
        #pragma unroll
        for (int ks = 0; ks < 4; ks++) {
            const int kk0 = ks * 16;
            uint32_t ah[4][4], bh[2][4], bl[2][4];
            const int arow = wm * 64 + (lane & 15);
            const int ak   = kk0 + (lane >> 4) * 8;
            #pragma unroll
            for (int mi = 0; mi < 4; mi++)
                ldsm4(ah[mi], &A[(arow + mi * 16) * AK64 + ak]);
            const int brow = wn * 32 + (lane & 7) + ((lane >> 4) & 1) * 8;
            const int bk   = kk0 + ((lane >> 3) & 1) * 8;
            #pragma unroll
            for (int nj = 0; nj < 2; nj++) {
                ldsm4(bh[nj], &Bh[(brow + nj * 16) * AK64 + bk]);
                ldsm4(bl[nj], &Bl[(brow + nj * 16) * AK64 + bk]);
            }
            #pragma unroll
            for (int mi = 0; mi < 4; mi++)
                #pragma unroll
                for (int nj = 0; nj < 2; nj++)
                    #pragma unroll
                    for (int h2 = 0; h2 < 2; h2++) {
                        float* c = acc[mi][nj * 2 + h2];
                        mma16h(c, ah[mi], &bh[nj][h2 * 2]);
                        mma16h(c, ah[mi], &bl[nj][h2 * 2]);
                    }
        }
        __syncthreads();
        if (it + 2 < NT) { fill(it & 1, (it + 2) * 64); CP_COMMIT(); }
    }

    #pragma unroll
    for (int mi = 0; mi < 4; mi++) {
        int row0 = m0 + wm * 64 + mi * 16 + g;
        #pragma unroll
        for (int ni = 0; ni < 4; ni++) {
            int col = j0 + wn * 32 + ni * 8 + 2 * t;
            *(float2*)&Y[(size_t)row0 * DD + col] =
                make_float2(acc[mi][ni][0] * INV32, acc[mi][ni][1] * INV32);
            *(float2*)&Y[(size_t)(row0 + 8) * DD + col] =
                make_float2(acc[mi][ni][2] * INV32, acc[mi][ni][3] * INV32);
        }
    }
}

// ============================================================================
// launch
// Inputs: 0=inputs 1=rotation 2=entangle 3=Wq 4=Wk 5=Wv 6=Wo; out (B,L,D) fp32
// ============================================================================
extern "C" void kernel_launch(void* const* d_in, const int* in_sizes, int n_in,
                              void* d_out, int out_size)
{
    const float* X   = (const float*)d_in[0];
    const float* R   = (const float*)d_in[1];
    const float* ent = (const float*)d_in[2];
    const float* Wq  = (const float*)d_in[3];
    const float* Wk  = (const float*)d_in[4];
    const float* Wv  = (const float*)d_in[5];
    const float* Wo  = (const float*)d_in[6];
    float* Y = (float*)d_out;

    cudaFuncSetAttribute(flash7, cudaFuncAttributeMaxDynamicSharedMemorySize, FL7_SMEM);
    cudaFuncSetAttribute(qkv_f2, cudaFuncAttributeMaxDynamicSharedMemorySize, QKV_SMEM);
    cudaFuncSetAttribute(out_f2, cudaFuncAttributeMaxDynamicSharedMemorySize, OUT_SMEM);

    combine_b3<<<dim3(8, 8, 3), 256>>>(Wq, Wk, Wv, R, X, Wo);
    qkv_f2<<<dim3(8, MTOK / 128, 3), 256, QKV_SMEM>>>(ent);
    flash7<<<dim3(LL / 256, BB * NH), 256, FL7_SMEM>>>();
    out_f2<<<dim3(8, MTOK / 128), 256, OUT_SMEM>>>(Y);
}